// round 1
// baseline (speedup 1.0000x reference)
#include <cuda_runtime.h>
#include <cstdint>
#include <cstddef>

#define NP 50000
#define NL 10000
#define H  128
#define D  16
#define NLAYER 4
#define EPP 500000
#define ELP 100000
#define EPL 100000

// ---------------- scratch (device globals; no runtime allocation) ----------------
__device__ float g_xpA[NP * H];
__device__ float g_xpB[NP * H];
__device__ float g_xlA[NL * H];
__device__ float g_xlB[NL * H];
__device__ float g_Pp[(size_t)NP * 8 * H];   // 8 protein projection slices
__device__ float g_Pl[(size_t)NL * 4 * H];   // 4 ligand projection slices
__device__ float g_rpp[(size_t)EPP * D];
__device__ float g_rlp[(size_t)ELP * D];
__device__ float g_rpl[(size_t)EPL * D];
__device__ float g_agg_pp[NP * H];
__device__ float g_agg_lp[NP * H];
__device__ float g_agg_pl[NL * H];

// ---------------- small helpers ----------------
__device__ __forceinline__ void block_reduce_2(float& s, float& q, float* shbuf)
{
    // blockDim.x == 128 (4 warps)
    unsigned m = 0xffffffffu;
    #pragma unroll
    for (int o = 16; o > 0; o >>= 1) {
        s += __shfl_down_sync(m, s, o);
        q += __shfl_down_sync(m, q, o);
    }
    int lane = threadIdx.x & 31, wid = threadIdx.x >> 5;
    if (lane == 0) { shbuf[wid] = s; shbuf[4 + wid] = q; }
    __syncthreads();
    s = shbuf[0] + shbuf[1] + shbuf[2] + shbuf[3];
    q = shbuf[4] + shbuf[5] + shbuf[6] + shbuf[7];
    __syncthreads();
}

// ---------------- initial embedding: out = x @ W(6xH) + b ----------------
__global__ __launch_bounds__(128) void embed_kernel(
    const float* __restrict__ x, const float* __restrict__ W,
    const float* __restrict__ b, float* __restrict__ out, int N)
{
    int i = blockIdx.x;
    int j = threadIdx.x;
    if (i >= N) return;
    const float* xr = x + (size_t)i * 6;
    float acc = b[j];
    #pragma unroll
    for (int k = 0; k < 6; ++k) acc += xr[k] * W[k * H + j];
    out[(size_t)i * H + j] = acc;
}

// ---------------- RBF expansion of edge distances ----------------
__global__ void rbf_kernel(const float* __restrict__ ea, float* __restrict__ out, int E)
{
    int idx = blockIdx.x * blockDim.x + threadIdx.x;
    if (idx >= E * D) return;
    int e = idx >> 4, k = idx & 15;
    const float step = 8.0f / 15.0f;
    float dlt = ea[e] - (float)k * step;
    const float coeff = -0.5f / (step * step);
    out[idx] = __expf(coeff * dlt * dlt);
}

// ---------------- node projection GEMM: P[:, slice, :] = X @ W_slice ----------------
struct PtrArr8 { const float* p[8]; };

#define BM 128
#define BN 128
#define BK 8

__global__ __launch_bounds__(256) void proj_gemm(
    const float* __restrict__ X, int N, PtrArr8 wp,
    float* __restrict__ out, int outStride)
{
    __shared__ float Xs[BK][BM];
    __shared__ float Wsm[BK][BN];
    const float* W = wp.p[blockIdx.y];
    int m0 = blockIdx.x * BM;
    int tid = threadIdx.x;
    int tx = tid & 15;        // col group (8 cols)
    int ty = tid >> 4;        // row group (8 rows)
    float acc[8][8];
    #pragma unroll
    for (int i = 0; i < 8; ++i)
        #pragma unroll
        for (int j = 0; j < 8; ++j) acc[i][j] = 0.f;

    int lr = tid >> 1;            // X-load row (0..127)
    int lc = (tid & 1) * 4;       // X-load k offset (0 or 4)
    int wk = tid >> 5;            // W-load row (0..7)
    int wj = (tid & 31) * 4;      // W-load col

    for (int k0 = 0; k0 < H; k0 += BK) {
        float4 xv = make_float4(0.f, 0.f, 0.f, 0.f);
        if (m0 + lr < N) xv = *(const float4*)(X + (size_t)(m0 + lr) * H + k0 + lc);
        Xs[lc + 0][lr] = xv.x; Xs[lc + 1][lr] = xv.y;
        Xs[lc + 2][lr] = xv.z; Xs[lc + 3][lr] = xv.w;
        *(float4*)(&Wsm[wk][wj]) = *(const float4*)(W + (size_t)(k0 + wk) * H + wj);
        __syncthreads();
        #pragma unroll
        for (int k = 0; k < BK; ++k) {
            float a[8], b[8];
            *(float4*)(a)     = *(const float4*)(&Xs[k][ty * 8]);
            *(float4*)(a + 4) = *(const float4*)(&Xs[k][ty * 8 + 4]);
            *(float4*)(b)     = *(const float4*)(&Wsm[k][tx * 8]);
            *(float4*)(b + 4) = *(const float4*)(&Wsm[k][tx * 8 + 4]);
            #pragma unroll
            for (int i = 0; i < 8; ++i)
                #pragma unroll
                for (int j = 0; j < 8; ++j) acc[i][j] += a[i] * b[j];
        }
        __syncthreads();
    }
    #pragma unroll
    for (int i = 0; i < 8; ++i) {
        int mm = m0 + ty * 8 + i;
        if (mm < N) {
            float* o = out + (size_t)mm * outStride + blockIdx.y * H + tx * 8;
            *(float4*)(o)     = make_float4(acc[i][0], acc[i][1], acc[i][2], acc[i][3]);
            *(float4*)(o + 4) = make_float4(acc[i][4], acc[i][5], acc[i][6], acc[i][7]);
        }
    }
}

// ---------------- edge kernel: gather + rbf@We + activations + scatter-add ----------------
__global__ __launch_bounds__(128) void edge_kernel(
    const int* __restrict__ ei, int E,
    const float* __restrict__ rbf,
    const float* __restrict__ Pdst, int dstStride, int dstF, int dstS,
    const float* __restrict__ Psrc, int srcStride, int srcF, int srcS,
    const float* __restrict__ WfE, const float* __restrict__ WsE,   // 16 x 128
    const float* __restrict__ bfp, const float* __restrict__ bsp,
    float* __restrict__ agg)
{
    int lane = threadIdx.x & 31;
    int j0 = lane * 4;

    // hoist edge-weight columns into registers (avoids smem crossbar tax)
    float4 wf[16], ws[16];
    #pragma unroll
    for (int k = 0; k < 16; ++k) {
        wf[k] = *(const float4*)(WfE + k * H + j0);
        ws[k] = *(const float4*)(WsE + k * H + j0);
    }
    float4 bf4 = *(const float4*)(bfp + j0);
    float4 bs4 = *(const float4*)(bsp + j0);

    int gw = blockIdx.x * (blockDim.x >> 5) + (threadIdx.x >> 5);
    int nw = gridDim.x * (blockDim.x >> 5);

    for (int e = gw; e < E; e += nw) {
        int src = ei[e];
        int dst = ei[E + e];
        const float4* rp = (const float4*)(rbf + (size_t)e * 16);
        float4 ra = rp[0], rb = rp[1], rc = rp[2], rd = rp[3];
        const float* pd = Pdst + (size_t)dst * dstStride;
        const float* ps = Psrc + (size_t)src * srcStride;
        float4 fd = *(const float4*)(pd + dstF + j0);
        float4 fs = *(const float4*)(ps + srcF + j0);
        float4 sd = *(const float4*)(pd + dstS + j0);
        float4 ss = *(const float4*)(ps + srcS + j0);

        float f0 = fd.x + fs.x + bf4.x;
        float f1 = fd.y + fs.y + bf4.y;
        float f2 = fd.z + fs.z + bf4.z;
        float f3 = fd.w + fs.w + bf4.w;
        float s0 = sd.x + ss.x + bs4.x;
        float s1 = sd.y + ss.y + bs4.y;
        float s2 = sd.z + ss.z + bs4.z;
        float s3 = sd.w + ss.w + bs4.w;

        float r[16] = { ra.x, ra.y, ra.z, ra.w, rb.x, rb.y, rb.z, rb.w,
                        rc.x, rc.y, rc.z, rc.w, rd.x, rd.y, rd.z, rd.w };
        #pragma unroll
        for (int k = 0; k < 16; ++k) {
            f0 += r[k] * wf[k].x; f1 += r[k] * wf[k].y;
            f2 += r[k] * wf[k].z; f3 += r[k] * wf[k].w;
            s0 += r[k] * ws[k].x; s1 += r[k] * ws[k].y;
            s2 += r[k] * ws[k].z; s3 += r[k] * ws[k].w;
        }
        // sigmoid(f) * softplus(s)
        float g0 = 1.0f / (1.0f + __expf(-f0));
        float g1 = 1.0f / (1.0f + __expf(-f1));
        float g2 = 1.0f / (1.0f + __expf(-f2));
        float g3 = 1.0f / (1.0f + __expf(-f3));
        float p0 = fmaxf(s0, 0.f) + __logf(1.0f + __expf(-fabsf(s0)));
        float p1 = fmaxf(s1, 0.f) + __logf(1.0f + __expf(-fabsf(s1)));
        float p2 = fmaxf(s2, 0.f) + __logf(1.0f + __expf(-fabsf(s2)));
        float p3 = fmaxf(s3, 0.f) + __logf(1.0f + __expf(-fabsf(s3)));
        float m0v = g0 * p0, m1v = g1 * p1, m2v = g2 * p2, m3v = g3 * p3;

        float* ap = agg + (size_t)dst * H + j0;
        asm volatile("red.global.add.v4.f32 [%0], {%1, %2, %3, %4};"
                     :: "l"(ap), "f"(m0v), "f"(m1v), "f"(m2v), "f"(m3v) : "memory");
    }
}

// ---------------- node epilogue: BN + residual + LN + relu + residual (x1 or x2 blocks) ----------------
__global__ __launch_bounds__(128) void node_update_kernel(
    const float* __restrict__ xin,
    const float* __restrict__ agg1,
    const float* __restrict__ bnw1, const float* __restrict__ bnb1,
    const float* __restrict__ lnw1, const float* __restrict__ lnb1,
    const float* __restrict__ agg2,
    const float* __restrict__ bnw2, const float* __restrict__ bnb2,
    const float* __restrict__ lnw2, const float* __restrict__ lnb2,
    float* __restrict__ xout)
{
    __shared__ float sh[8];
    int i = blockIdx.x, j = threadIdx.x;
    size_t off = (size_t)i * H + j;
    float x = xin[off];
    const float bnf = rsqrtf(1.0f + 1e-5f);

    float a1 = agg1[off] * (bnw1[j] * bnf) + bnb1[j] + x;
    float s = a1, q = a1 * a1;
    block_reduce_2(s, q, sh);
    float mean = s * (1.0f / H);
    float var = q * (1.0f / H) - mean * mean;
    float y = (a1 - mean) * rsqrtf(var + 1e-5f) * lnw1[j] + lnb1[j];
    float res = fmaxf(y, 0.f) + x;

    if (agg2) {
        float a2 = agg2[off] * (bnw2[j] * bnf) + bnb2[j] + x;
        s = a2; q = a2 * a2;
        block_reduce_2(s, q, sh);
        mean = s * (1.0f / H);
        var = q * (1.0f / H) - mean * mean;
        y = (a2 - mean) * rsqrtf(var + 1e-5f) * lnw2[j] + lnb2[j];
        res += fmaxf(y, 0.f) + x;
    }
    xout[off] = res;
}

// ---------------- final: LN(xp) @ fc_w + fc_b ----------------
__global__ __launch_bounds__(128) void final_kernel(
    const float* __restrict__ xp,
    const float* __restrict__ lnw, const float* __restrict__ lnb,
    const float* __restrict__ fcw, const float* __restrict__ fcb,
    float* __restrict__ out)
{
    __shared__ float sh[8];
    __shared__ float yb[H];
    __shared__ float part[4][21];
    int i = blockIdx.x, j = threadIdx.x;
    float x = xp[(size_t)i * H + j];
    float s = x, q = x * x;
    block_reduce_2(s, q, sh);
    float mean = s * (1.0f / H);
    float var = q * (1.0f / H) - mean * mean;
    yb[j] = (x - mean) * rsqrtf(var + 1e-5f) * lnw[j] + lnb[j];
    __syncthreads();
    if (j < 84) {
        int c = j % 21, qq = j / 21;
        float acc = 0.f;
        #pragma unroll
        for (int t = 0; t < 32; ++t) acc += yb[qq * 32 + t] * fcw[(qq * 32 + t) * 21 + c];
        part[qq][c] = acc;
    }
    __syncthreads();
    if (j < 21)
        out[(size_t)i * 21 + j] = part[0][j] + part[1][j] + part[2][j] + part[3][j] + fcb[j];
}

// ---------------- host ----------------
extern "C" void kernel_launch(void* const* d_in, const int* in_sizes, int n_in,
                              void* d_out, int out_size)
{
    const float* x_protein = (const float*)d_in[0];
    const float* x_ligand  = (const float*)d_in[1];
    const int*   ei_pp     = (const int*)d_in[2];
    const float* ea_pp     = (const float*)d_in[3];
    const int*   ei_lp     = (const int*)d_in[4];
    const float* ea_lp     = (const float*)d_in[5];
    const int*   ei_pl     = (const int*)d_in[6];
    const float* ea_pl     = (const float*)d_in[7];
    const float* Wp        = (const float*)d_in[8];
    const float* bp        = (const float*)d_in[9];
    const float* Wl        = (const float*)d_in[10];
    const float* bl        = (const float*)d_in[11];
    const float* Wf        = (const float*)d_in[12];
    const float* bf        = (const float*)d_in[13];
    const float* Ws        = (const float*)d_in[14];
    const float* bs        = (const float*)d_in[15];
    const float* bn_w      = (const float*)d_in[16];
    const float* bn_b      = (const float*)d_in[17];
    const float* ln_w      = (const float*)d_in[18];
    const float* ln_b      = (const float*)d_in[19];
    const float* lno_w     = (const float*)d_in[20];
    const float* lno_b     = (const float*)d_in[21];
    const float* fc_w      = (const float*)d_in[22];
    const float* fc_b      = (const float*)d_in[23];
    float* out = (float*)d_out;

    float *xpA, *xpB, *xlA, *xlB, *Pp, *Pl, *rpp, *rlp, *rpl, *agg_pp, *agg_lp, *agg_pl;
    cudaGetSymbolAddress((void**)&xpA, g_xpA);
    cudaGetSymbolAddress((void**)&xpB, g_xpB);
    cudaGetSymbolAddress((void**)&xlA, g_xlA);
    cudaGetSymbolAddress((void**)&xlB, g_xlB);
    cudaGetSymbolAddress((void**)&Pp, g_Pp);
    cudaGetSymbolAddress((void**)&Pl, g_Pl);
    cudaGetSymbolAddress((void**)&rpp, g_rpp);
    cudaGetSymbolAddress((void**)&rlp, g_rlp);
    cudaGetSymbolAddress((void**)&rpl, g_rpl);
    cudaGetSymbolAddress((void**)&agg_pp, g_agg_pp);
    cudaGetSymbolAddress((void**)&agg_lp, g_agg_lp);
    cudaGetSymbolAddress((void**)&agg_pl, g_agg_pl);

    // 1. initial embeddings
    embed_kernel<<<NP, 128>>>(x_protein, Wp, bp, xpA, NP);
    embed_kernel<<<NL, 128>>>(x_ligand, Wl, bl, xlA, NL);

    // 2. RBF expansion (edges are fixed across layers)
    rbf_kernel<<<(EPP * D + 255) / 256, 256>>>(ea_pp, rpp, EPP);
    rbf_kernel<<<(ELP * D + 255) / 256, 256>>>(ea_lp, rlp, ELP);
    rbf_kernel<<<(EPL * D + 255) / 256, 256>>>(ea_pl, rpl, EPL);

    float* xp_cur = xpA; float* xp_nxt = xpB;
    float* xl_cur = xlA; float* xl_nxt = xlB;

    for (int l = 0; l < NLAYER; ++l) {
        // weight sub-block pointers: Wx[l][b] row r at ((l*3+b)*272 + r)*128
        auto wfp = [&](int b, int r) { return Wf + ((size_t)(l * 3 + b) * 272 + r) * H; };
        auto wsp = [&](int b, int r) { return Ws + ((size_t)(l * 3 + b) * 272 + r) * H; };

        // protein projection slices:
        // 0: pp dst f | 1: pp src f | 2: pp dst s | 3: pp src s
        // 4: lp dst f | 5: lp dst s | 6: pl src f | 7: pl src s
        PtrArr8 pw;
        pw.p[0] = wfp(0, 0);   pw.p[1] = wfp(0, 128);
        pw.p[2] = wsp(0, 0);   pw.p[3] = wsp(0, 128);
        pw.p[4] = wfp(1, 0);   pw.p[5] = wsp(1, 0);
        pw.p[6] = wfp(2, 128); pw.p[7] = wsp(2, 128);
        // ligand slices: 0: lp src f | 1: lp src s | 2: pl dst f | 3: pl dst s
        PtrArr8 lw;
        lw.p[0] = wfp(1, 128); lw.p[1] = wsp(1, 128);
        lw.p[2] = wfp(2, 0);   lw.p[3] = wsp(2, 0);
        lw.p[4] = lw.p[5] = lw.p[6] = lw.p[7] = lw.p[0];

        proj_gemm<<<dim3((NP + 127) / 128, 8), 256>>>(xp_cur, NP, pw, Pp, 8 * H);
        proj_gemm<<<dim3((NL + 127) / 128, 4), 256>>>(xl_cur, NL, lw, Pl, 4 * H);

        cudaMemsetAsync(agg_pp, 0, (size_t)NP * H * sizeof(float), 0);
        cudaMemsetAsync(agg_lp, 0, (size_t)NP * H * sizeof(float), 0);
        cudaMemsetAsync(agg_pl, 0, (size_t)NL * H * sizeof(float), 0);

        // pp: dst/src protein
        edge_kernel<<<304, 128>>>(ei_pp, EPP, rpp,
                                  Pp, 8 * H, 0 * H, 2 * H,
                                  Pp, 8 * H, 1 * H, 3 * H,
                                  wfp(0, 256), wsp(0, 256),
                                  bf + (size_t)(l * 3 + 0) * H, bs + (size_t)(l * 3 + 0) * H,
                                  agg_pp);
        // lp: dst protein, src ligand
        edge_kernel<<<304, 128>>>(ei_lp, ELP, rlp,
                                  Pp, 8 * H, 4 * H, 5 * H,
                                  Pl, 4 * H, 0 * H, 1 * H,
                                  wfp(1, 256), wsp(1, 256),
                                  bf + (size_t)(l * 3 + 1) * H, bs + (size_t)(l * 3 + 1) * H,
                                  agg_lp);
        // pl: dst ligand, src protein
        edge_kernel<<<304, 128>>>(ei_pl, EPL, rpl,
                                  Pl, 4 * H, 2 * H, 3 * H,
                                  Pp, 8 * H, 6 * H, 7 * H,
                                  wfp(2, 256), wsp(2, 256),
                                  bf + (size_t)(l * 3 + 2) * H, bs + (size_t)(l * 3 + 2) * H,
                                  agg_pl);

        // protein update: p_pp + p_lp
        node_update_kernel<<<NP, 128>>>(xp_cur,
            agg_pp,
            bn_w + (size_t)(l * 3 + 0) * H, bn_b + (size_t)(l * 3 + 0) * H,
            ln_w + (size_t)(l * 3 + 0) * H, ln_b + (size_t)(l * 3 + 0) * H,
            agg_lp,
            bn_w + (size_t)(l * 3 + 1) * H, bn_b + (size_t)(l * 3 + 1) * H,
            ln_w + (size_t)(l * 3 + 1) * H, ln_b + (size_t)(l * 3 + 1) * H,
            xp_nxt);
        // ligand update: l_pl only
        node_update_kernel<<<NL, 128>>>(xl_cur,
            agg_pl,
            bn_w + (size_t)(l * 3 + 2) * H, bn_b + (size_t)(l * 3 + 2) * H,
            ln_w + (size_t)(l * 3 + 2) * H, ln_b + (size_t)(l * 3 + 2) * H,
            (const float*)nullptr, nullptr, nullptr, nullptr, nullptr,
            xl_nxt);

        float* t;
        t = xp_cur; xp_cur = xp_nxt; xp_nxt = t;
        t = xl_cur; xl_cur = xl_nxt; xl_nxt = t;
    }

    // final LN + FC
    final_kernel<<<NP, 128>>>(xp_cur, lno_w, lno_b, fc_w, fc_b, out);
}

// round 3
// speedup vs baseline: 1.1573x; 1.1573x over previous
#include <cuda_runtime.h>
#include <cstdint>
#include <cstddef>

#define NP 50000
#define NL 10000
#define H  128
#define D  16
#define NLAYER 4
#define EPP 500000
#define ELP 100000
#define EPL 100000
#define ETOT (EPP + ELP + EPL)

// ---------------- scratch (device globals; no runtime allocation) ----------------
__device__ float g_xpA[NP * H];
__device__ float g_xpB[NP * H];
__device__ float g_xlA[NL * H];
__device__ float g_xlB[NL * H];
__device__ float g_Pp[(size_t)NP * 8 * H];   // 8 protein projection slices
__device__ float g_Pl[(size_t)NL * 4 * H];   // 4 ligand projection slices
__device__ float g_rbf[(size_t)ETOT * D];
__device__ float g_agg_pp[NP * H];
__device__ float g_agg_lp[NP * H];
__device__ float g_agg_pl[NL * H];

// ---------------- small helpers ----------------
__device__ __forceinline__ void block_reduce_2(float& s, float& q, float* shbuf)
{
    unsigned m = 0xffffffffu;
    #pragma unroll
    for (int o = 16; o > 0; o >>= 1) {
        s += __shfl_down_sync(m, s, o);
        q += __shfl_down_sync(m, q, o);
    }
    int lane = threadIdx.x & 31, wid = threadIdx.x >> 5;
    if (lane == 0) { shbuf[wid] = s; shbuf[4 + wid] = q; }
    __syncthreads();
    s = shbuf[0] + shbuf[1] + shbuf[2] + shbuf[3];
    q = shbuf[4] + shbuf[5] + shbuf[6] + shbuf[7];
    __syncthreads();
}

__device__ __forceinline__ uint32_t f2tf32(float f) {
    uint32_t r;
    asm("cvt.rna.tf32.f32 %0, %1;" : "=r"(r) : "f"(f));
    return r;
}

// ---------------- merged RBF expansion ----------------
__global__ void rbf_kernel(const float* __restrict__ ea_pp, const float* __restrict__ ea_lp,
                           const float* __restrict__ ea_pl, float* __restrict__ out)
{
    int idx = blockIdx.x * blockDim.x + threadIdx.x;
    if (idx >= ETOT * D) return;
    int e = idx >> 4, k = idx & 15;
    float dv;
    if (e < EPP) dv = ea_pp[e];
    else if (e < EPP + ELP) dv = ea_lp[e - EPP];
    else dv = ea_pl[e - EPP - ELP];
    const float step = 8.0f / 15.0f;
    float dlt = dv - (float)k * step;
    const float coeff = -0.5f / (step * step);
    out[idx] = __expf(coeff * dlt * dlt);
}

// ---------------- merged initial embedding ----------------
__global__ __launch_bounds__(128) void embed_kernel(
    const float* __restrict__ xp, const float* __restrict__ Wp, const float* __restrict__ bp,
    const float* __restrict__ xl, const float* __restrict__ Wl, const float* __restrict__ bl,
    float* __restrict__ outp, float* __restrict__ outl)
{
    int i = blockIdx.x;
    int j = threadIdx.x;
    const float *x, *W, *b; float* o; int r;
    if (i < NP) { x = xp; W = Wp; b = bp; o = outp; r = i; }
    else        { x = xl; W = Wl; b = bl; o = outl; r = i - NP; }
    const float* xr = x + (size_t)r * 6;
    float acc = b[j];
    #pragma unroll
    for (int k = 0; k < 6; ++k) acc += xr[k] * W[k * H + j];
    o[(size_t)r * H + j] = acc;
}

// ---------------- tf32 mma.sync projection GEMM ----------------
struct PtrArr8 { const float* p[8]; };

#define APITCH 132
#define SMEM_B_FLOAT (128 * APITCH)
#define SMEM_MMA_BYTES (2 * 128 * APITCH * 4)

__global__ __launch_bounds__(256) void proj_mma(
    const float* __restrict__ X, int N, PtrArr8 wp,
    float* __restrict__ out, int outStride)
{
    extern __shared__ uint32_t sm[];
    uint32_t* As = sm;                   // [row][k]  row pitch APITCH
    uint32_t* Bs = sm + SMEM_B_FLOAT;    // [k][n]    row pitch APITCH

    const float* W = wp.p[blockIdx.y];
    int m0 = blockIdx.x * 128;
    int tid = threadIdx.x;
    int lane = tid & 31, warp = tid >> 5;
    int g = lane >> 2, t = lane & 3;

    // load A tile (X rows, guarded) and B tile (W), converting to tf32
    #pragma unroll
    for (int it = 0; it < 16; ++it) {
        int idx = it * 256 + tid;
        int r = idx >> 5, c4 = (idx & 31) * 4;
        float4 av = make_float4(0.f, 0.f, 0.f, 0.f);
        if (m0 + r < N) av = *(const float4*)(X + (size_t)(m0 + r) * H + c4);
        uint32_t* ap = As + r * APITCH + c4;
        ap[0] = f2tf32(av.x); ap[1] = f2tf32(av.y);
        ap[2] = f2tf32(av.z); ap[3] = f2tf32(av.w);
        float4 bv = *(const float4*)(W + (size_t)r * H + c4);
        uint32_t* bp2 = Bs + r * APITCH + c4;
        bp2[0] = f2tf32(bv.x); bp2[1] = f2tf32(bv.y);
        bp2[2] = f2tf32(bv.z); bp2[3] = f2tf32(bv.w);
    }
    __syncthreads();

    int wm = warp >> 2;      // 0..1 -> m offset 0/64
    int wn = warp & 3;       // 0..3 -> n offset 0/32/64/96
    int mbase = wm * 64;
    int nbase = wn * 32;

    float d[4][4][4];
    #pragma unroll
    for (int i = 0; i < 4; ++i)
        #pragma unroll
        for (int j = 0; j < 4; ++j)
            #pragma unroll
            for (int q = 0; q < 4; ++q) d[i][j][q] = 0.f;

    #pragma unroll
    for (int ks = 0; ks < 16; ++ks) {
        int kb = ks * 8;
        uint32_t a[4][4];
        #pragma unroll
        for (int i = 0; i < 4; ++i) {
            int r0 = mbase + i * 16 + g;
            a[i][0] = As[r0 * APITCH + kb + t];
            a[i][1] = As[(r0 + 8) * APITCH + kb + t];
            a[i][2] = As[r0 * APITCH + kb + 4 + t];
            a[i][3] = As[(r0 + 8) * APITCH + kb + 4 + t];
        }
        uint32_t b[4][2];
        #pragma unroll
        for (int j = 0; j < 4; ++j) {
            int c0 = nbase + j * 8 + g;
            b[j][0] = Bs[(kb + t) * APITCH + c0];
            b[j][1] = Bs[(kb + 4 + t) * APITCH + c0];
        }
        #pragma unroll
        for (int i = 0; i < 4; ++i)
            #pragma unroll
            for (int j = 0; j < 4; ++j) {
                asm volatile(
                    "mma.sync.aligned.m16n8k8.row.col.f32.tf32.tf32.f32 "
                    "{%0,%1,%2,%3}, {%4,%5,%6,%7}, {%8,%9}, {%0,%1,%2,%3};"
                    : "+f"(d[i][j][0]), "+f"(d[i][j][1]), "+f"(d[i][j][2]), "+f"(d[i][j][3])
                    : "r"(a[i][0]), "r"(a[i][1]), "r"(a[i][2]), "r"(a[i][3]),
                      "r"(b[j][0]), "r"(b[j][1]));
            }
    }

    // epilogue: direct global stores
    size_t colbase = (size_t)blockIdx.y * H;
    #pragma unroll
    for (int i = 0; i < 4; ++i) {
        int gr0 = m0 + mbase + i * 16 + g;
        int gr1 = gr0 + 8;
        #pragma unroll
        for (int j = 0; j < 4; ++j) {
            int gc = nbase + j * 8 + t * 2;
            if (gr0 < N)
                *(float2*)(out + (size_t)gr0 * outStride + colbase + gc) =
                    make_float2(d[i][j][0], d[i][j][1]);
            if (gr1 < N)
                *(float2*)(out + (size_t)gr1 * outStride + colbase + gc) =
                    make_float2(d[i][j][2], d[i][j][3]);
        }
    }
}

// ---------------- edge kernel: gather + rbf@We + activations + scatter-add ----------------
__global__ __launch_bounds__(128) void edge_kernel(
    const int* __restrict__ ei, int E,
    const float* __restrict__ rbf,
    const float* __restrict__ Pdst, int dstStride, int dstF, int dstS,
    const float* __restrict__ Psrc, int srcStride, int srcF, int srcS,
    const float* __restrict__ WfE, const float* __restrict__ WsE,   // 16 x 128
    const float* __restrict__ bfp, const float* __restrict__ bsp,
    float* __restrict__ agg)
{
    int lane = threadIdx.x & 31;
    int j0 = lane * 4;

    float4 wf[16], ws[16];
    #pragma unroll
    for (int k = 0; k < 16; ++k) {
        wf[k] = *(const float4*)(WfE + k * H + j0);
        ws[k] = *(const float4*)(WsE + k * H + j0);
    }
    float4 bf4 = *(const float4*)(bfp + j0);
    float4 bs4 = *(const float4*)(bsp + j0);

    int gw = blockIdx.x * (blockDim.x >> 5) + (threadIdx.x >> 5);
    int nw = gridDim.x * (blockDim.x >> 5);

    for (int e = gw; e < E; e += nw) {
        int src = ei[e];
        int dst = ei[E + e];
        const float4* rp = (const float4*)(rbf + (size_t)e * 16);
        float4 ra = rp[0], rb = rp[1], rc = rp[2], rd = rp[3];
        const float* pd = Pdst + (size_t)dst * dstStride;
        const float* ps = Psrc + (size_t)src * srcStride;
        float4 fd = *(const float4*)(pd + dstF + j0);
        float4 fs = *(const float4*)(ps + srcF + j0);
        float4 sd = *(const float4*)(pd + dstS + j0);
        float4 ss = *(const float4*)(ps + srcS + j0);

        float f0 = fd.x + fs.x + bf4.x;
        float f1 = fd.y + fs.y + bf4.y;
        float f2 = fd.z + fs.z + bf4.z;
        float f3 = fd.w + fs.w + bf4.w;
        float s0 = sd.x + ss.x + bs4.x;
        float s1 = sd.y + ss.y + bs4.y;
        float s2 = sd.z + ss.z + bs4.z;
        float s3 = sd.w + ss.w + bs4.w;

        float r[16] = { ra.x, ra.y, ra.z, ra.w, rb.x, rb.y, rb.z, rb.w,
                        rc.x, rc.y, rc.z, rc.w, rd.x, rd.y, rd.z, rd.w };
        #pragma unroll
        for (int k = 0; k < 16; ++k) {
            f0 += r[k] * wf[k].x; f1 += r[k] * wf[k].y;
            f2 += r[k] * wf[k].z; f3 += r[k] * wf[k].w;
            s0 += r[k] * ws[k].x; s1 += r[k] * ws[k].y;
            s2 += r[k] * ws[k].z; s3 += r[k] * ws[k].w;
        }
        float g0 = 1.0f / (1.0f + __expf(-f0));
        float g1 = 1.0f / (1.0f + __expf(-f1));
        float g2 = 1.0f / (1.0f + __expf(-f2));
        float g3 = 1.0f / (1.0f + __expf(-f3));
        float p0 = fmaxf(s0, 0.f) + __logf(1.0f + __expf(-fabsf(s0)));
        float p1 = fmaxf(s1, 0.f) + __logf(1.0f + __expf(-fabsf(s1)));
        float p2 = fmaxf(s2, 0.f) + __logf(1.0f + __expf(-fabsf(s2)));
        float p3 = fmaxf(s3, 0.f) + __logf(1.0f + __expf(-fabsf(s3)));
        float m0v = g0 * p0, m1v = g1 * p1, m2v = g2 * p2, m3v = g3 * p3;

        float* ap = agg + (size_t)dst * H + j0;
        asm volatile("red.global.add.v4.f32 [%0], {%1, %2, %3, %4};"
                     :: "l"(ap), "f"(m0v), "f"(m1v), "f"(m2v), "f"(m3v) : "memory");
    }
}

// ---------------- node epilogue ----------------
__global__ __launch_bounds__(128) void node_update_kernel(
    const float* __restrict__ xin,
    const float* __restrict__ agg1,
    const float* __restrict__ bnw1, const float* __restrict__ bnb1,
    const float* __restrict__ lnw1, const float* __restrict__ lnb1,
    const float* __restrict__ agg2,
    const float* __restrict__ bnw2, const float* __restrict__ bnb2,
    const float* __restrict__ lnw2, const float* __restrict__ lnb2,
    float* __restrict__ xout)
{
    __shared__ float sh[8];
    int i = blockIdx.x, j = threadIdx.x;
    size_t off = (size_t)i * H + j;
    float x = xin[off];
    const float bnf = rsqrtf(1.0f + 1e-5f);

    float a1 = agg1[off] * (bnw1[j] * bnf) + bnb1[j] + x;
    float s = a1, q = a1 * a1;
    block_reduce_2(s, q, sh);
    float mean = s * (1.0f / H);
    float var = q * (1.0f / H) - mean * mean;
    float y = (a1 - mean) * rsqrtf(var + 1e-5f) * lnw1[j] + lnb1[j];
    float res = fmaxf(y, 0.f) + x;

    if (agg2) {
        float a2 = agg2[off] * (bnw2[j] * bnf) + bnb2[j] + x;
        s = a2; q = a2 * a2;
        block_reduce_2(s, q, sh);
        mean = s * (1.0f / H);
        var = q * (1.0f / H) - mean * mean;
        y = (a2 - mean) * rsqrtf(var + 1e-5f) * lnw2[j] + lnb2[j];
        res += fmaxf(y, 0.f) + x;
    }
    xout[off] = res;
}

// ---------------- final: LN(xp) @ fc_w + fc_b ----------------
__global__ __launch_bounds__(128) void final_kernel(
    const float* __restrict__ xp,
    const float* __restrict__ lnw, const float* __restrict__ lnb,
    const float* __restrict__ fcw, const float* __restrict__ fcb,
    float* __restrict__ out)
{
    __shared__ float sh[8];
    __shared__ float yb[H];
    __shared__ float part[4][21];
    int i = blockIdx.x, j = threadIdx.x;
    float x = xp[(size_t)i * H + j];
    float s = x, q = x * x;
    block_reduce_2(s, q, sh);
    float mean = s * (1.0f / H);
    float var = q * (1.0f / H) - mean * mean;
    yb[j] = (x - mean) * rsqrtf(var + 1e-5f) * lnw[j] + lnb[j];
    __syncthreads();
    if (j < 84) {
        int c = j % 21, qq = j / 21;
        float acc = 0.f;
        #pragma unroll
        for (int t = 0; t < 32; ++t) acc += yb[qq * 32 + t] * fcw[(qq * 32 + t) * 21 + c];
        part[qq][c] = acc;
    }
    __syncthreads();
    if (j < 21)
        out[(size_t)i * 21 + j] = part[0][j] + part[1][j] + part[2][j] + part[3][j] + fcb[j];
}

// ---------------- host ----------------
extern "C" void kernel_launch(void* const* d_in, const int* in_sizes, int n_in,
                              void* d_out, int out_size)
{
    const float* x_protein = (const float*)d_in[0];
    const float* x_ligand  = (const float*)d_in[1];
    const int*   ei_pp     = (const int*)d_in[2];
    const float* ea_pp     = (const float*)d_in[3];
    const int*   ei_lp     = (const int*)d_in[4];
    const float* ea_lp     = (const float*)d_in[5];
    const int*   ei_pl     = (const int*)d_in[6];
    const float* ea_pl     = (const float*)d_in[7];
    const float* Wp        = (const float*)d_in[8];
    const float* bp        = (const float*)d_in[9];
    const float* Wl        = (const float*)d_in[10];
    const float* bl        = (const float*)d_in[11];
    const float* Wf        = (const float*)d_in[12];
    const float* bf        = (const float*)d_in[13];
    const float* Ws        = (const float*)d_in[14];
    const float* bs        = (const float*)d_in[15];
    const float* bn_w      = (const float*)d_in[16];
    const float* bn_b      = (const float*)d_in[17];
    const float* ln_w      = (const float*)d_in[18];
    const float* ln_b      = (const float*)d_in[19];
    const float* lno_w     = (const float*)d_in[20];
    const float* lno_b     = (const float*)d_in[21];
    const float* fc_w      = (const float*)d_in[22];
    const float* fc_b      = (const float*)d_in[23];
    float* out = (float*)d_out;

    float *xpA, *xpB, *xlA, *xlB, *Pp, *Pl, *rbfb, *agg_pp, *agg_lp, *agg_pl;
    cudaGetSymbolAddress((void**)&xpA, g_xpA);
    cudaGetSymbolAddress((void**)&xpB, g_xpB);
    cudaGetSymbolAddress((void**)&xlA, g_xlA);
    cudaGetSymbolAddress((void**)&xlB, g_xlB);
    cudaGetSymbolAddress((void**)&Pp, g_Pp);
    cudaGetSymbolAddress((void**)&Pl, g_Pl);
    cudaGetSymbolAddress((void**)&rbfb, g_rbf);
    cudaGetSymbolAddress((void**)&agg_pp, g_agg_pp);
    cudaGetSymbolAddress((void**)&agg_lp, g_agg_lp);
    cudaGetSymbolAddress((void**)&agg_pl, g_agg_pl);
    float* rpp = rbfb;
    float* rlp = rbfb + (size_t)EPP * D;
    float* rpl = rbfb + (size_t)(EPP + ELP) * D;

    cudaFuncSetAttribute(proj_mma, cudaFuncAttributeMaxDynamicSharedMemorySize, SMEM_MMA_BYTES);

    rbf_kernel<<<(ETOT * D + 255) / 256, 256>>>(ea_pp, ea_lp, ea_pl, rbfb);
    embed_kernel<<<NP + NL, 128>>>(x_protein, Wp, bp, x_ligand, Wl, bl, xpA, xlA);

    float* xp_cur = xpA; float* xp_nxt = xpB;
    float* xl_cur = xlA; float* xl_nxt = xlB;

    for (int l = 0; l < NLAYER; ++l) {
        auto wfp = [&](int b, int r) { return Wf + ((size_t)(l * 3 + b) * 272 + r) * H; };
        auto wsp = [&](int b, int r) { return Ws + ((size_t)(l * 3 + b) * 272 + r) * H; };

        PtrArr8 pw;
        pw.p[0] = wfp(0, 0);   pw.p[1] = wfp(0, 128);
        pw.p[2] = wsp(0, 0);   pw.p[3] = wsp(0, 128);
        pw.p[4] = wfp(1, 0);   pw.p[5] = wsp(1, 0);
        pw.p[6] = wfp(2, 128); pw.p[7] = wsp(2, 128);
        PtrArr8 lw;
        lw.p[0] = wfp(1, 128); lw.p[1] = wsp(1, 128);
        lw.p[2] = wfp(2, 0);   lw.p[3] = wsp(2, 0);
        lw.p[4] = lw.p[5] = lw.p[6] = lw.p[7] = lw.p[0];

        cudaMemsetAsync(agg_pp, 0, (size_t)NP * H * sizeof(float), 0);
        cudaMemsetAsync(agg_lp, 0, (size_t)NP * H * sizeof(float), 0);
        cudaMemsetAsync(agg_pl, 0, (size_t)NL * H * sizeof(float), 0);

        proj_mma<<<dim3((NP + 127) / 128, 8), 256, SMEM_MMA_BYTES>>>(xp_cur, NP, pw, Pp, 8 * H);
        proj_mma<<<dim3((NL + 127) / 128, 4), 256, SMEM_MMA_BYTES>>>(xl_cur, NL, lw, Pl, 4 * H);

        edge_kernel<<<304, 128>>>(ei_pp, EPP, rpp,
                                  Pp, 8 * H, 0 * H, 2 * H,
                                  Pp, 8 * H, 1 * H, 3 * H,
                                  wfp(0, 256), wsp(0, 256),
                                  bf + (size_t)(l * 3 + 0) * H, bs + (size_t)(l * 3 + 0) * H,
                                  agg_pp);
        edge_kernel<<<304, 128>>>(ei_lp, ELP, rlp,
                                  Pp, 8 * H, 4 * H, 5 * H,
                                  Pl, 4 * H, 0 * H, 1 * H,
                                  wfp(1, 256), wsp(1, 256),
                                  bf + (size_t)(l * 3 + 1) * H, bs + (size_t)(l * 3 + 1) * H,
                                  agg_lp);
        edge_kernel<<<304, 128>>>(ei_pl, EPL, rpl,
                                  Pl, 4 * H, 2 * H, 3 * H,
                                  Pp, 8 * H, 6 * H, 7 * H,
                                  wfp(2, 256), wsp(2, 256),
                                  bf + (size_t)(l * 3 + 2) * H, bs + (size_t)(l * 3 + 2) * H,
                                  agg_pl);

        node_update_kernel<<<NP, 128>>>(xp_cur,
            agg_pp,
            bn_w + (size_t)(l * 3 + 0) * H, bn_b + (size_t)(l * 3 + 0) * H,
            ln_w + (size_t)(l * 3 + 0) * H, ln_b + (size_t)(l * 3 + 0) * H,
            agg_lp,
            bn_w + (size_t)(l * 3 + 1) * H, bn_b + (size_t)(l * 3 + 1) * H,
            ln_w + (size_t)(l * 3 + 1) * H, ln_b + (size_t)(l * 3 + 1) * H,
            xp_nxt);
        node_update_kernel<<<NL, 128>>>(xl_cur,
            agg_pl,
            bn_w + (size_t)(l * 3 + 2) * H, bn_b + (size_t)(l * 3 + 2) * H,
            ln_w + (size_t)(l * 3 + 2) * H, ln_b + (size_t)(l * 3 + 2) * H,
            (const float*)nullptr, nullptr, nullptr, nullptr, nullptr,
            xl_nxt);

        float* t;
        t = xp_cur; xp_cur = xp_nxt; xp_nxt = t;
        t = xl_cur; xl_cur = xl_nxt; xl_nxt = t;
    }

    final_kernel<<<NP, 128>>>(xp_cur, lno_w, lno_b, fc_w, fc_b, out);
}

// round 4
// speedup vs baseline: 1.5438x; 1.3340x over previous
#include <cuda_runtime.h>
#include <cstdint>
#include <cstddef>

#define NP 50000
#define NL 10000
#define H  128
#define D  16
#define NLAYER 4
#define EPP 500000
#define ELP 100000
#define EPL 100000
#define ETOT (EPP + ELP + EPL)
#define NCNT (2 * NP + NL)

// ---------------- scratch (device globals; no runtime allocation) ----------------
__device__ float g_xpA[NP * H];
__device__ float g_xpB[NP * H];
__device__ float g_xlA[NL * H];
__device__ float g_xlB[NL * H];
__device__ float g_Pp[(size_t)NP * 8 * H];   // 8 protein projection slices
__device__ float g_Pl[(size_t)NL * 4 * H];   // 4 ligand projection slices
__device__ float g_rbf[(size_t)ETOT * D];    // RBF in dst-sorted order
__device__ float g_agg_pp[NP * H];
__device__ float g_agg_lp[NP * H];
__device__ float g_agg_pl[NL * H];
// CSR scratch
__device__ int   g_cnt[NCNT];
__device__ int   g_off[NCNT + 3];
__device__ int   g_cur[NCNT];
__device__ int   g_ssrc[ETOT];
__device__ float g_sea[ETOT];

// ---------------- small helpers ----------------
__device__ __forceinline__ void block_reduce_2(float& s, float& q, float* shbuf)
{
    unsigned m = 0xffffffffu;
    #pragma unroll
    for (int o = 16; o > 0; o >>= 1) {
        s += __shfl_down_sync(m, s, o);
        q += __shfl_down_sync(m, q, o);
    }
    int lane = threadIdx.x & 31, wid = threadIdx.x >> 5;
    if (lane == 0) { shbuf[wid] = s; shbuf[4 + wid] = q; }
    __syncthreads();
    s = shbuf[0] + shbuf[1] + shbuf[2] + shbuf[3];
    q = shbuf[4] + shbuf[5] + shbuf[6] + shbuf[7];
    __syncthreads();
}

__device__ __forceinline__ uint32_t f2tf32(float f) {
    uint32_t r;
    asm("cvt.rna.tf32.f32 %0, %1;" : "=r"(r) : "f"(f));
    return r;
}
__device__ __forceinline__ float sig_tanh(float x) {
    float t;
    asm("tanh.approx.f32 %0, %1;" : "=f"(t) : "f"(x * 0.5f));
    return 0.5f * t + 0.5f;
}
__device__ __forceinline__ float softplus_f(float x) {
    return fmaxf(x, 0.f) + __logf(1.0f + __expf(-fabsf(x)));
}

// ---------------- CSR build: histogram over all 3 edge sets ----------------
__global__ void hist_all(const int* __restrict__ ei_pp, const int* __restrict__ ei_lp,
                         const int* __restrict__ ei_pl, int* __restrict__ cnt)
{
    int idx = blockIdx.x * blockDim.x + threadIdx.x;
    if (idx >= ETOT) return;
    if (idx < EPP) {
        atomicAdd(&cnt[ei_pp[EPP + idx]], 1);
    } else if (idx < EPP + ELP) {
        int e = idx - EPP;
        atomicAdd(&cnt[NP + ei_lp[ELP + e]], 1);
    } else {
        int e = idx - EPP - ELP;
        atomicAdd(&cnt[2 * NP + ei_pl[EPL + e]], 1);
    }
}

// ---------------- 3-segment exclusive scan (one block per segment) ----------------
__device__ void scan_seg(const int* __restrict__ cnt, int N, int* __restrict__ off,
                         int* __restrict__ cur)
{
    __shared__ int s[1024];
    __shared__ int base;
    if (threadIdx.x == 0) base = 0;
    __syncthreads();
    for (int c = 0; c < N; c += 1024) {
        int i = c + threadIdx.x;
        int v = (i < N) ? cnt[i] : 0;
        s[threadIdx.x] = v;
        __syncthreads();
        #pragma unroll
        for (int o = 1; o < 1024; o <<= 1) {
            int t = (threadIdx.x >= (unsigned)o) ? s[threadIdx.x - o] : 0;
            __syncthreads();
            s[threadIdx.x] += t;
            __syncthreads();
        }
        int excl = base + s[threadIdx.x] - v;
        if (i < N) { off[i] = excl; cur[i] = excl; }
        int tot = s[1023];
        __syncthreads();
        if (threadIdx.x == 0) base += tot;
        __syncthreads();
    }
    if (threadIdx.x == 0) off[N] = base;
}

__global__ void scan3(int* __restrict__ cnt, int* __restrict__ off, int* __restrict__ cur)
{
    if (blockIdx.x == 0)      scan_seg(cnt,          NP, off,              cur);
    else if (blockIdx.x == 1) scan_seg(cnt + NP,     NP, off + NP + 1,     cur + NP);
    else                      scan_seg(cnt + 2 * NP, NL, off + 2 * NP + 2, cur + 2 * NP);
}

// ---------------- scatter edges into dst-sorted order ----------------
__global__ void scatter_all(const int* __restrict__ ei_pp, const float* __restrict__ ea_pp,
                            const int* __restrict__ ei_lp, const float* __restrict__ ea_lp,
                            const int* __restrict__ ei_pl, const float* __restrict__ ea_pl,
                            int* __restrict__ cur, int* __restrict__ ssrc,
                            float* __restrict__ sea)
{
    int idx = blockIdx.x * blockDim.x + threadIdx.x;
    if (idx >= ETOT) return;
    if (idx < EPP) {
        int e = idx;
        int d = ei_pp[EPP + e];
        int p = atomicAdd(&cur[d], 1);
        ssrc[p] = ei_pp[e];
        sea[p] = ea_pp[e];
    } else if (idx < EPP + ELP) {
        int e = idx - EPP;
        int d = ei_lp[ELP + e];
        int p = EPP + atomicAdd(&cur[NP + d], 1);
        ssrc[p] = ei_lp[e];
        sea[p] = ea_lp[e];
    } else {
        int e = idx - EPP - ELP;
        int d = ei_pl[EPL + e];
        int p = EPP + ELP + atomicAdd(&cur[2 * NP + d], 1);
        ssrc[p] = ei_pl[e];
        sea[p] = ea_pl[e];
    }
}

// ---------------- RBF expansion on sorted ea ----------------
__global__ void rbf_kernel(const float* __restrict__ sea, float* __restrict__ out)
{
    int idx = blockIdx.x * blockDim.x + threadIdx.x;
    if (idx >= ETOT * D) return;
    int e = idx >> 4, k = idx & 15;
    const float step = 8.0f / 15.0f;
    float dlt = sea[e] - (float)k * step;
    const float coeff = -0.5f / (step * step);
    out[idx] = __expf(coeff * dlt * dlt);
}

// ---------------- merged initial embedding ----------------
__global__ __launch_bounds__(128) void embed_kernel(
    const float* __restrict__ xp, const float* __restrict__ Wp, const float* __restrict__ bp,
    const float* __restrict__ xl, const float* __restrict__ Wl, const float* __restrict__ bl,
    float* __restrict__ outp, float* __restrict__ outl)
{
    int i = blockIdx.x;
    int j = threadIdx.x;
    const float *x, *W, *b; float* o; int r;
    if (i < NP) { x = xp; W = Wp; b = bp; o = outp; r = i; }
    else        { x = xl; W = Wl; b = bl; o = outl; r = i - NP; }
    const float* xr = x + (size_t)r * 6;
    float acc = b[j];
    #pragma unroll
    for (int k = 0; k < 6; ++k) acc += xr[k] * W[k * H + j];
    o[(size_t)r * H + j] = acc;
}

// ---------------- tf32 mma.sync projection GEMM ----------------
struct PtrArr8 { const float* p[8]; };

#define APITCH 132
#define SMEM_B_FLOAT (128 * APITCH)
#define SMEM_MMA_BYTES (2 * 128 * APITCH * 4)

__global__ __launch_bounds__(256) void proj_mma(
    const float* __restrict__ X, int N, PtrArr8 wp,
    float* __restrict__ out, int outStride)
{
    extern __shared__ uint32_t sm[];
    uint32_t* As = sm;
    uint32_t* Bs = sm + SMEM_B_FLOAT;

    const float* W = wp.p[blockIdx.y];
    int m0 = blockIdx.x * 128;
    int tid = threadIdx.x;
    int lane = tid & 31, warp = tid >> 5;
    int g = lane >> 2, t = lane & 3;

    #pragma unroll
    for (int it = 0; it < 16; ++it) {
        int idx = it * 256 + tid;
        int r = idx >> 5, c4 = (idx & 31) * 4;
        float4 av = make_float4(0.f, 0.f, 0.f, 0.f);
        if (m0 + r < N) av = *(const float4*)(X + (size_t)(m0 + r) * H + c4);
        uint32_t* ap = As + r * APITCH + c4;
        ap[0] = f2tf32(av.x); ap[1] = f2tf32(av.y);
        ap[2] = f2tf32(av.z); ap[3] = f2tf32(av.w);
        float4 bv = *(const float4*)(W + (size_t)r * H + c4);
        uint32_t* bp2 = Bs + r * APITCH + c4;
        bp2[0] = f2tf32(bv.x); bp2[1] = f2tf32(bv.y);
        bp2[2] = f2tf32(bv.z); bp2[3] = f2tf32(bv.w);
    }
    __syncthreads();

    int wm = warp >> 2;
    int wn = warp & 3;
    int mbase = wm * 64;
    int nbase = wn * 32;

    float d[4][4][4];
    #pragma unroll
    for (int i = 0; i < 4; ++i)
        #pragma unroll
        for (int j = 0; j < 4; ++j)
            #pragma unroll
            for (int q = 0; q < 4; ++q) d[i][j][q] = 0.f;

    #pragma unroll
    for (int ks = 0; ks < 16; ++ks) {
        int kb = ks * 8;
        uint32_t a[4][4];
        #pragma unroll
        for (int i = 0; i < 4; ++i) {
            int r0 = mbase + i * 16 + g;
            a[i][0] = As[r0 * APITCH + kb + t];
            a[i][1] = As[(r0 + 8) * APITCH + kb + t];
            a[i][2] = As[r0 * APITCH + kb + 4 + t];
            a[i][3] = As[(r0 + 8) * APITCH + kb + 4 + t];
        }
        uint32_t b[4][2];
        #pragma unroll
        for (int j = 0; j < 4; ++j) {
            int c0 = nbase + j * 8 + g;
            b[j][0] = Bs[(kb + t) * APITCH + c0];
            b[j][1] = Bs[(kb + 4 + t) * APITCH + c0];
        }
        #pragma unroll
        for (int i = 0; i < 4; ++i)
            #pragma unroll
            for (int j = 0; j < 4; ++j) {
                asm volatile(
                    "mma.sync.aligned.m16n8k8.row.col.f32.tf32.tf32.f32 "
                    "{%0,%1,%2,%3}, {%4,%5,%6,%7}, {%8,%9}, {%0,%1,%2,%3};"
                    : "+f"(d[i][j][0]), "+f"(d[i][j][1]), "+f"(d[i][j][2]), "+f"(d[i][j][3])
                    : "r"(a[i][0]), "r"(a[i][1]), "r"(a[i][2]), "r"(a[i][3]),
                      "r"(b[j][0]), "r"(b[j][1]));
            }
    }

    size_t colbase = (size_t)blockIdx.y * H;
    #pragma unroll
    for (int i = 0; i < 4; ++i) {
        int gr0 = m0 + mbase + i * 16 + g;
        int gr1 = gr0 + 8;
        #pragma unroll
        for (int j = 0; j < 4; ++j) {
            int gc = nbase + j * 8 + t * 2;
            if (gr0 < N)
                *(float2*)(out + (size_t)gr0 * outStride + colbase + gc) =
                    make_float2(d[i][j][0], d[i][j][1]);
            if (gr1 < N)
                *(float2*)(out + (size_t)gr1 * outStride + colbase + gc) =
                    make_float2(d[i][j][2], d[i][j][3]);
        }
    }
}

// ---------------- CSR edge kernel: warp per dst node ----------------
__global__ __launch_bounds__(128) void edge_csr(
    const int* __restrict__ off, const int* __restrict__ ssrc,
    const float* __restrict__ rbf, int Ndst,
    const float* __restrict__ Pdst, int dstStride, int dstF, int dstS,
    const float* __restrict__ Psrc, int srcStride, int srcF, int srcS,
    const float* __restrict__ WfE, const float* __restrict__ WsE,   // 16 x 128
    const float* __restrict__ bfp, const float* __restrict__ bsp,
    float* __restrict__ agg)
{
    int lane = threadIdx.x & 31;
    int j0 = lane * 4;

    float4 wf[16], ws[16];
    #pragma unroll
    for (int k = 0; k < 16; ++k) {
        wf[k] = *(const float4*)(WfE + k * H + j0);
        ws[k] = *(const float4*)(WsE + k * H + j0);
    }
    float4 bf4 = *(const float4*)(bfp + j0);
    float4 bs4 = *(const float4*)(bsp + j0);

    int gw = blockIdx.x * (blockDim.x >> 5) + (threadIdx.x >> 5);
    int nw = gridDim.x * (blockDim.x >> 5);

    for (int n = gw; n < Ndst; n += nw) {
        int p0 = off[n], p1 = off[n + 1];
        const float* pd = Pdst + (size_t)n * dstStride;
        float4 fdv = *(const float4*)(pd + dstF + j0);
        float4 sdv = *(const float4*)(pd + dstS + j0);
        float fd0 = fdv.x + bf4.x, fd1 = fdv.y + bf4.y, fd2 = fdv.z + bf4.z, fd3 = fdv.w + bf4.w;
        float sd0 = sdv.x + bs4.x, sd1 = sdv.y + bs4.y, sd2 = sdv.z + bs4.z, sd3 = sdv.w + bs4.w;

        float a0 = 0.f, a1 = 0.f, a2 = 0.f, a3 = 0.f;

        #pragma unroll 2
        for (int p = p0; p < p1; ++p) {
            int src = ssrc[p];
            const float4* rp = (const float4*)(rbf + (size_t)p * 16);
            float4 ra = rp[0], rb = rp[1], rc = rp[2], rd = rp[3];
            const float* ps = Psrc + (size_t)src * srcStride;
            float4 fs = *(const float4*)(ps + srcF + j0);
            float4 ssv = *(const float4*)(ps + srcS + j0);

            float f0 = fd0 + fs.x, f1 = fd1 + fs.y, f2 = fd2 + fs.z, f3 = fd3 + fs.w;
            float s0 = sd0 + ssv.x, s1 = sd1 + ssv.y, s2 = sd2 + ssv.z, s3 = sd3 + ssv.w;

            float r[16] = { ra.x, ra.y, ra.z, ra.w, rb.x, rb.y, rb.z, rb.w,
                            rc.x, rc.y, rc.z, rc.w, rd.x, rd.y, rd.z, rd.w };
            #pragma unroll
            for (int k = 0; k < 16; ++k) {
                f0 += r[k] * wf[k].x; f1 += r[k] * wf[k].y;
                f2 += r[k] * wf[k].z; f3 += r[k] * wf[k].w;
                s0 += r[k] * ws[k].x; s1 += r[k] * ws[k].y;
                s2 += r[k] * ws[k].z; s3 += r[k] * ws[k].w;
            }
            a0 += sig_tanh(f0) * softplus_f(s0);
            a1 += sig_tanh(f1) * softplus_f(s1);
            a2 += sig_tanh(f2) * softplus_f(s2);
            a3 += sig_tanh(f3) * softplus_f(s3);
        }
        *(float4*)(agg + (size_t)n * H + j0) = make_float4(a0, a1, a2, a3);
    }
}

// ---------------- node epilogue ----------------
__global__ __launch_bounds__(128) void node_update_kernel(
    const float* __restrict__ xin,
    const float* __restrict__ agg1,
    const float* __restrict__ bnw1, const float* __restrict__ bnb1,
    const float* __restrict__ lnw1, const float* __restrict__ lnb1,
    const float* __restrict__ agg2,
    const float* __restrict__ bnw2, const float* __restrict__ bnb2,
    const float* __restrict__ lnw2, const float* __restrict__ lnb2,
    float* __restrict__ xout)
{
    __shared__ float sh[8];
    int i = blockIdx.x, j = threadIdx.x;
    size_t off = (size_t)i * H + j;
    float x = xin[off];
    const float bnf = rsqrtf(1.0f + 1e-5f);

    float a1 = agg1[off] * (bnw1[j] * bnf) + bnb1[j] + x;
    float s = a1, q = a1 * a1;
    block_reduce_2(s, q, sh);
    float mean = s * (1.0f / H);
    float var = q * (1.0f / H) - mean * mean;
    float y = (a1 - mean) * rsqrtf(var + 1e-5f) * lnw1[j] + lnb1[j];
    float res = fmaxf(y, 0.f) + x;

    if (agg2) {
        float a2 = agg2[off] * (bnw2[j] * bnf) + bnb2[j] + x;
        s = a2; q = a2 * a2;
        block_reduce_2(s, q, sh);
        mean = s * (1.0f / H);
        var = q * (1.0f / H) - mean * mean;
        y = (a2 - mean) * rsqrtf(var + 1e-5f) * lnw2[j] + lnb2[j];
        res += fmaxf(y, 0.f) + x;
    }
    xout[off] = res;
}

// ---------------- final: LN(xp) @ fc_w + fc_b ----------------
__global__ __launch_bounds__(128) void final_kernel(
    const float* __restrict__ xp,
    const float* __restrict__ lnw, const float* __restrict__ lnb,
    const float* __restrict__ fcw, const float* __restrict__ fcb,
    float* __restrict__ out)
{
    __shared__ float sh[8];
    __shared__ float yb[H];
    __shared__ float part[4][21];
    int i = blockIdx.x, j = threadIdx.x;
    float x = xp[(size_t)i * H + j];
    float s = x, q = x * x;
    block_reduce_2(s, q, sh);
    float mean = s * (1.0f / H);
    float var = q * (1.0f / H) - mean * mean;
    yb[j] = (x - mean) * rsqrtf(var + 1e-5f) * lnw[j] + lnb[j];
    __syncthreads();
    if (j < 84) {
        int c = j % 21, qq = j / 21;
        float acc = 0.f;
        #pragma unroll
        for (int t = 0; t < 32; ++t) acc += yb[qq * 32 + t] * fcw[(qq * 32 + t) * 21 + c];
        part[qq][c] = acc;
    }
    __syncthreads();
    if (j < 21)
        out[(size_t)i * 21 + j] = part[0][j] + part[1][j] + part[2][j] + part[3][j] + fcb[j];
}

// ---------------- host ----------------
extern "C" void kernel_launch(void* const* d_in, const int* in_sizes, int n_in,
                              void* d_out, int out_size)
{
    const float* x_protein = (const float*)d_in[0];
    const float* x_ligand  = (const float*)d_in[1];
    const int*   ei_pp     = (const int*)d_in[2];
    const float* ea_pp     = (const float*)d_in[3];
    const int*   ei_lp     = (const int*)d_in[4];
    const float* ea_lp     = (const float*)d_in[5];
    const int*   ei_pl     = (const int*)d_in[6];
    const float* ea_pl     = (const float*)d_in[7];
    const float* Wp        = (const float*)d_in[8];
    const float* bp        = (const float*)d_in[9];
    const float* Wl        = (const float*)d_in[10];
    const float* bl        = (const float*)d_in[11];
    const float* Wf        = (const float*)d_in[12];
    const float* bf        = (const float*)d_in[13];
    const float* Ws        = (const float*)d_in[14];
    const float* bs        = (const float*)d_in[15];
    const float* bn_w      = (const float*)d_in[16];
    const float* bn_b      = (const float*)d_in[17];
    const float* ln_w      = (const float*)d_in[18];
    const float* ln_b      = (const float*)d_in[19];
    const float* lno_w     = (const float*)d_in[20];
    const float* lno_b     = (const float*)d_in[21];
    const float* fc_w      = (const float*)d_in[22];
    const float* fc_b      = (const float*)d_in[23];
    float* out = (float*)d_out;

    float *xpA, *xpB, *xlA, *xlB, *Pp, *Pl, *rbfb, *agg_pp, *agg_lp, *agg_pl, *sea;
    int *cnt, *offs, *cur, *ssrc;
    cudaGetSymbolAddress((void**)&xpA, g_xpA);
    cudaGetSymbolAddress((void**)&xpB, g_xpB);
    cudaGetSymbolAddress((void**)&xlA, g_xlA);
    cudaGetSymbolAddress((void**)&xlB, g_xlB);
    cudaGetSymbolAddress((void**)&Pp, g_Pp);
    cudaGetSymbolAddress((void**)&Pl, g_Pl);
    cudaGetSymbolAddress((void**)&rbfb, g_rbf);
    cudaGetSymbolAddress((void**)&agg_pp, g_agg_pp);
    cudaGetSymbolAddress((void**)&agg_lp, g_agg_lp);
    cudaGetSymbolAddress((void**)&agg_pl, g_agg_pl);
    cudaGetSymbolAddress((void**)&cnt, g_cnt);
    cudaGetSymbolAddress((void**)&offs, g_off);
    cudaGetSymbolAddress((void**)&cur, g_cur);
    cudaGetSymbolAddress((void**)&ssrc, g_ssrc);
    cudaGetSymbolAddress((void**)&sea, g_sea);

    cudaFuncSetAttribute(proj_mma, cudaFuncAttributeMaxDynamicSharedMemorySize, SMEM_MMA_BYTES);

    // ---- CSR build (edges are layer-invariant) ----
    cudaMemsetAsync(cnt, 0, NCNT * sizeof(int), 0);
    hist_all<<<(ETOT + 255) / 256, 256>>>(ei_pp, ei_lp, ei_pl, cnt);
    scan3<<<3, 1024>>>(cnt, offs, cur);
    scatter_all<<<(ETOT + 255) / 256, 256>>>(ei_pp, ea_pp, ei_lp, ea_lp, ei_pl, ea_pl,
                                             cur, ssrc, sea);
    rbf_kernel<<<(ETOT * D + 255) / 256, 256>>>(sea, rbfb);
    embed_kernel<<<NP + NL, 128>>>(x_protein, Wp, bp, x_ligand, Wl, bl, xpA, xlA);

    const int* off_pp = offs;
    const int* off_lp = offs + NP + 1;
    const int* off_pl = offs + 2 * NP + 2;
    const int* ssrc_pp = ssrc;
    const int* ssrc_lp = ssrc + EPP;
    const int* ssrc_pl = ssrc + EPP + ELP;
    const float* rbf_pp = rbfb;
    const float* rbf_lp = rbfb + (size_t)EPP * D;
    const float* rbf_pl = rbfb + (size_t)(EPP + ELP) * D;

    float* xp_cur = xpA; float* xp_nxt = xpB;
    float* xl_cur = xlA; float* xl_nxt = xlB;

    for (int l = 0; l < NLAYER; ++l) {
        auto wfp = [&](int b, int r) { return Wf + ((size_t)(l * 3 + b) * 272 + r) * H; };
        auto wsp = [&](int b, int r) { return Ws + ((size_t)(l * 3 + b) * 272 + r) * H; };

        PtrArr8 pw;
        pw.p[0] = wfp(0, 0);   pw.p[1] = wfp(0, 128);
        pw.p[2] = wsp(0, 0);   pw.p[3] = wsp(0, 128);
        pw.p[4] = wfp(1, 0);   pw.p[5] = wsp(1, 0);
        pw.p[6] = wfp(2, 128); pw.p[7] = wsp(2, 128);
        PtrArr8 lw;
        lw.p[0] = wfp(1, 128); lw.p[1] = wsp(1, 128);
        lw.p[2] = wfp(2, 0);   lw.p[3] = wsp(2, 0);
        lw.p[4] = lw.p[5] = lw.p[6] = lw.p[7] = lw.p[0];

        proj_mma<<<dim3((NP + 127) / 128, 8), 256, SMEM_MMA_BYTES>>>(xp_cur, NP, pw, Pp, 8 * H);
        proj_mma<<<dim3((NL + 127) / 128, 4), 256, SMEM_MMA_BYTES>>>(xl_cur, NL, lw, Pl, 4 * H);

        // pp: dst/src protein — one warp per dst node
        edge_csr<<<(NP + 3) / 4, 128>>>(off_pp, ssrc_pp, rbf_pp, NP,
                                        Pp, 8 * H, 0 * H, 2 * H,
                                        Pp, 8 * H, 1 * H, 3 * H,
                                        wfp(0, 256), wsp(0, 256),
                                        bf + (size_t)(l * 3 + 0) * H, bs + (size_t)(l * 3 + 0) * H,
                                        agg_pp);
        // lp: dst protein, src ligand — 4 nodes per warp
        edge_csr<<<(NP + 15) / 16, 128>>>(off_lp, ssrc_lp, rbf_lp, NP,
                                          Pp, 8 * H, 4 * H, 5 * H,
                                          Pl, 4 * H, 0 * H, 1 * H,
                                          wfp(1, 256), wsp(1, 256),
                                          bf + (size_t)(l * 3 + 1) * H, bs + (size_t)(l * 3 + 1) * H,
                                          agg_lp);
        // pl: dst ligand, src protein
        edge_csr<<<(NL + 3) / 4, 128>>>(off_pl, ssrc_pl, rbf_pl, NL,
                                        Pl, 4 * H, 2 * H, 3 * H,
                                        Pp, 8 * H, 6 * H, 7 * H,
                                        wfp(2, 256), wsp(2, 256),
                                        bf + (size_t)(l * 3 + 2) * H, bs + (size_t)(l * 3 + 2) * H,
                                        agg_pl);

        node_update_kernel<<<NP, 128>>>(xp_cur,
            agg_pp,
            bn_w + (size_t)(l * 3 + 0) * H, bn_b + (size_t)(l * 3 + 0) * H,
            ln_w + (size_t)(l * 3 + 0) * H, ln_b + (size_t)(l * 3 + 0) * H,
            agg_lp,
            bn_w + (size_t)(l * 3 + 1) * H, bn_b + (size_t)(l * 3 + 1) * H,
            ln_w + (size_t)(l * 3 + 1) * H, ln_b + (size_t)(l * 3 + 1) * H,
            xp_nxt);
        node_update_kernel<<<NL, 128>>>(xl_cur,
            agg_pl,
            bn_w + (size_t)(l * 3 + 2) * H, bn_b + (size_t)(l * 3 + 2) * H,
            ln_w + (size_t)(l * 3 + 2) * H, ln_b + (size_t)(l * 3 + 2) * H,
            (const float*)nullptr, nullptr, nullptr, nullptr, nullptr,
            xl_nxt);

        float* t;
        t = xp_cur; xp_cur = xp_nxt; xp_nxt = t;
        t = xl_cur; xl_cur = xl_nxt; xl_nxt = t;
    }

    final_kernel<<<NP, 128>>>(xp_cur, lno_w, lno_b, fc_w, fc_b, out);
}

// round 5
// speedup vs baseline: 2.5352x; 1.6422x over previous
#include <cuda_runtime.h>
#include <cstdint>
#include <cstddef>

#define NP 50000
#define NL 10000
#define H  128
#define D  16
#define NLAYER 4
#define EPP 500000
#define ELP 100000
#define EPL 100000
#define ETOT (EPP + ELP + EPL)
#define NCNT (2 * NP + NL)
#define NBIN 512

// ---------------- scratch (device globals; no runtime allocation) ----------------
__device__ float g_xpA[NP * H];
__device__ float g_xpB[NP * H];
__device__ float g_xlA[NL * H];
__device__ float g_xlB[NL * H];
__device__ float g_Pp[(size_t)NP * 8 * H];   // 8 protein projection slices
__device__ float g_Pl[(size_t)NL * 4 * H];   // 4 ligand projection slices
__device__ float g_agg_pp[NP * H];
__device__ float g_agg_lp[NP * H];
__device__ float g_agg_pl[NL * H];
// edge-weight LUT: 12 tables (layer x type), (NBIN+1) rows x 256 cols (f|s)
__device__ float g_T[(size_t)12 * (NBIN + 1) * 256];
// CSR scratch
__device__ int   g_cnt[NCNT];
__device__ int   g_off[NCNT + 3];
__device__ int   g_cur[NCNT];
__device__ int   g_ssrc[ETOT];
__device__ float g_su[ETOT];     // pre-scaled bin coordinate u = d * NBIN/8

// ---------------- small helpers ----------------
__device__ __forceinline__ void block_reduce_2(float& s, float& q, float* shbuf)
{
    unsigned m = 0xffffffffu;
    #pragma unroll
    for (int o = 16; o > 0; o >>= 1) {
        s += __shfl_down_sync(m, s, o);
        q += __shfl_down_sync(m, q, o);
    }
    int lane = threadIdx.x & 31, wid = threadIdx.x >> 5;
    if (lane == 0) { shbuf[wid] = s; shbuf[4 + wid] = q; }
    __syncthreads();
    s = shbuf[0] + shbuf[1] + shbuf[2] + shbuf[3];
    q = shbuf[4] + shbuf[5] + shbuf[6] + shbuf[7];
    __syncthreads();
}

__device__ __forceinline__ uint32_t f2tf32(float f) {
    uint32_t r;
    asm("cvt.rna.tf32.f32 %0, %1;" : "=r"(r) : "f"(f));
    return r;
}
__device__ __forceinline__ float sig_tanh(float x) {
    float t;
    asm("tanh.approx.f32 %0, %1;" : "=f"(t) : "f"(x * 0.5f));
    return 0.5f * t + 0.5f;
}
__device__ __forceinline__ float softplus_f(float x) {
    return fmaxf(x, 0.f) + __logf(1.0f + __expf(-fabsf(x)));
}

// ---------------- CSR build: histogram over all 3 edge sets ----------------
__global__ void hist_all(const int* __restrict__ ei_pp, const int* __restrict__ ei_lp,
                         const int* __restrict__ ei_pl, int* __restrict__ cnt)
{
    int idx = blockIdx.x * blockDim.x + threadIdx.x;
    if (idx >= ETOT) return;
    if (idx < EPP) {
        atomicAdd(&cnt[ei_pp[EPP + idx]], 1);
    } else if (idx < EPP + ELP) {
        int e = idx - EPP;
        atomicAdd(&cnt[NP + ei_lp[ELP + e]], 1);
    } else {
        int e = idx - EPP - ELP;
        atomicAdd(&cnt[2 * NP + ei_pl[EPL + e]], 1);
    }
}

// ---------------- 3-segment exclusive scan ----------------
__device__ void scan_seg(const int* __restrict__ cnt, int N, int* __restrict__ off,
                         int* __restrict__ cur)
{
    __shared__ int s[1024];
    __shared__ int base;
    if (threadIdx.x == 0) base = 0;
    __syncthreads();
    for (int c = 0; c < N; c += 1024) {
        int i = c + threadIdx.x;
        int v = (i < N) ? cnt[i] : 0;
        s[threadIdx.x] = v;
        __syncthreads();
        #pragma unroll
        for (int o = 1; o < 1024; o <<= 1) {
            int t = (threadIdx.x >= (unsigned)o) ? s[threadIdx.x - o] : 0;
            __syncthreads();
            s[threadIdx.x] += t;
            __syncthreads();
        }
        int excl = base + s[threadIdx.x] - v;
        if (i < N) { off[i] = excl; cur[i] = excl; }
        int tot = s[1023];
        __syncthreads();
        if (threadIdx.x == 0) base += tot;
        __syncthreads();
    }
    if (threadIdx.x == 0) off[N] = base;
}

__global__ void scan3(int* __restrict__ cnt, int* __restrict__ off, int* __restrict__ cur)
{
    if (blockIdx.x == 0)      scan_seg(cnt,          NP, off,              cur);
    else if (blockIdx.x == 1) scan_seg(cnt + NP,     NP, off + NP + 1,     cur + NP);
    else                      scan_seg(cnt + 2 * NP, NL, off + 2 * NP + 2, cur + 2 * NP);
}

// ---------------- scatter edges into dst-sorted order (store bin coord) ----------------
__global__ void scatter_all(const int* __restrict__ ei_pp, const float* __restrict__ ea_pp,
                            const int* __restrict__ ei_lp, const float* __restrict__ ea_lp,
                            const int* __restrict__ ei_pl, const float* __restrict__ ea_pl,
                            int* __restrict__ cur, int* __restrict__ ssrc,
                            float* __restrict__ su)
{
    const float usc = (float)NBIN / 8.0f;
    int idx = blockIdx.x * blockDim.x + threadIdx.x;
    if (idx >= ETOT) return;
    if (idx < EPP) {
        int e = idx;
        int d = ei_pp[EPP + e];
        int p = atomicAdd(&cur[d], 1);
        ssrc[p] = ei_pp[e];
        su[p] = ea_pp[e] * usc;
    } else if (idx < EPP + ELP) {
        int e = idx - EPP;
        int d = ei_lp[ELP + e];
        int p = EPP + atomicAdd(&cur[NP + d], 1);
        ssrc[p] = ei_lp[e];
        su[p] = ea_lp[e] * usc;
    } else {
        int e = idx - EPP - ELP;
        int d = ei_pl[EPL + e];
        int p = EPP + ELP + atomicAdd(&cur[2 * NP + d], 1);
        ssrc[p] = ei_pl[e];
        su[p] = ea_pl[e] * usc;
    }
}

// ---------------- LUT build: T[lt][bin][j] = rbf(d_bin) @ We_{f|s}[lt] ----------------
__global__ __launch_bounds__(256) void lut_build(
    const float* __restrict__ Wf, const float* __restrict__ Ws, float* __restrict__ T)
{
    int b = blockIdx.x;        // 0..NBIN
    int lt = blockIdx.y;       // 0..11  (layer*3 + type)
    int j = threadIdx.x;       // 0..255 : 0-127 -> f, 128-255 -> s
    float d = (float)b * (8.0f / (float)NBIN);
    const float step = 8.0f / 15.0f;
    const float coeff = -0.5f / (step * step);
    float r[16];
    #pragma unroll
    for (int k = 0; k < 16; ++k) {
        float dlt = d - (float)k * step;
        r[k] = __expf(coeff * dlt * dlt);
    }
    const float* W = (j < 128 ? Wf : Ws) + ((size_t)lt * 272 + 256) * H + (j & 127);
    float acc = 0.f;
    #pragma unroll
    for (int k = 0; k < 16; ++k) acc += r[k] * W[(size_t)k * H];
    T[((size_t)lt * (NBIN + 1) + b) * 256 + j] = acc;
}

// ---------------- merged initial embedding ----------------
__global__ __launch_bounds__(128) void embed_kernel(
    const float* __restrict__ xp, const float* __restrict__ Wp, const float* __restrict__ bp,
    const float* __restrict__ xl, const float* __restrict__ Wl, const float* __restrict__ bl,
    float* __restrict__ outp, float* __restrict__ outl)
{
    int i = blockIdx.x;
    int j = threadIdx.x;
    const float *x, *W, *b; float* o; int r;
    if (i < NP) { x = xp; W = Wp; b = bp; o = outp; r = i; }
    else        { x = xl; W = Wl; b = bl; o = outl; r = i - NP; }
    const float* xr = x + (size_t)r * 6;
    float acc = b[j];
    #pragma unroll
    for (int k = 0; k < 6; ++k) acc += xr[k] * W[k * H + j];
    o[(size_t)r * H + j] = acc;
}

// ---------------- tf32 mma.sync projection GEMM ----------------
struct PtrArr8 { const float* p[8]; };

#define APITCH 132
#define SMEM_B_FLOAT (128 * APITCH)
#define SMEM_MMA_BYTES (2 * 128 * APITCH * 4)

__global__ __launch_bounds__(256) void proj_mma(
    const float* __restrict__ X, int N, PtrArr8 wp,
    float* __restrict__ out, int outStride)
{
    extern __shared__ uint32_t sm[];
    uint32_t* As = sm;
    uint32_t* Bs = sm + SMEM_B_FLOAT;

    const float* W = wp.p[blockIdx.y];
    int m0 = blockIdx.x * 128;
    int tid = threadIdx.x;
    int lane = tid & 31, warp = tid >> 5;
    int g = lane >> 2, t = lane & 3;

    #pragma unroll
    for (int it = 0; it < 16; ++it) {
        int idx = it * 256 + tid;
        int r = idx >> 5, c4 = (idx & 31) * 4;
        float4 av = make_float4(0.f, 0.f, 0.f, 0.f);
        if (m0 + r < N) av = *(const float4*)(X + (size_t)(m0 + r) * H + c4);
        uint32_t* ap = As + r * APITCH + c4;
        ap[0] = f2tf32(av.x); ap[1] = f2tf32(av.y);
        ap[2] = f2tf32(av.z); ap[3] = f2tf32(av.w);
        float4 bv = *(const float4*)(W + (size_t)r * H + c4);
        uint32_t* bp2 = Bs + r * APITCH + c4;
        bp2[0] = f2tf32(bv.x); bp2[1] = f2tf32(bv.y);
        bp2[2] = f2tf32(bv.z); bp2[3] = f2tf32(bv.w);
    }
    __syncthreads();

    int wm = warp >> 2;
    int wn = warp & 3;
    int mbase = wm * 64;
    int nbase = wn * 32;

    float d[4][4][4];
    #pragma unroll
    for (int i = 0; i < 4; ++i)
        #pragma unroll
        for (int j = 0; j < 4; ++j)
            #pragma unroll
            for (int q = 0; q < 4; ++q) d[i][j][q] = 0.f;

    #pragma unroll
    for (int ks = 0; ks < 16; ++ks) {
        int kb = ks * 8;
        uint32_t a[4][4];
        #pragma unroll
        for (int i = 0; i < 4; ++i) {
            int r0 = mbase + i * 16 + g;
            a[i][0] = As[r0 * APITCH + kb + t];
            a[i][1] = As[(r0 + 8) * APITCH + kb + t];
            a[i][2] = As[r0 * APITCH + kb + 4 + t];
            a[i][3] = As[(r0 + 8) * APITCH + kb + 4 + t];
        }
        uint32_t b[4][2];
        #pragma unroll
        for (int j = 0; j < 4; ++j) {
            int c0 = nbase + j * 8 + g;
            b[j][0] = Bs[(kb + t) * APITCH + c0];
            b[j][1] = Bs[(kb + 4 + t) * APITCH + c0];
        }
        #pragma unroll
        for (int i = 0; i < 4; ++i)
            #pragma unroll
            for (int j = 0; j < 4; ++j) {
                asm volatile(
                    "mma.sync.aligned.m16n8k8.row.col.f32.tf32.tf32.f32 "
                    "{%0,%1,%2,%3}, {%4,%5,%6,%7}, {%8,%9}, {%0,%1,%2,%3};"
                    : "+f"(d[i][j][0]), "+f"(d[i][j][1]), "+f"(d[i][j][2]), "+f"(d[i][j][3])
                    : "r"(a[i][0]), "r"(a[i][1]), "r"(a[i][2]), "r"(a[i][3]),
                      "r"(b[j][0]), "r"(b[j][1]));
            }
    }

    size_t colbase = (size_t)blockIdx.y * H;
    #pragma unroll
    for (int i = 0; i < 4; ++i) {
        int gr0 = m0 + mbase + i * 16 + g;
        int gr1 = gr0 + 8;
        #pragma unroll
        for (int j = 0; j < 4; ++j) {
            int gc = nbase + j * 8 + t * 2;
            if (gr0 < N)
                *(float2*)(out + (size_t)gr0 * outStride + colbase + gc) =
                    make_float2(d[i][j][0], d[i][j][1]);
            if (gr1 < N)
                *(float2*)(out + (size_t)gr1 * outStride + colbase + gc) =
                    make_float2(d[i][j][2], d[i][j][3]);
        }
    }
}

// ---------------- CSR edge kernel with LUT: warp per dst node ----------------
__global__ __launch_bounds__(128) void edge_csr(
    const int* __restrict__ off, const int* __restrict__ ssrc,
    const float* __restrict__ su, int Ndst,
    const float* __restrict__ T,                       // (NBIN+1) x 256
    const float* __restrict__ Pdst, int dstStride, int dstF, int dstS,
    const float* __restrict__ Psrc, int srcStride, int srcF, int srcS,
    const float* __restrict__ bfp, const float* __restrict__ bsp,
    float* __restrict__ agg)
{
    int lane = threadIdx.x & 31;
    int j0 = lane * 4;

    float4 bf4 = *(const float4*)(bfp + j0);
    float4 bs4 = *(const float4*)(bsp + j0);

    int gw = blockIdx.x * (blockDim.x >> 5) + (threadIdx.x >> 5);
    int nw = gridDim.x * (blockDim.x >> 5);

    for (int n = gw; n < Ndst; n += nw) {
        int p0 = off[n], p1 = off[n + 1];
        const float* pd = Pdst + (size_t)n * dstStride;
        float4 fdv = *(const float4*)(pd + dstF + j0);
        float4 sdv = *(const float4*)(pd + dstS + j0);
        float fd0 = fdv.x + bf4.x, fd1 = fdv.y + bf4.y, fd2 = fdv.z + bf4.z, fd3 = fdv.w + bf4.w;
        float sd0 = sdv.x + bs4.x, sd1 = sdv.y + bs4.y, sd2 = sdv.z + bs4.z, sd3 = sdv.w + bs4.w;

        float a0 = 0.f, a1 = 0.f, a2 = 0.f, a3 = 0.f;

        #pragma unroll 2
        for (int p = p0; p < p1; ++p) {
            int src = ssrc[p];
            float u = su[p];
            int b = (int)u;
            b = min(b, NBIN - 1);
            float w = u - (float)b;
            const float* Tb = T + (size_t)b * 256 + j0;
            float4 flo = *(const float4*)(Tb);
            float4 fhi = *(const float4*)(Tb + 256);
            float4 slo = *(const float4*)(Tb + 128);
            float4 shi = *(const float4*)(Tb + 384);

            const float* ps = Psrc + (size_t)src * srcStride;
            float4 fs = *(const float4*)(ps + srcF + j0);
            float4 ssv = *(const float4*)(ps + srcS + j0);

            float f0 = fd0 + fs.x + flo.x + w * (fhi.x - flo.x);
            float f1 = fd1 + fs.y + flo.y + w * (fhi.y - flo.y);
            float f2 = fd2 + fs.z + flo.z + w * (fhi.z - flo.z);
            float f3 = fd3 + fs.w + flo.w + w * (fhi.w - flo.w);
            float s0 = sd0 + ssv.x + slo.x + w * (shi.x - slo.x);
            float s1 = sd1 + ssv.y + slo.y + w * (shi.y - slo.y);
            float s2 = sd2 + ssv.z + slo.z + w * (shi.z - slo.z);
            float s3 = sd3 + ssv.w + slo.w + w * (shi.w - slo.w);

            a0 += sig_tanh(f0) * softplus_f(s0);
            a1 += sig_tanh(f1) * softplus_f(s1);
            a2 += sig_tanh(f2) * softplus_f(s2);
            a3 += sig_tanh(f3) * softplus_f(s3);
        }
        *(float4*)(agg + (size_t)n * H + j0) = make_float4(a0, a1, a2, a3);
    }
}

// ---------------- node epilogue ----------------
__global__ __launch_bounds__(128) void node_update_kernel(
    const float* __restrict__ xin,
    const float* __restrict__ agg1,
    const float* __restrict__ bnw1, const float* __restrict__ bnb1,
    const float* __restrict__ lnw1, const float* __restrict__ lnb1,
    const float* __restrict__ agg2,
    const float* __restrict__ bnw2, const float* __restrict__ bnb2,
    const float* __restrict__ lnw2, const float* __restrict__ lnb2,
    float* __restrict__ xout)
{
    __shared__ float sh[8];
    int i = blockIdx.x, j = threadIdx.x;
    size_t off = (size_t)i * H + j;
    float x = xin[off];
    const float bnf = rsqrtf(1.0f + 1e-5f);

    float a1 = agg1[off] * (bnw1[j] * bnf) + bnb1[j] + x;
    float s = a1, q = a1 * a1;
    block_reduce_2(s, q, sh);
    float mean = s * (1.0f / H);
    float var = q * (1.0f / H) - mean * mean;
    float y = (a1 - mean) * rsqrtf(var + 1e-5f) * lnw1[j] + lnb1[j];
    float res = fmaxf(y, 0.f) + x;

    if (agg2) {
        float a2 = agg2[off] * (bnw2[j] * bnf) + bnb2[j] + x;
        s = a2; q = a2 * a2;
        block_reduce_2(s, q, sh);
        mean = s * (1.0f / H);
        var = q * (1.0f / H) - mean * mean;
        y = (a2 - mean) * rsqrtf(var + 1e-5f) * lnw2[j] + lnb2[j];
        res += fmaxf(y, 0.f) + x;
    }
    xout[off] = res;
}

// ---------------- final: LN(xp) @ fc_w + fc_b ----------------
__global__ __launch_bounds__(128) void final_kernel(
    const float* __restrict__ xp,
    const float* __restrict__ lnw, const float* __restrict__ lnb,
    const float* __restrict__ fcw, const float* __restrict__ fcb,
    float* __restrict__ out)
{
    __shared__ float sh[8];
    __shared__ float yb[H];
    __shared__ float part[4][21];
    int i = blockIdx.x, j = threadIdx.x;
    float x = xp[(size_t)i * H + j];
    float s = x, q = x * x;
    block_reduce_2(s, q, sh);
    float mean = s * (1.0f / H);
    float var = q * (1.0f / H) - mean * mean;
    yb[j] = (x - mean) * rsqrtf(var + 1e-5f) * lnw[j] + lnb[j];
    __syncthreads();
    if (j < 84) {
        int c = j % 21, qq = j / 21;
        float acc = 0.f;
        #pragma unroll
        for (int t = 0; t < 32; ++t) acc += yb[qq * 32 + t] * fcw[(qq * 32 + t) * 21 + c];
        part[qq][c] = acc;
    }
    __syncthreads();
    if (j < 21)
        out[(size_t)i * 21 + j] = part[0][j] + part[1][j] + part[2][j] + part[3][j] + fcb[j];
}

// ---------------- host ----------------
extern "C" void kernel_launch(void* const* d_in, const int* in_sizes, int n_in,
                              void* d_out, int out_size)
{
    const float* x_protein = (const float*)d_in[0];
    const float* x_ligand  = (const float*)d_in[1];
    const int*   ei_pp     = (const int*)d_in[2];
    const float* ea_pp     = (const float*)d_in[3];
    const int*   ei_lp     = (const int*)d_in[4];
    const float* ea_lp     = (const float*)d_in[5];
    const int*   ei_pl     = (const int*)d_in[6];
    const float* ea_pl     = (const float*)d_in[7];
    const float* Wp        = (const float*)d_in[8];
    const float* bp        = (const float*)d_in[9];
    const float* Wl        = (const float*)d_in[10];
    const float* bl        = (const float*)d_in[11];
    const float* Wf        = (const float*)d_in[12];
    const float* bf        = (const float*)d_in[13];
    const float* Ws        = (const float*)d_in[14];
    const float* bs        = (const float*)d_in[15];
    const float* bn_w      = (const float*)d_in[16];
    const float* bn_b      = (const float*)d_in[17];
    const float* ln_w      = (const float*)d_in[18];
    const float* ln_b      = (const float*)d_in[19];
    const float* lno_w     = (const float*)d_in[20];
    const float* lno_b     = (const float*)d_in[21];
    const float* fc_w      = (const float*)d_in[22];
    const float* fc_b      = (const float*)d_in[23];
    float* out = (float*)d_out;

    float *xpA, *xpB, *xlA, *xlB, *Pp, *Pl, *agg_pp, *agg_lp, *agg_pl, *su, *Tb;
    int *cnt, *offs, *cur, *ssrc;
    cudaGetSymbolAddress((void**)&xpA, g_xpA);
    cudaGetSymbolAddress((void**)&xpB, g_xpB);
    cudaGetSymbolAddress((void**)&xlA, g_xlA);
    cudaGetSymbolAddress((void**)&xlB, g_xlB);
    cudaGetSymbolAddress((void**)&Pp, g_Pp);
    cudaGetSymbolAddress((void**)&Pl, g_Pl);
    cudaGetSymbolAddress((void**)&agg_pp, g_agg_pp);
    cudaGetSymbolAddress((void**)&agg_lp, g_agg_lp);
    cudaGetSymbolAddress((void**)&agg_pl, g_agg_pl);
    cudaGetSymbolAddress((void**)&Tb, g_T);
    cudaGetSymbolAddress((void**)&cnt, g_cnt);
    cudaGetSymbolAddress((void**)&offs, g_off);
    cudaGetSymbolAddress((void**)&cur, g_cur);
    cudaGetSymbolAddress((void**)&ssrc, g_ssrc);
    cudaGetSymbolAddress((void**)&su, g_su);

    cudaFuncSetAttribute(proj_mma, cudaFuncAttributeMaxDynamicSharedMemorySize, SMEM_MMA_BYTES);

    // ---- CSR build + LUT (edges are layer-invariant) ----
    cudaMemsetAsync(cnt, 0, NCNT * sizeof(int), 0);
    hist_all<<<(ETOT + 255) / 256, 256>>>(ei_pp, ei_lp, ei_pl, cnt);
    scan3<<<3, 1024>>>(cnt, offs, cur);
    scatter_all<<<(ETOT + 255) / 256, 256>>>(ei_pp, ea_pp, ei_lp, ea_lp, ei_pl, ea_pl,
                                             cur, ssrc, su);
    lut_build<<<dim3(NBIN + 1, 12), 256>>>(Wf, Ws, Tb);
    embed_kernel<<<NP + NL, 128>>>(x_protein, Wp, bp, x_ligand, Wl, bl, xpA, xlA);

    const int* off_pp = offs;
    const int* off_lp = offs + NP + 1;
    const int* off_pl = offs + 2 * NP + 2;
    const int* ssrc_pp = ssrc;
    const int* ssrc_lp = ssrc + EPP;
    const int* ssrc_pl = ssrc + EPP + ELP;
    const float* su_pp = su;
    const float* su_lp = su + EPP;
    const float* su_pl = su + EPP + ELP;

    float* xp_cur = xpA; float* xp_nxt = xpB;
    float* xl_cur = xlA; float* xl_nxt = xlB;

    for (int l = 0; l < NLAYER; ++l) {
        auto wfp = [&](int b, int r) { return Wf + ((size_t)(l * 3 + b) * 272 + r) * H; };
        auto wsp = [&](int b, int r) { return Ws + ((size_t)(l * 3 + b) * 272 + r) * H; };
        auto Tp = [&](int b) { return Tb + (size_t)(l * 3 + b) * (NBIN + 1) * 256; };

        PtrArr8 pw;
        pw.p[0] = wfp(0, 0);   pw.p[1] = wfp(0, 128);
        pw.p[2] = wsp(0, 0);   pw.p[3] = wsp(0, 128);
        pw.p[4] = wfp(1, 0);   pw.p[5] = wsp(1, 0);
        pw.p[6] = wfp(2, 128); pw.p[7] = wsp(2, 128);
        PtrArr8 lw;
        lw.p[0] = wfp(1, 128); lw.p[1] = wsp(1, 128);
        lw.p[2] = wfp(2, 0);   lw.p[3] = wsp(2, 0);
        lw.p[4] = lw.p[5] = lw.p[6] = lw.p[7] = lw.p[0];

        proj_mma<<<dim3((NP + 127) / 128, 8), 256, SMEM_MMA_BYTES>>>(xp_cur, NP, pw, Pp, 8 * H);
        proj_mma<<<dim3((NL + 127) / 128, 4), 256, SMEM_MMA_BYTES>>>(xl_cur, NL, lw, Pl, 4 * H);

        // pp: dst/src protein — one warp per dst node
        edge_csr<<<(NP + 3) / 4, 128>>>(off_pp, ssrc_pp, su_pp, NP, Tp(0),
                                        Pp, 8 * H, 0 * H, 2 * H,
                                        Pp, 8 * H, 1 * H, 3 * H,
                                        bf + (size_t)(l * 3 + 0) * H, bs + (size_t)(l * 3 + 0) * H,
                                        agg_pp);
        // lp: dst protein, src ligand
        edge_csr<<<(NP + 15) / 16, 128>>>(off_lp, ssrc_lp, su_lp, NP, Tp(1),
                                          Pp, 8 * H, 4 * H, 5 * H,
                                          Pl, 4 * H, 0 * H, 1 * H,
                                          bf + (size_t)(l * 3 + 1) * H, bs + (size_t)(l * 3 + 1) * H,
                                          agg_lp);
        // pl: dst ligand, src protein
        edge_csr<<<(NL + 3) / 4, 128>>>(off_pl, ssrc_pl, su_pl, NL, Tp(2),
                                        Pl, 4 * H, 2 * H, 3 * H,
                                        Pp, 8 * H, 6 * H, 7 * H,
                                        bf + (size_t)(l * 3 + 2) * H, bs + (size_t)(l * 3 + 2) * H,
                                        agg_pl);

        node_update_kernel<<<NP, 128>>>(xp_cur,
            agg_pp,
            bn_w + (size_t)(l * 3 + 0) * H, bn_b + (size_t)(l * 3 + 0) * H,
            ln_w + (size_t)(l * 3 + 0) * H, ln_b + (size_t)(l * 3 + 0) * H,
            agg_lp,
            bn_w + (size_t)(l * 3 + 1) * H, bn_b + (size_t)(l * 3 + 1) * H,
            ln_w + (size_t)(l * 3 + 1) * H, ln_b + (size_t)(l * 3 + 1) * H,
            xp_nxt);
        node_update_kernel<<<NL, 128>>>(xl_cur,
            agg_pl,
            bn_w + (size_t)(l * 3 + 2) * H, bn_b + (size_t)(l * 3 + 2) * H,
            ln_w + (size_t)(l * 3 + 2) * H, ln_b + (size_t)(l * 3 + 2) * H,
            (const float*)nullptr, nullptr, nullptr, nullptr, nullptr,
            xl_nxt);

        float* t;
        t = xp_cur; xp_cur = xp_nxt; xp_nxt = t;
        t = xl_cur; xl_cur = xl_nxt; xl_nxt = t;
    }

    final_kernel<<<NP, 128>>>(xp_cur, lno_w, lno_b, fc_w, fc_b, out);
}

// round 6
// speedup vs baseline: 2.5531x; 1.0071x over previous
#include <cuda_runtime.h>
#include <cstdint>
#include <cstddef>

#define NP 50000
#define NL 10000
#define H  128
#define D  16
#define NLAYER 4
#define EPP 500000
#define ELP 100000
#define EPL 100000
#define ETOT (EPP + ELP + EPL)
#define NCNT (2 * NP + NL)
#define NBIN 512

// ---------------- scratch (device globals; no runtime allocation) ----------------
__device__ float g_xpA[NP * H];
__device__ float g_xpB[NP * H];
__device__ float g_xlA[NL * H];
__device__ float g_xlB[NL * H];
__device__ float g_Pp[(size_t)NP * 8 * H];   // 8 protein projection slices (f|s pairs adjacent)
__device__ float g_Pl[(size_t)NL * 4 * H];   // 4 ligand projection slices
__device__ float g_agg_pp[NP * H];
__device__ float g_agg_lp[NP * H];
__device__ float g_agg_pl[NL * H];
// edge-weight LUT: 12 tables (layer x type), (NBIN+1) rows x 256 cols (f|s)
__device__ float g_T[(size_t)12 * (NBIN + 1) * 256];
// CSR scratch
__device__ int   g_cnt[NCNT];
__device__ int   g_off[NCNT + 3];
__device__ int   g_cur[NCNT];
__device__ int   g_ssrc[ETOT];
__device__ float g_su[ETOT];     // pre-scaled bin coordinate u = d * NBIN/8

// ---------------- small helpers ----------------
__device__ __forceinline__ void block_reduce_2(float& s, float& q, float* shbuf)
{
    unsigned m = 0xffffffffu;
    #pragma unroll
    for (int o = 16; o > 0; o >>= 1) {
        s += __shfl_down_sync(m, s, o);
        q += __shfl_down_sync(m, q, o);
    }
    int lane = threadIdx.x & 31, wid = threadIdx.x >> 5;
    if (lane == 0) { shbuf[wid] = s; shbuf[4 + wid] = q; }
    __syncthreads();
    s = shbuf[0] + shbuf[1] + shbuf[2] + shbuf[3];
    q = shbuf[4] + shbuf[5] + shbuf[6] + shbuf[7];
    __syncthreads();
}

__device__ __forceinline__ uint32_t f2tf32(float f) {
    uint32_t r;
    asm("cvt.rna.tf32.f32 %0, %1;" : "=r"(r) : "f"(f));
    return r;
}
__device__ __forceinline__ float sig_tanh(float x) {
    float t;
    asm("tanh.approx.f32 %0, %1;" : "=f"(t) : "f"(x * 0.5f));
    return 0.5f * t + 0.5f;
}
__device__ __forceinline__ float softplus_f(float x) {
    return fmaxf(x, 0.f) + __logf(1.0f + __expf(-fabsf(x)));
}

// warp-level LN + relu on float4/lane (128 values per warp)
__device__ __forceinline__ float4 cg_ln_relu(float4 a, float4 lw, float4 lb)
{
    float s = a.x + a.y + a.z + a.w;
    float q = a.x * a.x + a.y * a.y + a.z * a.z + a.w * a.w;
    #pragma unroll
    for (int o = 16; o > 0; o >>= 1) {
        s += __shfl_xor_sync(0xffffffffu, s, o);
        q += __shfl_xor_sync(0xffffffffu, q, o);
    }
    float mean = s * (1.0f / H);
    float var = q * (1.0f / H) - mean * mean;
    float r = rsqrtf(var + 1e-5f);
    float4 y;
    y.x = fmaxf((a.x - mean) * r * lw.x + lb.x, 0.f);
    y.y = fmaxf((a.y - mean) * r * lw.y + lb.y, 0.f);
    y.z = fmaxf((a.z - mean) * r * lw.z + lb.z, 0.f);
    y.w = fmaxf((a.w - mean) * r * lw.w + lb.w, 0.f);
    return y;
}

// ---------------- CSR build: histogram over all 3 edge sets ----------------
__global__ void hist_all(const int* __restrict__ ei_pp, const int* __restrict__ ei_lp,
                         const int* __restrict__ ei_pl, int* __restrict__ cnt)
{
    int idx = blockIdx.x * blockDim.x + threadIdx.x;
    if (idx >= ETOT) return;
    if (idx < EPP) {
        atomicAdd(&cnt[ei_pp[EPP + idx]], 1);
    } else if (idx < EPP + ELP) {
        int e = idx - EPP;
        atomicAdd(&cnt[NP + ei_lp[ELP + e]], 1);
    } else {
        int e = idx - EPP - ELP;
        atomicAdd(&cnt[2 * NP + ei_pl[EPL + e]], 1);
    }
}

// ---------------- 3-segment exclusive scan ----------------
__device__ void scan_seg(const int* __restrict__ cnt, int N, int* __restrict__ off,
                         int* __restrict__ cur)
{
    __shared__ int s[1024];
    __shared__ int base;
    if (threadIdx.x == 0) base = 0;
    __syncthreads();
    for (int c = 0; c < N; c += 1024) {
        int i = c + threadIdx.x;
        int v = (i < N) ? cnt[i] : 0;
        s[threadIdx.x] = v;
        __syncthreads();
        #pragma unroll
        for (int o = 1; o < 1024; o <<= 1) {
            int t = (threadIdx.x >= (unsigned)o) ? s[threadIdx.x - o] : 0;
            __syncthreads();
            s[threadIdx.x] += t;
            __syncthreads();
        }
        int excl = base + s[threadIdx.x] - v;
        if (i < N) { off[i] = excl; cur[i] = excl; }
        int tot = s[1023];
        __syncthreads();
        if (threadIdx.x == 0) base += tot;
        __syncthreads();
    }
    if (threadIdx.x == 0) off[N] = base;
}

__global__ void scan3(int* __restrict__ cnt, int* __restrict__ off, int* __restrict__ cur)
{
    if (blockIdx.x == 0)      scan_seg(cnt,          NP, off,              cur);
    else if (blockIdx.x == 1) scan_seg(cnt + NP,     NP, off + NP + 1,     cur + NP);
    else                      scan_seg(cnt + 2 * NP, NL, off + 2 * NP + 2, cur + 2 * NP);
}

// ---------------- scatter edges into dst-sorted order (store bin coord) ----------------
__global__ void scatter_all(const int* __restrict__ ei_pp, const float* __restrict__ ea_pp,
                            const int* __restrict__ ei_lp, const float* __restrict__ ea_lp,
                            const int* __restrict__ ei_pl, const float* __restrict__ ea_pl,
                            int* __restrict__ cur, int* __restrict__ ssrc,
                            float* __restrict__ su)
{
    const float usc = (float)NBIN / 8.0f;
    int idx = blockIdx.x * blockDim.x + threadIdx.x;
    if (idx >= ETOT) return;
    if (idx < EPP) {
        int e = idx;
        int d = ei_pp[EPP + e];
        int p = atomicAdd(&cur[d], 1);
        ssrc[p] = ei_pp[e];
        su[p] = ea_pp[e] * usc;
    } else if (idx < EPP + ELP) {
        int e = idx - EPP;
        int d = ei_lp[ELP + e];
        int p = EPP + atomicAdd(&cur[NP + d], 1);
        ssrc[p] = ei_lp[e];
        su[p] = ea_lp[e] * usc;
    } else {
        int e = idx - EPP - ELP;
        int d = ei_pl[EPL + e];
        int p = EPP + ELP + atomicAdd(&cur[2 * NP + d], 1);
        ssrc[p] = ei_pl[e];
        su[p] = ea_pl[e] * usc;
    }
}

// ---------------- LUT build: T[lt][bin][j] = rbf(d_bin) @ We_{f|s}[lt] ----------------
__global__ __launch_bounds__(256) void lut_build(
    const float* __restrict__ Wf, const float* __restrict__ Ws, float* __restrict__ T)
{
    int b = blockIdx.x;        // 0..NBIN
    int lt = blockIdx.y;       // 0..11  (layer*3 + type)
    int j = threadIdx.x;       // 0..255 : 0-127 -> f, 128-255 -> s
    float d = (float)b * (8.0f / (float)NBIN);
    const float step = 8.0f / 15.0f;
    const float coeff = -0.5f / (step * step);
    float r[16];
    #pragma unroll
    for (int k = 0; k < 16; ++k) {
        float dlt = d - (float)k * step;
        r[k] = __expf(coeff * dlt * dlt);
    }
    const float* W = (j < 128 ? Wf : Ws) + ((size_t)lt * 272 + 256) * H + (j & 127);
    float acc = 0.f;
    #pragma unroll
    for (int k = 0; k < 16; ++k) acc += r[k] * W[(size_t)k * H];
    T[((size_t)lt * (NBIN + 1) + b) * 256 + j] = acc;
}

// ---------------- merged initial embedding ----------------
__global__ __launch_bounds__(128) void embed_kernel(
    const float* __restrict__ xp, const float* __restrict__ Wp, const float* __restrict__ bp,
    const float* __restrict__ xl, const float* __restrict__ Wl, const float* __restrict__ bl,
    float* __restrict__ outp, float* __restrict__ outl)
{
    int i = blockIdx.x;
    int j = threadIdx.x;
    const float *x, *W, *b; float* o; int r;
    if (i < NP) { x = xp; W = Wp; b = bp; o = outp; r = i; }
    else        { x = xl; W = Wl; b = bl; o = outl; r = i - NP; }
    const float* xr = x + (size_t)r * 6;
    float acc = b[j];
    #pragma unroll
    for (int k = 0; k < 6; ++k) acc += xr[k] * W[k * H + j];
    o[(size_t)r * H + j] = acc;
}

// ---------------- tf32 mma.sync projection GEMM ----------------
struct PtrArr8 { const float* p[8]; };

#define APITCH 132
#define SMEM_B_FLOAT (128 * APITCH)
#define SMEM_MMA_BYTES (2 * 128 * APITCH * 4)

__global__ __launch_bounds__(256) void proj_mma(
    const float* __restrict__ X, int N, PtrArr8 wp,
    float* __restrict__ out, int outStride)
{
    extern __shared__ uint32_t sm[];
    uint32_t* As = sm;
    uint32_t* Bs = sm + SMEM_B_FLOAT;

    const float* W = wp.p[blockIdx.y];
    int m0 = blockIdx.x * 128;
    int tid = threadIdx.x;
    int lane = tid & 31, warp = tid >> 5;
    int g = lane >> 2, t = lane & 3;

    #pragma unroll
    for (int it = 0; it < 16; ++it) {
        int idx = it * 256 + tid;
        int r = idx >> 5, c4 = (idx & 31) * 4;
        float4 av = make_float4(0.f, 0.f, 0.f, 0.f);
        if (m0 + r < N) av = *(const float4*)(X + (size_t)(m0 + r) * H + c4);
        uint32_t* ap = As + r * APITCH + c4;
        ap[0] = f2tf32(av.x); ap[1] = f2tf32(av.y);
        ap[2] = f2tf32(av.z); ap[3] = f2tf32(av.w);
        float4 bv = *(const float4*)(W + (size_t)r * H + c4);
        uint32_t* bp2 = Bs + r * APITCH + c4;
        bp2[0] = f2tf32(bv.x); bp2[1] = f2tf32(bv.y);
        bp2[2] = f2tf32(bv.z); bp2[3] = f2tf32(bv.w);
    }
    __syncthreads();

    int wm = warp >> 2;
    int wn = warp & 3;
    int mbase = wm * 64;
    int nbase = wn * 32;

    float d[4][4][4];
    #pragma unroll
    for (int i = 0; i < 4; ++i)
        #pragma unroll
        for (int j = 0; j < 4; ++j)
            #pragma unroll
            for (int q = 0; q < 4; ++q) d[i][j][q] = 0.f;

    #pragma unroll
    for (int ks = 0; ks < 16; ++ks) {
        int kb = ks * 8;
        uint32_t a[4][4];
        #pragma unroll
        for (int i = 0; i < 4; ++i) {
            int r0 = mbase + i * 16 + g;
            a[i][0] = As[r0 * APITCH + kb + t];
            a[i][1] = As[(r0 + 8) * APITCH + kb + t];
            a[i][2] = As[r0 * APITCH + kb + 4 + t];
            a[i][3] = As[(r0 + 8) * APITCH + kb + 4 + t];
        }
        uint32_t b[4][2];
        #pragma unroll
        for (int j = 0; j < 4; ++j) {
            int c0 = nbase + j * 8 + g;
            b[j][0] = Bs[(kb + t) * APITCH + c0];
            b[j][1] = Bs[(kb + 4 + t) * APITCH + c0];
        }
        #pragma unroll
        for (int i = 0; i < 4; ++i)
            #pragma unroll
            for (int j = 0; j < 4; ++j) {
                asm volatile(
                    "mma.sync.aligned.m16n8k8.row.col.f32.tf32.tf32.f32 "
                    "{%0,%1,%2,%3}, {%4,%5,%6,%7}, {%8,%9}, {%0,%1,%2,%3};"
                    : "+f"(d[i][j][0]), "+f"(d[i][j][1]), "+f"(d[i][j][2]), "+f"(d[i][j][3])
                    : "r"(a[i][0]), "r"(a[i][1]), "r"(a[i][2]), "r"(a[i][3]),
                      "r"(b[j][0]), "r"(b[j][1]));
            }
    }

    size_t colbase = (size_t)blockIdx.y * H;
    #pragma unroll
    for (int i = 0; i < 4; ++i) {
        int gr0 = m0 + mbase + i * 16 + g;
        int gr1 = gr0 + 8;
        #pragma unroll
        for (int j = 0; j < 4; ++j) {
            int gc = nbase + j * 8 + t * 2;
            if (gr0 < N)
                *(float2*)(out + (size_t)gr0 * outStride + colbase + gc) =
                    make_float2(d[i][j][0], d[i][j][1]);
            if (gr1 < N)
                *(float2*)(out + (size_t)gr1 * outStride + colbase + gc) =
                    make_float2(d[i][j][2], d[i][j][3]);
        }
    }
}

// ---------------- CSR edge kernel with LUT: warp per dst node, pipelined ----------------
__global__ __launch_bounds__(256) void edge_csr(
    const int* __restrict__ off, const int* __restrict__ ssrc,
    const float* __restrict__ su, int Ndst,
    const float* __restrict__ T,                       // (NBIN+1) x 256
    const float* __restrict__ PdstF, int dstStride,    // f at +0, s at +H
    const float* __restrict__ PsrcF, int srcStride,
    const float* __restrict__ bfp, const float* __restrict__ bsp,
    float* __restrict__ agg)
{
    int lane = threadIdx.x & 31;
    int j0 = lane * 4;

    float4 bf4 = *(const float4*)(bfp + j0);
    float4 bs4 = *(const float4*)(bsp + j0);

    int gw = blockIdx.x * 8 + (threadIdx.x >> 5);
    int nw = gridDim.x * 8;

    for (int n = gw; n < Ndst; n += nw) {
        int p0 = off[n], p1 = off[n + 1];
        const float* pd = PdstF + (size_t)n * dstStride + j0;
        float4 fdv = *(const float4*)(pd);
        float4 sdv = *(const float4*)(pd + H);
        float fd0 = fdv.x + bf4.x, fd1 = fdv.y + bf4.y, fd2 = fdv.z + bf4.z, fd3 = fdv.w + bf4.w;
        float sd0 = sdv.x + bs4.x, sd1 = sdv.y + bs4.y, sd2 = sdv.z + bs4.z, sd3 = sdv.w + bs4.w;

        float a0 = 0.f, a1 = 0.f, a2 = 0.f, a3 = 0.f;

        int src = 0; float u = 0.f;
        if (p0 < p1) { src = ssrc[p0]; u = su[p0]; }

        #pragma unroll 2
        for (int p = p0; p < p1; ++p) {
            const float* ps = PsrcF + (size_t)src * srcStride + j0;
            float4 fs = *(const float4*)(ps);
            float4 ssv = *(const float4*)(ps + H);

            int b = min((int)u, NBIN - 1);
            float w = u - (float)b;
            const float* Tb = T + (size_t)b * 256 + j0;
            float4 flo = *(const float4*)(Tb);
            float4 fhi = *(const float4*)(Tb + 256);
            float4 slo = *(const float4*)(Tb + 128);
            float4 shi = *(const float4*)(Tb + 384);

            // prefetch next edge's index/coord before the math
            if (p + 1 < p1) { src = ssrc[p + 1]; u = su[p + 1]; }

            float f0 = fd0 + fs.x + flo.x + w * (fhi.x - flo.x);
            float f1 = fd1 + fs.y + flo.y + w * (fhi.y - flo.y);
            float f2 = fd2 + fs.z + flo.z + w * (fhi.z - flo.z);
            float f3 = fd3 + fs.w + flo.w + w * (fhi.w - flo.w);
            float s0 = sd0 + ssv.x + slo.x + w * (shi.x - slo.x);
            float s1 = sd1 + ssv.y + slo.y + w * (shi.y - slo.y);
            float s2 = sd2 + ssv.z + slo.z + w * (shi.z - slo.z);
            float s3 = sd3 + ssv.w + slo.w + w * (shi.w - slo.w);

            a0 += sig_tanh(f0) * softplus_f(s0);
            a1 += sig_tanh(f1) * softplus_f(s1);
            a2 += sig_tanh(f2) * softplus_f(s2);
            a3 += sig_tanh(f3) * softplus_f(s3);
        }
        *(float4*)(agg + (size_t)n * H + j0) = make_float4(a0, a1, a2, a3);
    }
}

// ---------------- merged node epilogue: warp per node, shfl-only LN ----------------
__global__ __launch_bounds__(256) void node_update(
    const float* __restrict__ xp_in, const float* __restrict__ agg_pp,
    const float* __restrict__ agg_lp,
    const float* __restrict__ xl_in, const float* __restrict__ agg_pl,
    const float* __restrict__ bn_w, const float* __restrict__ bn_b,
    const float* __restrict__ ln_w, const float* __restrict__ ln_b, int l,
    float* __restrict__ xp_out, float* __restrict__ xl_out)
{
    int w = blockIdx.x * 8 + (threadIdx.x >> 5);
    int lane = threadIdx.x & 31;
    int j0 = lane * 4;
    const float bnf = rsqrtf(1.0f + 1e-5f);

    if (w < NP) {
        size_t off = (size_t)w * H + j0;
        float4 x = *(const float4*)(xp_in + off);

        // block 0 (pp)
        size_t pb0 = (size_t)(l * 3 + 0) * H + j0;
        float4 bw = *(const float4*)(bn_w + pb0);
        float4 bb = *(const float4*)(bn_b + pb0);
        float4 lw = *(const float4*)(ln_w + pb0);
        float4 lb = *(const float4*)(ln_b + pb0);
        float4 g = *(const float4*)(agg_pp + off);
        float4 a;
        a.x = g.x * (bw.x * bnf) + bb.x + x.x;
        a.y = g.y * (bw.y * bnf) + bb.y + x.y;
        a.z = g.z * (bw.z * bnf) + bb.z + x.z;
        a.w = g.w * (bw.w * bnf) + bb.w + x.w;
        float4 y1 = cg_ln_relu(a, lw, lb);

        // block 1 (lp)
        size_t pb1 = (size_t)(l * 3 + 1) * H + j0;
        bw = *(const float4*)(bn_w + pb1);
        bb = *(const float4*)(bn_b + pb1);
        lw = *(const float4*)(ln_w + pb1);
        lb = *(const float4*)(ln_b + pb1);
        g = *(const float4*)(agg_lp + off);
        a.x = g.x * (bw.x * bnf) + bb.x + x.x;
        a.y = g.y * (bw.y * bnf) + bb.y + x.y;
        a.z = g.z * (bw.z * bnf) + bb.z + x.z;
        a.w = g.w * (bw.w * bnf) + bb.w + x.w;
        float4 y2 = cg_ln_relu(a, lw, lb);

        float4 r;
        r.x = y1.x + y2.x + 2.f * x.x;
        r.y = y1.y + y2.y + 2.f * x.y;
        r.z = y1.z + y2.z + 2.f * x.z;
        r.w = y1.w + y2.w + 2.f * x.w;
        *(float4*)(xp_out + off) = r;
    } else if (w < NP + NL) {
        int i = w - NP;
        size_t off = (size_t)i * H + j0;
        float4 x = *(const float4*)(xl_in + off);
        size_t pb2 = (size_t)(l * 3 + 2) * H + j0;
        float4 bw = *(const float4*)(bn_w + pb2);
        float4 bb = *(const float4*)(bn_b + pb2);
        float4 lw = *(const float4*)(ln_w + pb2);
        float4 lb = *(const float4*)(ln_b + pb2);
        float4 g = *(const float4*)(agg_pl + off);
        float4 a;
        a.x = g.x * (bw.x * bnf) + bb.x + x.x;
        a.y = g.y * (bw.y * bnf) + bb.y + x.y;
        a.z = g.z * (bw.z * bnf) + bb.z + x.z;
        a.w = g.w * (bw.w * bnf) + bb.w + x.w;
        float4 y = cg_ln_relu(a, lw, lb);
        float4 r;
        r.x = y.x + x.x; r.y = y.y + x.y; r.z = y.z + x.z; r.w = y.w + x.w;
        *(float4*)(xl_out + off) = r;
    }
}

// ---------------- final: LN(xp) @ fc_w + fc_b ----------------
__global__ __launch_bounds__(128) void final_kernel(
    const float* __restrict__ xp,
    const float* __restrict__ lnw, const float* __restrict__ lnb,
    const float* __restrict__ fcw, const float* __restrict__ fcb,
    float* __restrict__ out)
{
    __shared__ float sh[8];
    __shared__ float yb[H];
    __shared__ float part[4][21];
    int i = blockIdx.x, j = threadIdx.x;
    float x = xp[(size_t)i * H + j];
    float s = x, q = x * x;
    block_reduce_2(s, q, sh);
    float mean = s * (1.0f / H);
    float var = q * (1.0f / H) - mean * mean;
    yb[j] = (x - mean) * rsqrtf(var + 1e-5f) * lnw[j] + lnb[j];
    __syncthreads();
    if (j < 84) {
        int c = j % 21, qq = j / 21;
        float acc = 0.f;
        #pragma unroll
        for (int t = 0; t < 32; ++t) acc += yb[qq * 32 + t] * fcw[(qq * 32 + t) * 21 + c];
        part[qq][c] = acc;
    }
    __syncthreads();
    if (j < 21)
        out[(size_t)i * 21 + j] = part[0][j] + part[1][j] + part[2][j] + part[3][j] + fcb[j];
}

// ---------------- host ----------------
extern "C" void kernel_launch(void* const* d_in, const int* in_sizes, int n_in,
                              void* d_out, int out_size)
{
    const float* x_protein = (const float*)d_in[0];
    const float* x_ligand  = (const float*)d_in[1];
    const int*   ei_pp     = (const int*)d_in[2];
    const float* ea_pp     = (const float*)d_in[3];
    const int*   ei_lp     = (const int*)d_in[4];
    const float* ea_lp     = (const float*)d_in[5];
    const int*   ei_pl     = (const int*)d_in[6];
    const float* ea_pl     = (const float*)d_in[7];
    const float* Wp        = (const float*)d_in[8];
    const float* bp        = (const float*)d_in[9];
    const float* Wl        = (const float*)d_in[10];
    const float* bl        = (const float*)d_in[11];
    const float* Wf        = (const float*)d_in[12];
    const float* bf        = (const float*)d_in[13];
    const float* Ws        = (const float*)d_in[14];
    const float* bs        = (const float*)d_in[15];
    const float* bn_w      = (const float*)d_in[16];
    const float* bn_b      = (const float*)d_in[17];
    const float* ln_w      = (const float*)d_in[18];
    const float* ln_b      = (const float*)d_in[19];
    const float* lno_w     = (const float*)d_in[20];
    const float* lno_b     = (const float*)d_in[21];
    const float* fc_w      = (const float*)d_in[22];
    const float* fc_b      = (const float*)d_in[23];
    float* out = (float*)d_out;

    float *xpA, *xpB, *xlA, *xlB, *Pp, *Pl, *agg_pp, *agg_lp, *agg_pl, *su, *Tb;
    int *cnt, *offs, *cur, *ssrc;
    cudaGetSymbolAddress((void**)&xpA, g_xpA);
    cudaGetSymbolAddress((void**)&xpB, g_xpB);
    cudaGetSymbolAddress((void**)&xlA, g_xlA);
    cudaGetSymbolAddress((void**)&xlB, g_xlB);
    cudaGetSymbolAddress((void**)&Pp, g_Pp);
    cudaGetSymbolAddress((void**)&Pl, g_Pl);
    cudaGetSymbolAddress((void**)&agg_pp, g_agg_pp);
    cudaGetSymbolAddress((void**)&agg_lp, g_agg_lp);
    cudaGetSymbolAddress((void**)&agg_pl, g_agg_pl);
    cudaGetSymbolAddress((void**)&Tb, g_T);
    cudaGetSymbolAddress((void**)&cnt, g_cnt);
    cudaGetSymbolAddress((void**)&offs, g_off);
    cudaGetSymbolAddress((void**)&cur, g_cur);
    cudaGetSymbolAddress((void**)&ssrc, g_ssrc);
    cudaGetSymbolAddress((void**)&su, g_su);

    cudaFuncSetAttribute(proj_mma, cudaFuncAttributeMaxDynamicSharedMemorySize, SMEM_MMA_BYTES);

    // ---- CSR build + LUT (edges are layer-invariant) ----
    cudaMemsetAsync(cnt, 0, NCNT * sizeof(int), 0);
    hist_all<<<(ETOT + 255) / 256, 256>>>(ei_pp, ei_lp, ei_pl, cnt);
    scan3<<<3, 1024>>>(cnt, offs, cur);
    scatter_all<<<(ETOT + 255) / 256, 256>>>(ei_pp, ea_pp, ei_lp, ea_lp, ei_pl, ea_pl,
                                             cur, ssrc, su);
    lut_build<<<dim3(NBIN + 1, 12), 256>>>(Wf, Ws, Tb);
    embed_kernel<<<NP + NL, 128>>>(x_protein, Wp, bp, x_ligand, Wl, bl, xpA, xlA);

    const int* off_pp = offs;
    const int* off_lp = offs + NP + 1;
    const int* off_pl = offs + 2 * NP + 2;
    const int* ssrc_pp = ssrc;
    const int* ssrc_lp = ssrc + EPP;
    const int* ssrc_pl = ssrc + EPP + ELP;
    const float* su_pp = su;
    const float* su_lp = su + EPP;
    const float* su_pl = su + EPP + ELP;

    float* xp_cur = xpA; float* xp_nxt = xpB;
    float* xl_cur = xlA; float* xl_nxt = xlB;

    for (int l = 0; l < NLAYER; ++l) {
        auto wfp = [&](int b, int r) { return Wf + ((size_t)(l * 3 + b) * 272 + r) * H; };
        auto wsp = [&](int b, int r) { return Ws + ((size_t)(l * 3 + b) * 272 + r) * H; };
        auto Tp = [&](int b) { return Tb + (size_t)(l * 3 + b) * (NBIN + 1) * 256; };

        // slice layout (f|s pairs adjacent):
        // Pp: 0 pp_dst_f | 1 pp_dst_s | 2 pp_src_f | 3 pp_src_s
        //     4 lp_dst_f | 5 lp_dst_s | 6 pl_src_f | 7 pl_src_s
        PtrArr8 pw;
        pw.p[0] = wfp(0, 0);   pw.p[1] = wsp(0, 0);
        pw.p[2] = wfp(0, 128); pw.p[3] = wsp(0, 128);
        pw.p[4] = wfp(1, 0);   pw.p[5] = wsp(1, 0);
        pw.p[6] = wfp(2, 128); pw.p[7] = wsp(2, 128);
        // Pl: 0 lp_src_f | 1 lp_src_s | 2 pl_dst_f | 3 pl_dst_s
        PtrArr8 lw;
        lw.p[0] = wfp(1, 128); lw.p[1] = wsp(1, 128);
        lw.p[2] = wfp(2, 0);   lw.p[3] = wsp(2, 0);
        lw.p[4] = lw.p[5] = lw.p[6] = lw.p[7] = lw.p[0];

        proj_mma<<<dim3((NP + 127) / 128, 8), 256, SMEM_MMA_BYTES>>>(xp_cur, NP, pw, Pp, 8 * H);
        proj_mma<<<dim3((NL + 127) / 128, 4), 256, SMEM_MMA_BYTES>>>(xl_cur, NL, lw, Pl, 4 * H);

        // pp: dst/src protein — warp per dst node
        edge_csr<<<(NP + 7) / 8, 256>>>(off_pp, ssrc_pp, su_pp, NP, Tp(0),
                                        Pp + 0 * H, 8 * H,
                                        Pp + 2 * H, 8 * H,
                                        bf + (size_t)(l * 3 + 0) * H, bs + (size_t)(l * 3 + 0) * H,
                                        agg_pp);
        // lp: dst protein, src ligand
        edge_csr<<<(NP + 7) / 8, 256>>>(off_lp, ssrc_lp, su_lp, NP, Tp(1),
                                        Pp + 4 * H, 8 * H,
                                        Pl + 0 * H, 4 * H,
                                        bf + (size_t)(l * 3 + 1) * H, bs + (size_t)(l * 3 + 1) * H,
                                        agg_lp);
        // pl: dst ligand, src protein
        edge_csr<<<(NL + 7) / 8, 256>>>(off_pl, ssrc_pl, su_pl, NL, Tp(2),
                                        Pl + 2 * H, 4 * H,
                                        Pp + 6 * H, 8 * H,
                                        bf + (size_t)(l * 3 + 2) * H, bs + (size_t)(l * 3 + 2) * H,
                                        agg_pl);

        node_update<<<(NP + NL + 7) / 8, 256>>>(xp_cur, agg_pp, agg_lp,
                                                xl_cur, agg_pl,
                                                bn_w, bn_b, ln_w, ln_b, l,
                                                xp_nxt, xl_nxt);

        float* t;
        t = xp_cur; xp_cur = xp_nxt; xp_nxt = t;
        t = xl_cur; xl_cur = xl_nxt; xl_nxt = t;
    }

    final_kernel<<<NP, 128>>>(xp_cur, lno_w, lno_b, fc_w, fc_b, out);
}

// round 7
// speedup vs baseline: 2.7895x; 1.0926x over previous
#include <cuda_runtime.h>
#include <cstdint>
#include <cstddef>

#define NP 50000
#define NL 10000
#define H  128
#define D  16
#define NLAYER 4
#define EPP 500000
#define ELP 100000
#define EPL 100000
#define ETOT (EPP + ELP + EPL)
#define NCNT (2 * NP + NL)
#define NBIN 512
#define CH0 49
#define CH1 49
#define CH2 10
#define CHT (CH0 + CH1 + CH2)

// ---------------- scratch (device globals; no runtime allocation) ----------------
__device__ float g_xpA[NP * H];
__device__ float g_xpB[NP * H];
__device__ float g_xlA[NL * H];
__device__ float g_xlB[NL * H];
__device__ float g_Pp[(size_t)NP * 8 * H];   // 8 protein projection slices (f|s pairs adjacent)
__device__ float g_Pl[(size_t)NL * 4 * H];   // 4 ligand projection slices
__device__ float g_agg_pp[NP * H];
__device__ float g_agg_lp[NP * H];
__device__ float g_agg_pl[NL * H];
__device__ float g_T[(size_t)12 * (NBIN + 1) * 256];
// CSR scratch
__device__ int   g_cnt[NCNT];
__device__ int   g_off[NCNT + 3];
__device__ int   g_cur[NCNT];
__device__ int   g_ssrc[ETOT];
__device__ float g_su[ETOT];
__device__ int   g_chunksum[CHT];
__device__ int   g_chunkbase[CHT];

// ---------------- small helpers ----------------
__device__ __forceinline__ void block_reduce_2(float& s, float& q, float* shbuf)
{
    unsigned m = 0xffffffffu;
    #pragma unroll
    for (int o = 16; o > 0; o >>= 1) {
        s += __shfl_down_sync(m, s, o);
        q += __shfl_down_sync(m, q, o);
    }
    int lane = threadIdx.x & 31, wid = threadIdx.x >> 5;
    if (lane == 0) { shbuf[wid] = s; shbuf[4 + wid] = q; }
    __syncthreads();
    s = shbuf[0] + shbuf[1] + shbuf[2] + shbuf[3];
    q = shbuf[4] + shbuf[5] + shbuf[6] + shbuf[7];
    __syncthreads();
}

__device__ __forceinline__ uint32_t f2tf32(float f) {
    uint32_t r;
    asm("cvt.rna.tf32.f32 %0, %1;" : "=r"(r) : "f"(f));
    return r;
}
__device__ __forceinline__ float sig_tanh(float x) {
    float t;
    asm("tanh.approx.f32 %0, %1;" : "=f"(t) : "f"(x * 0.5f));
    return 0.5f * t + 0.5f;
}
__device__ __forceinline__ float softplus_f(float x) {
    return fmaxf(x, 0.f) + __logf(1.0f + __expf(-fabsf(x)));
}

__device__ __forceinline__ float4 cg_ln_relu(float4 a, float4 lw, float4 lb)
{
    float s = a.x + a.y + a.z + a.w;
    float q = a.x * a.x + a.y * a.y + a.z * a.z + a.w * a.w;
    #pragma unroll
    for (int o = 16; o > 0; o >>= 1) {
        s += __shfl_xor_sync(0xffffffffu, s, o);
        q += __shfl_xor_sync(0xffffffffu, q, o);
    }
    float mean = s * (1.0f / H);
    float var = q * (1.0f / H) - mean * mean;
    float r = rsqrtf(var + 1e-5f);
    float4 y;
    y.x = fmaxf((a.x - mean) * r * lw.x + lb.x, 0.f);
    y.y = fmaxf((a.y - mean) * r * lw.y + lb.y, 0.f);
    y.z = fmaxf((a.z - mean) * r * lw.z + lb.z, 0.f);
    y.w = fmaxf((a.w - mean) * r * lw.w + lb.w, 0.f);
    return y;
}

// ---------------- CSR build ----------------
__global__ void hist_all(const int* __restrict__ ei_pp, const int* __restrict__ ei_lp,
                         const int* __restrict__ ei_pl, int* __restrict__ cnt)
{
    int idx = blockIdx.x * blockDim.x + threadIdx.x;
    if (idx >= ETOT) return;
    if (idx < EPP) {
        atomicAdd(&cnt[ei_pp[EPP + idx]], 1);
    } else if (idx < EPP + ELP) {
        int e = idx - EPP;
        atomicAdd(&cnt[NP + ei_lp[ELP + e]], 1);
    } else {
        int e = idx - EPP - ELP;
        atomicAdd(&cnt[2 * NP + ei_pl[EPL + e]], 1);
    }
}

// parallel scan: A local chunk scans, B chunk-total scan, C add bases
__global__ __launch_bounds__(1024) void scanA(const int* __restrict__ cnt,
                                              int* __restrict__ off,
                                              int* __restrict__ chunksum)
{
    __shared__ int s[1024];
    int bid = blockIdx.x;
    const int* cbase; int* obase; int N; int c;
    if (bid < CH0)            { cbase = cnt;          obase = off;              N = NP; c = bid; }
    else if (bid < CH0 + CH1) { cbase = cnt + NP;     obase = off + NP + 1;     N = NP; c = bid - CH0; }
    else                      { cbase = cnt + 2 * NP; obase = off + 2 * NP + 2; N = NL; c = bid - CH0 - CH1; }
    int tid = threadIdx.x;
    int i = c * 1024 + tid;
    int v = (i < N) ? cbase[i] : 0;
    s[tid] = v;
    __syncthreads();
    #pragma unroll
    for (int o = 1; o < 1024; o <<= 1) {
        int t = (tid >= o) ? s[tid - o] : 0;
        __syncthreads();
        s[tid] += t;
        __syncthreads();
    }
    if (i < N) obase[i] = s[tid] - v;
    if (tid == 1023) chunksum[bid] = s[1023];
}

__global__ void scanB(const int* __restrict__ chunksum, int* __restrict__ chunkbase,
                      int* __restrict__ off)
{
    int t = threadIdx.x;
    if (t == 0) {
        int b = 0;
        for (int c = 0; c < CH0; ++c) { chunkbase[c] = b; b += chunksum[c]; }
        off[NP] = b;
    } else if (t == 1) {
        int b = 0;
        for (int c = 0; c < CH1; ++c) { chunkbase[CH0 + c] = b; b += chunksum[CH0 + c]; }
        off[NP + 1 + NP] = b;
    } else if (t == 2) {
        int b = 0;
        for (int c = 0; c < CH2; ++c) { chunkbase[CH0 + CH1 + c] = b; b += chunksum[CH0 + CH1 + c]; }
        off[2 * NP + 2 + NL] = b;
    }
}

__global__ __launch_bounds__(1024) void scanC(int* __restrict__ off,
                                              const int* __restrict__ chunkbase,
                                              int* __restrict__ cur)
{
    int bid = blockIdx.x;
    int* obase; int* curb; int N; int c;
    if (bid < CH0)            { obase = off;              curb = cur;          N = NP; c = bid; }
    else if (bid < CH0 + CH1) { obase = off + NP + 1;     curb = cur + NP;     N = NP; c = bid - CH0; }
    else                      { obase = off + 2 * NP + 2; curb = cur + 2 * NP; N = NL; c = bid - CH0 - CH1; }
    int i = c * 1024 + threadIdx.x;
    if (i < N) {
        int v = obase[i] + chunkbase[bid];
        obase[i] = v;
        curb[i] = v;
    }
}

__global__ void scatter_all(const int* __restrict__ ei_pp, const float* __restrict__ ea_pp,
                            const int* __restrict__ ei_lp, const float* __restrict__ ea_lp,
                            const int* __restrict__ ei_pl, const float* __restrict__ ea_pl,
                            int* __restrict__ cur, int* __restrict__ ssrc,
                            float* __restrict__ su)
{
    const float usc = (float)NBIN / 8.0f;
    int idx = blockIdx.x * blockDim.x + threadIdx.x;
    if (idx >= ETOT) return;
    if (idx < EPP) {
        int e = idx;
        int d = ei_pp[EPP + e];
        int p = atomicAdd(&cur[d], 1);
        ssrc[p] = ei_pp[e];
        su[p] = ea_pp[e] * usc;
    } else if (idx < EPP + ELP) {
        int e = idx - EPP;
        int d = ei_lp[ELP + e];
        int p = EPP + atomicAdd(&cur[NP + d], 1);
        ssrc[p] = ei_lp[e];
        su[p] = ea_lp[e] * usc;
    } else {
        int e = idx - EPP - ELP;
        int d = ei_pl[EPL + e];
        int p = EPP + ELP + atomicAdd(&cur[2 * NP + d], 1);
        ssrc[p] = ei_pl[e];
        su[p] = ea_pl[e] * usc;
    }
}

// ---------------- LUT build ----------------
__global__ __launch_bounds__(256) void lut_build(
    const float* __restrict__ Wf, const float* __restrict__ Ws, float* __restrict__ T)
{
    int b = blockIdx.x;
    int lt = blockIdx.y;
    int j = threadIdx.x;
    float d = (float)b * (8.0f / (float)NBIN);
    const float step = 8.0f / 15.0f;
    const float coeff = -0.5f / (step * step);
    float r[16];
    #pragma unroll
    for (int k = 0; k < 16; ++k) {
        float dlt = d - (float)k * step;
        r[k] = __expf(coeff * dlt * dlt);
    }
    const float* W = (j < 128 ? Wf : Ws) + ((size_t)lt * 272 + 256) * H + (j & 127);
    float acc = 0.f;
    #pragma unroll
    for (int k = 0; k < 16; ++k) acc += r[k] * W[(size_t)k * H];
    T[((size_t)lt * (NBIN + 1) + b) * 256 + j] = acc;
}

// ---------------- merged initial embedding ----------------
__global__ __launch_bounds__(128) void embed_kernel(
    const float* __restrict__ xp, const float* __restrict__ Wp, const float* __restrict__ bp,
    const float* __restrict__ xl, const float* __restrict__ Wl, const float* __restrict__ bl,
    float* __restrict__ outp, float* __restrict__ outl)
{
    int i = blockIdx.x;
    int j = threadIdx.x;
    const float *x, *W, *b; float* o; int r;
    if (i < NP) { x = xp; W = Wp; b = bp; o = outp; r = i; }
    else        { x = xl; W = Wl; b = bl; o = outl; r = i - NP; }
    const float* xr = x + (size_t)r * 6;
    float acc = b[j];
    #pragma unroll
    for (int k = 0; k < 6; ++k) acc += xr[k] * W[k * H + j];
    o[(size_t)r * H + j] = acc;
}

// ---------------- merged tf32 mma.sync projection GEMM ----------------
struct PtrArr12 { const float* p[12]; };

#define APITCH 132
#define SMEM_B_FLOAT (128 * APITCH)
#define SMEM_MMA_BYTES (2 * 128 * APITCH * 4)

__global__ __launch_bounds__(256) void proj_mma(
    const float* __restrict__ Xp, const float* __restrict__ Xl, PtrArr12 wp,
    float* __restrict__ outP, float* __restrict__ outL)
{
    int slice = blockIdx.y;
    const float* X; float* out; int N, outStride, col;
    if (slice < 8) { X = Xp; out = outP; N = NP; outStride = 8 * H; col = slice; }
    else           { X = Xl; out = outL; N = NL; outStride = 4 * H; col = slice - 8; }
    int m0 = blockIdx.x * 128;
    if (m0 >= N) return;

    extern __shared__ uint32_t sm[];
    uint32_t* As = sm;
    uint32_t* Bs = sm + SMEM_B_FLOAT;

    const float* W = wp.p[slice];
    int tid = threadIdx.x;
    int lane = tid & 31, warp = tid >> 5;
    int g = lane >> 2, t = lane & 3;

    #pragma unroll
    for (int it = 0; it < 16; ++it) {
        int idx = it * 256 + tid;
        int r = idx >> 5, c4 = (idx & 31) * 4;
        float4 av = make_float4(0.f, 0.f, 0.f, 0.f);
        if (m0 + r < N) av = *(const float4*)(X + (size_t)(m0 + r) * H + c4);
        uint32_t* ap = As + r * APITCH + c4;
        ap[0] = f2tf32(av.x); ap[1] = f2tf32(av.y);
        ap[2] = f2tf32(av.z); ap[3] = f2tf32(av.w);
        float4 bv = *(const float4*)(W + (size_t)r * H + c4);
        uint32_t* bp2 = Bs + r * APITCH + c4;
        bp2[0] = f2tf32(bv.x); bp2[1] = f2tf32(bv.y);
        bp2[2] = f2tf32(bv.z); bp2[3] = f2tf32(bv.w);
    }
    __syncthreads();

    int wm = warp >> 2;
    int wn = warp & 3;
    int mbase = wm * 64;
    int nbase = wn * 32;

    float d[4][4][4];
    #pragma unroll
    for (int i = 0; i < 4; ++i)
        #pragma unroll
        for (int j = 0; j < 4; ++j)
            #pragma unroll
            for (int q = 0; q < 4; ++q) d[i][j][q] = 0.f;

    #pragma unroll
    for (int ks = 0; ks < 16; ++ks) {
        int kb = ks * 8;
        uint32_t a[4][4];
        #pragma unroll
        for (int i = 0; i < 4; ++i) {
            int r0 = mbase + i * 16 + g;
            a[i][0] = As[r0 * APITCH + kb + t];
            a[i][1] = As[(r0 + 8) * APITCH + kb + t];
            a[i][2] = As[r0 * APITCH + kb + 4 + t];
            a[i][3] = As[(r0 + 8) * APITCH + kb + 4 + t];
        }
        uint32_t b[4][2];
        #pragma unroll
        for (int j = 0; j < 4; ++j) {
            int c0 = nbase + j * 8 + g;
            b[j][0] = Bs[(kb + t) * APITCH + c0];
            b[j][1] = Bs[(kb + 4 + t) * APITCH + c0];
        }
        #pragma unroll
        for (int i = 0; i < 4; ++i)
            #pragma unroll
            for (int j = 0; j < 4; ++j) {
                asm volatile(
                    "mma.sync.aligned.m16n8k8.row.col.f32.tf32.tf32.f32 "
                    "{%0,%1,%2,%3}, {%4,%5,%6,%7}, {%8,%9}, {%0,%1,%2,%3};"
                    : "+f"(d[i][j][0]), "+f"(d[i][j][1]), "+f"(d[i][j][2]), "+f"(d[i][j][3])
                    : "r"(a[i][0]), "r"(a[i][1]), "r"(a[i][2]), "r"(a[i][3]),
                      "r"(b[j][0]), "r"(b[j][1]));
            }
    }

    size_t colbase = (size_t)col * H;
    #pragma unroll
    for (int i = 0; i < 4; ++i) {
        int gr0 = m0 + mbase + i * 16 + g;
        int gr1 = gr0 + 8;
        #pragma unroll
        for (int j = 0; j < 4; ++j) {
            int gc = nbase + j * 8 + t * 2;
            if (gr0 < N)
                *(float2*)(out + (size_t)gr0 * outStride + colbase + gc) =
                    make_float2(d[i][j][0], d[i][j][1]);
            if (gr1 < N)
                *(float2*)(out + (size_t)gr1 * outStride + colbase + gc) =
                    make_float2(d[i][j][2], d[i][j][3]);
        }
    }
}

// ---------------- merged CSR edge kernel: 4-edge batched gathers ----------------
struct EdgeArgs {
    const int*   off[3];
    const int*   ssrc[3];
    const float* su[3];
    const float* T[3];
    const float* Pd[3]; int dstr[3];
    const float* Ps[3]; int sstr[3];
    const float* bfp[3];
    const float* bsp[3];
    float*       agg[3];
};

__device__ __forceinline__ void edge_math(
    float4 fsv, float4 ssv, float u, const float* __restrict__ T, int j0,
    float fd0, float fd1, float fd2, float fd3,
    float sd0, float sd1, float sd2, float sd3,
    float& a0, float& a1, float& a2, float& a3, bool valid)
{
    int b = min((int)u, NBIN - 1);
    float w = u - (float)b;
    const float* Tb = T + (size_t)b * 256 + j0;
    float4 flo = *(const float4*)(Tb);
    float4 fhi = *(const float4*)(Tb + 256);
    float4 slo = *(const float4*)(Tb + 128);
    float4 shi = *(const float4*)(Tb + 384);

    float f0 = fd0 + fsv.x + flo.x + w * (fhi.x - flo.x);
    float f1 = fd1 + fsv.y + flo.y + w * (fhi.y - flo.y);
    float f2 = fd2 + fsv.z + flo.z + w * (fhi.z - flo.z);
    float f3 = fd3 + fsv.w + flo.w + w * (fhi.w - flo.w);
    float s0 = sd0 + ssv.x + slo.x + w * (shi.x - slo.x);
    float s1 = sd1 + ssv.y + slo.y + w * (shi.y - slo.y);
    float s2 = sd2 + ssv.z + slo.z + w * (shi.z - slo.z);
    float s3 = sd3 + ssv.w + slo.w + w * (shi.w - slo.w);

    if (valid) {
        a0 += sig_tanh(f0) * softplus_f(s0);
        a1 += sig_tanh(f1) * softplus_f(s1);
        a2 += sig_tanh(f2) * softplus_f(s2);
        a3 += sig_tanh(f3) * softplus_f(s3);
    }
}

__global__ __launch_bounds__(256) void edge_all(EdgeArgs ea)
{
    int w = blockIdx.x * 8 + (threadIdx.x >> 5);
    int lane = threadIdx.x & 31;
    int j0 = lane * 4;

    int t, n;
    if (w < NP)               { t = 0; n = w; }
    else if (w < 2 * NP)      { t = 1; n = w - NP; }
    else if (w < 2 * NP + NL) { t = 2; n = w - 2 * NP; }
    else return;

    const int* off = ea.off[t];
    int p0 = off[n], p1 = off[n + 1];

    float4 bf4 = *(const float4*)(ea.bfp[t] + j0);
    float4 bs4 = *(const float4*)(ea.bsp[t] + j0);
    const float* pd = ea.Pd[t] + (size_t)n * ea.dstr[t] + j0;
    float4 fdv = *(const float4*)(pd);
    float4 sdv = *(const float4*)(pd + H);
    float fd0 = fdv.x + bf4.x, fd1 = fdv.y + bf4.y, fd2 = fdv.z + bf4.z, fd3 = fdv.w + bf4.w;
    float sd0 = sdv.x + bs4.x, sd1 = sdv.y + bs4.y, sd2 = sdv.z + bs4.z, sd3 = sdv.w + bs4.w;

    const float* Ps = ea.Ps[t];
    int sstr = ea.sstr[t];
    const int* ssrc = ea.ssrc[t];
    const float* su = ea.su[t];
    const float* T = ea.T[t];

    float a0 = 0.f, a1 = 0.f, a2 = 0.f, a3 = 0.f;

    for (int p = p0; p < p1; p += 4) {
        int pe = p1 - 1;
        int i1 = min(p + 1, pe), i2 = min(p + 2, pe), i3 = min(p + 3, pe);
        int sA = ssrc[p], sB = ssrc[i1], sC = ssrc[i2], sD = ssrc[i3];
        float uA = su[p], uB = su[i1], uC = su[i2], uD = su[i3];

        // issue all 8 gathers back-to-back (MLP=8)
        const float* qA = Ps + (size_t)sA * sstr + j0;
        const float* qB = Ps + (size_t)sB * sstr + j0;
        const float* qC = Ps + (size_t)sC * sstr + j0;
        const float* qD = Ps + (size_t)sD * sstr + j0;
        float4 fA = *(const float4*)(qA);
        float4 fB = *(const float4*)(qB);
        float4 fC = *(const float4*)(qC);
        float4 fD = *(const float4*)(qD);
        float4 sA4 = *(const float4*)(qA + H);
        float4 sB4 = *(const float4*)(qB + H);
        float4 sC4 = *(const float4*)(qC + H);
        float4 sD4 = *(const float4*)(qD + H);

        edge_math(fA, sA4, uA, T, j0, fd0, fd1, fd2, fd3, sd0, sd1, sd2, sd3,
                  a0, a1, a2, a3, true);
        edge_math(fB, sB4, uB, T, j0, fd0, fd1, fd2, fd3, sd0, sd1, sd2, sd3,
                  a0, a1, a2, a3, p + 1 < p1);
        edge_math(fC, sC4, uC, T, j0, fd0, fd1, fd2, fd3, sd0, sd1, sd2, sd3,
                  a0, a1, a2, a3, p + 2 < p1);
        edge_math(fD, sD4, uD, T, j0, fd0, fd1, fd2, fd3, sd0, sd1, sd2, sd3,
                  a0, a1, a2, a3, p + 3 < p1);
    }
    *(float4*)(ea.agg[t] + (size_t)n * H + j0) = make_float4(a0, a1, a2, a3);
}

// ---------------- merged node epilogue ----------------
__global__ __launch_bounds__(256) void node_update(
    const float* __restrict__ xp_in, const float* __restrict__ agg_pp,
    const float* __restrict__ agg_lp,
    const float* __restrict__ xl_in, const float* __restrict__ agg_pl,
    const float* __restrict__ bn_w, const float* __restrict__ bn_b,
    const float* __restrict__ ln_w, const float* __restrict__ ln_b, int l,
    float* __restrict__ xp_out, float* __restrict__ xl_out)
{
    int w = blockIdx.x * 8 + (threadIdx.x >> 5);
    int lane = threadIdx.x & 31;
    int j0 = lane * 4;
    const float bnf = rsqrtf(1.0f + 1e-5f);

    if (w < NP) {
        size_t off = (size_t)w * H + j0;
        float4 x = *(const float4*)(xp_in + off);

        size_t pb0 = (size_t)(l * 3 + 0) * H + j0;
        float4 bw = *(const float4*)(bn_w + pb0);
        float4 bb = *(const float4*)(bn_b + pb0);
        float4 lw = *(const float4*)(ln_w + pb0);
        float4 lb = *(const float4*)(ln_b + pb0);
        float4 g = *(const float4*)(agg_pp + off);
        float4 a;
        a.x = g.x * (bw.x * bnf) + bb.x + x.x;
        a.y = g.y * (bw.y * bnf) + bb.y + x.y;
        a.z = g.z * (bw.z * bnf) + bb.z + x.z;
        a.w = g.w * (bw.w * bnf) + bb.w + x.w;
        float4 y1 = cg_ln_relu(a, lw, lb);

        size_t pb1 = (size_t)(l * 3 + 1) * H + j0;
        bw = *(const float4*)(bn_w + pb1);
        bb = *(const float4*)(bn_b + pb1);
        lw = *(const float4*)(ln_w + pb1);
        lb = *(const float4*)(ln_b + pb1);
        g = *(const float4*)(agg_lp + off);
        a.x = g.x * (bw.x * bnf) + bb.x + x.x;
        a.y = g.y * (bw.y * bnf) + bb.y + x.y;
        a.z = g.z * (bw.z * bnf) + bb.z + x.z;
        a.w = g.w * (bw.w * bnf) + bb.w + x.w;
        float4 y2 = cg_ln_relu(a, lw, lb);

        float4 r;
        r.x = y1.x + y2.x + 2.f * x.x;
        r.y = y1.y + y2.y + 2.f * x.y;
        r.z = y1.z + y2.z + 2.f * x.z;
        r.w = y1.w + y2.w + 2.f * x.w;
        *(float4*)(xp_out + off) = r;
    } else if (w < NP + NL) {
        int i = w - NP;
        size_t off = (size_t)i * H + j0;
        float4 x = *(const float4*)(xl_in + off);
        size_t pb2 = (size_t)(l * 3 + 2) * H + j0;
        float4 bw = *(const float4*)(bn_w + pb2);
        float4 bb = *(const float4*)(bn_b + pb2);
        float4 lw = *(const float4*)(ln_w + pb2);
        float4 lb = *(const float4*)(ln_b + pb2);
        float4 g = *(const float4*)(agg_pl + off);
        float4 a;
        a.x = g.x * (bw.x * bnf) + bb.x + x.x;
        a.y = g.y * (bw.y * bnf) + bb.y + x.y;
        a.z = g.z * (bw.z * bnf) + bb.z + x.z;
        a.w = g.w * (bw.w * bnf) + bb.w + x.w;
        float4 y = cg_ln_relu(a, lw, lb);
        float4 r;
        r.x = y.x + x.x; r.y = y.y + x.y; r.z = y.z + x.z; r.w = y.w + x.w;
        *(float4*)(xl_out + off) = r;
    }
}

// ---------------- final: LN(xp) @ fc_w + fc_b ----------------
__global__ __launch_bounds__(128) void final_kernel(
    const float* __restrict__ xp,
    const float* __restrict__ lnw, const float* __restrict__ lnb,
    const float* __restrict__ fcw, const float* __restrict__ fcb,
    float* __restrict__ out)
{
    __shared__ float sh[8];
    __shared__ float yb[H];
    __shared__ float part[4][21];
    int i = blockIdx.x, j = threadIdx.x;
    float x = xp[(size_t)i * H + j];
    float s = x, q = x * x;
    block_reduce_2(s, q, sh);
    float mean = s * (1.0f / H);
    float var = q * (1.0f / H) - mean * mean;
    yb[j] = (x - mean) * rsqrtf(var + 1e-5f) * lnw[j] + lnb[j];
    __syncthreads();
    if (j < 84) {
        int c = j % 21, qq = j / 21;
        float acc = 0.f;
        #pragma unroll
        for (int t = 0; t < 32; ++t) acc += yb[qq * 32 + t] * fcw[(qq * 32 + t) * 21 + c];
        part[qq][c] = acc;
    }
    __syncthreads();
    if (j < 21)
        out[(size_t)i * 21 + j] = part[0][j] + part[1][j] + part[2][j] + part[3][j] + fcb[j];
}

// ---------------- host ----------------
extern "C" void kernel_launch(void* const* d_in, const int* in_sizes, int n_in,
                              void* d_out, int out_size)
{
    const float* x_protein = (const float*)d_in[0];
    const float* x_ligand  = (const float*)d_in[1];
    const int*   ei_pp     = (const int*)d_in[2];
    const float* ea_pp     = (const float*)d_in[3];
    const int*   ei_lp     = (const int*)d_in[4];
    const float* ea_lp     = (const float*)d_in[5];
    const int*   ei_pl     = (const int*)d_in[6];
    const float* ea_pl     = (const float*)d_in[7];
    const float* Wp        = (const float*)d_in[8];
    const float* bp        = (const float*)d_in[9];
    const float* Wl        = (const float*)d_in[10];
    const float* bl        = (const float*)d_in[11];
    const float* Wf        = (const float*)d_in[12];
    const float* bf        = (const float*)d_in[13];
    const float* Ws        = (const float*)d_in[14];
    const float* bs        = (const float*)d_in[15];
    const float* bn_w      = (const float*)d_in[16];
    const float* bn_b      = (const float*)d_in[17];
    const float* ln_w      = (const float*)d_in[18];
    const float* ln_b      = (const float*)d_in[19];
    const float* lno_w     = (const float*)d_in[20];
    const float* lno_b     = (const float*)d_in[21];
    const float* fc_w      = (const float*)d_in[22];
    const float* fc_b      = (const float*)d_in[23];
    float* out = (float*)d_out;

    float *xpA, *xpB, *xlA, *xlB, *Pp, *Pl, *agg_pp, *agg_lp, *agg_pl, *su, *Tb;
    int *cnt, *offs, *cur, *ssrc, *chs, *chb;
    cudaGetSymbolAddress((void**)&xpA, g_xpA);
    cudaGetSymbolAddress((void**)&xpB, g_xpB);
    cudaGetSymbolAddress((void**)&xlA, g_xlA);
    cudaGetSymbolAddress((void**)&xlB, g_xlB);
    cudaGetSymbolAddress((void**)&Pp, g_Pp);
    cudaGetSymbolAddress((void**)&Pl, g_Pl);
    cudaGetSymbolAddress((void**)&agg_pp, g_agg_pp);
    cudaGetSymbolAddress((void**)&agg_lp, g_agg_lp);
    cudaGetSymbolAddress((void**)&agg_pl, g_agg_pl);
    cudaGetSymbolAddress((void**)&Tb, g_T);
    cudaGetSymbolAddress((void**)&cnt, g_cnt);
    cudaGetSymbolAddress((void**)&offs, g_off);
    cudaGetSymbolAddress((void**)&cur, g_cur);
    cudaGetSymbolAddress((void**)&ssrc, g_ssrc);
    cudaGetSymbolAddress((void**)&su, g_su);
    cudaGetSymbolAddress((void**)&chs, g_chunksum);
    cudaGetSymbolAddress((void**)&chb, g_chunkbase);

    cudaFuncSetAttribute(proj_mma, cudaFuncAttributeMaxDynamicSharedMemorySize, SMEM_MMA_BYTES);

    auto wfp = [&](int l, int b, int r) { return Wf + ((size_t)(l * 3 + b) * 272 + r) * H; };
    auto wsp = [&](int l, int b, int r) { return Ws + ((size_t)(l * 3 + b) * 272 + r) * H; };
    auto mkw = [&](int l) {
        PtrArr12 w;
        w.p[0] = wfp(l, 0, 0);    w.p[1] = wsp(l, 0, 0);
        w.p[2] = wfp(l, 0, 128);  w.p[3] = wsp(l, 0, 128);
        w.p[4] = wfp(l, 1, 0);    w.p[5] = wsp(l, 1, 0);
        w.p[6] = wfp(l, 2, 128);  w.p[7] = wsp(l, 2, 128);
        w.p[8] = wfp(l, 1, 128);  w.p[9] = wsp(l, 1, 128);
        w.p[10] = wfp(l, 2, 0);   w.p[11] = wsp(l, 2, 0);
        return w;
    };

    // setup (ordered so the capture slot lands on proj_mma)
    embed_kernel<<<NP + NL, 128>>>(x_protein, Wp, bp, x_ligand, Wl, bl, xpA, xlA);
    lut_build<<<dim3(NBIN + 1, 12), 256>>>(Wf, Ws, Tb);
    cudaMemsetAsync(cnt, 0, NCNT * sizeof(int), 0);
    hist_all<<<(ETOT + 255) / 256, 256>>>(ei_pp, ei_lp, ei_pl, cnt);
    proj_mma<<<dim3((NP + 127) / 128, 12), 256, SMEM_MMA_BYTES>>>(xpA, xlA, mkw(0), Pp, Pl);
    scanA<<<CHT, 1024>>>(cnt, offs, chs);
    scanB<<<1, 32>>>(chs, chb, offs);
    scanC<<<CHT, 1024>>>(offs, chb, cur);
    scatter_all<<<(ETOT + 255) / 256, 256>>>(ei_pp, ea_pp, ei_lp, ea_lp, ei_pl, ea_pl,
                                             cur, ssrc, su);

    float* xp_cur = xpA; float* xp_nxt = xpB;
    float* xl_cur = xlA; float* xl_nxt = xlB;

    for (int l = 0; l < NLAYER; ++l) {
        if (l > 0)
            proj_mma<<<dim3((NP + 127) / 128, 12), 256, SMEM_MMA_BYTES>>>(xp_cur, xl_cur, mkw(l), Pp, Pl);

        EdgeArgs ea;
        // pp
        ea.off[0] = offs;              ea.ssrc[0] = ssrc;             ea.su[0] = su;
        ea.T[0] = Tb + (size_t)(l * 3 + 0) * (NBIN + 1) * 256;
        ea.Pd[0] = Pp + 0 * H; ea.dstr[0] = 8 * H;
        ea.Ps[0] = Pp + 2 * H; ea.sstr[0] = 8 * H;
        ea.bfp[0] = bf + (size_t)(l * 3 + 0) * H; ea.bsp[0] = bs + (size_t)(l * 3 + 0) * H;
        ea.agg[0] = agg_pp;
        // lp
        ea.off[1] = offs + NP + 1;     ea.ssrc[1] = ssrc + EPP;       ea.su[1] = su + EPP;
        ea.T[1] = Tb + (size_t)(l * 3 + 1) * (NBIN + 1) * 256;
        ea.Pd[1] = Pp + 4 * H; ea.dstr[1] = 8 * H;
        ea.Ps[1] = Pl + 0 * H; ea.sstr[1] = 4 * H;
        ea.bfp[1] = bf + (size_t)(l * 3 + 1) * H; ea.bsp[1] = bs + (size_t)(l * 3 + 1) * H;
        ea.agg[1] = agg_lp;
        // pl
        ea.off[2] = offs + 2 * NP + 2; ea.ssrc[2] = ssrc + EPP + ELP; ea.su[2] = su + EPP + ELP;
        ea.T[2] = Tb + (size_t)(l * 3 + 2) * (NBIN + 1) * 256;
        ea.Pd[2] = Pl + 2 * H; ea.dstr[2] = 4 * H;
        ea.Ps[2] = Pp + 6 * H; ea.sstr[2] = 8 * H;
        ea.bfp[2] = bf + (size_t)(l * 3 + 2) * H; ea.bsp[2] = bs + (size_t)(l * 3 + 2) * H;
        ea.agg[2] = agg_pl;

        edge_all<<<(2 * NP + NL + 7) / 8, 256>>>(ea);

        node_update<<<(NP + NL + 7) / 8, 256>>>(xp_cur, agg_pp, agg_lp,
                                                xl_cur, agg_pl,
                                                bn_w, bn_b, ln_w, ln_b, l,
                                                xp_nxt, xl_nxt);

        float* t;
        t = xp_cur; xp_cur = xp_nxt; xp_nxt = t;
        t = xl_cur; xl_cur = xl_nxt; xl_nxt = t;
    }

    final_kernel<<<NP, 128>>>(xp_cur, lno_w, lno_b, fc_w, fc_b, out);
}

// round 8
// speedup vs baseline: 3.6113x; 1.2946x over previous
#include <cuda_runtime.h>
#include <cstdint>
#include <cstddef>

#define NP 50000
#define NL 10000
#define H  128
#define D  16
#define NLAYER 4
#define EPP 500000
#define ELP 100000
#define EPL 100000
#define ETOT (EPP + ELP + EPL)
#define NCNT (2 * NP + NL)
#define NBIN 512
#define CH0 49
#define CH1 49
#define CH2 10
#define CHT (CH0 + CH1 + CH2)

// ---------------- scratch (device globals; no runtime allocation) ----------------
__device__ float g_xpA[NP * H];
__device__ float g_xpB[NP * H];
__device__ float g_xlA[NL * H];
__device__ float g_xlB[NL * H];
__device__ float g_Pp[(size_t)NP * 8 * H];
__device__ float g_Pl[(size_t)NL * 4 * H];
__device__ float g_agg_pp[NP * H];
__device__ float g_agg_lp[NP * H];
__device__ float g_agg_pl[NL * H];
__device__ float g_T[(size_t)12 * (NBIN + 1) * 256];
__device__ int   g_cnt[NCNT];
__device__ int   g_off[NCNT + 3];
__device__ int   g_cur[NCNT];
__device__ int   g_ssrc[ETOT];
__device__ float g_su[ETOT];
__device__ int   g_chunksum[CHT];
__device__ int   g_chunkbase[CHT];

// ---------------- small helpers ----------------
__device__ __forceinline__ uint32_t smem_u32(const void* p) {
    uint32_t a;
    asm("{ .reg .u64 t; cvta.to.shared.u64 t, %1; cvt.u32.u64 %0, t; }" : "=r"(a) : "l"(p));
    return a;
}
__device__ __forceinline__ void block_reduce_2(float& s, float& q, float* shbuf)
{
    unsigned m = 0xffffffffu;
    #pragma unroll
    for (int o = 16; o > 0; o >>= 1) {
        s += __shfl_down_sync(m, s, o);
        q += __shfl_down_sync(m, q, o);
    }
    int lane = threadIdx.x & 31, wid = threadIdx.x >> 5;
    if (lane == 0) { shbuf[wid] = s; shbuf[4 + wid] = q; }
    __syncthreads();
    s = shbuf[0] + shbuf[1] + shbuf[2] + shbuf[3];
    q = shbuf[4] + shbuf[5] + shbuf[6] + shbuf[7];
    __syncthreads();
}
__device__ __forceinline__ float sig_tanh(float x) {
    float t;
    asm("tanh.approx.f32 %0, %1;" : "=f"(t) : "f"(x * 0.5f));
    return 0.5f * t + 0.5f;
}
__device__ __forceinline__ float softplus_f(float x) {
    return fmaxf(x, 0.f) + __logf(1.0f + __expf(-fabsf(x)));
}
__device__ __forceinline__ float4 cg_ln_relu(float4 a, float4 lw, float4 lb)
{
    float s = a.x + a.y + a.z + a.w;
    float q = a.x * a.x + a.y * a.y + a.z * a.z + a.w * a.w;
    #pragma unroll
    for (int o = 16; o > 0; o >>= 1) {
        s += __shfl_xor_sync(0xffffffffu, s, o);
        q += __shfl_xor_sync(0xffffffffu, q, o);
    }
    float mean = s * (1.0f / H);
    float var = q * (1.0f / H) - mean * mean;
    float r = rsqrtf(var + 1e-5f);
    float4 y;
    y.x = fmaxf((a.x - mean) * r * lw.x + lb.x, 0.f);
    y.y = fmaxf((a.y - mean) * r * lw.y + lb.y, 0.f);
    y.z = fmaxf((a.z - mean) * r * lw.z + lb.z, 0.f);
    y.w = fmaxf((a.w - mean) * r * lw.w + lb.w, 0.f);
    return y;
}

// ---------------- CSR build ----------------
__global__ void hist_all(const int* __restrict__ ei_pp, const int* __restrict__ ei_lp,
                         const int* __restrict__ ei_pl, int* __restrict__ cnt)
{
    int idx = blockIdx.x * blockDim.x + threadIdx.x;
    if (idx >= ETOT) return;
    if (idx < EPP) {
        atomicAdd(&cnt[ei_pp[EPP + idx]], 1);
    } else if (idx < EPP + ELP) {
        int e = idx - EPP;
        atomicAdd(&cnt[NP + ei_lp[ELP + e]], 1);
    } else {
        int e = idx - EPP - ELP;
        atomicAdd(&cnt[2 * NP + ei_pl[EPL + e]], 1);
    }
}

__global__ __launch_bounds__(1024) void scanA(const int* __restrict__ cnt,
                                              int* __restrict__ off,
                                              int* __restrict__ chunksum)
{
    __shared__ int s[1024];
    int bid = blockIdx.x;
    const int* cbase; int* obase; int N; int c;
    if (bid < CH0)            { cbase = cnt;          obase = off;              N = NP; c = bid; }
    else if (bid < CH0 + CH1) { cbase = cnt + NP;     obase = off + NP + 1;     N = NP; c = bid - CH0; }
    else                      { cbase = cnt + 2 * NP; obase = off + 2 * NP + 2; N = NL; c = bid - CH0 - CH1; }
    int tid = threadIdx.x;
    int i = c * 1024 + tid;
    int v = (i < N) ? cbase[i] : 0;
    s[tid] = v;
    __syncthreads();
    #pragma unroll
    for (int o = 1; o < 1024; o <<= 1) {
        int t = (tid >= o) ? s[tid - o] : 0;
        __syncthreads();
        s[tid] += t;
        __syncthreads();
    }
    if (i < N) obase[i] = s[tid] - v;
    if (tid == 1023) chunksum[bid] = s[1023];
}

__global__ void scanB(const int* __restrict__ chunksum, int* __restrict__ chunkbase,
                      int* __restrict__ off)
{
    int t = threadIdx.x;
    if (t == 0) {
        int b = 0;
        for (int c = 0; c < CH0; ++c) { chunkbase[c] = b; b += chunksum[c]; }
        off[NP] = b;
    } else if (t == 1) {
        int b = 0;
        for (int c = 0; c < CH1; ++c) { chunkbase[CH0 + c] = b; b += chunksum[CH0 + c]; }
        off[NP + 1 + NP] = b;
    } else if (t == 2) {
        int b = 0;
        for (int c = 0; c < CH2; ++c) { chunkbase[CH0 + CH1 + c] = b; b += chunksum[CH0 + CH1 + c]; }
        off[2 * NP + 2 + NL] = b;
    }
}

__global__ __launch_bounds__(1024) void scanC(int* __restrict__ off,
                                              const int* __restrict__ chunkbase,
                                              int* __restrict__ cur)
{
    int bid = blockIdx.x;
    int* obase; int* curb; int N; int c;
    if (bid < CH0)            { obase = off;              curb = cur;          N = NP; c = bid; }
    else if (bid < CH0 + CH1) { obase = off + NP + 1;     curb = cur + NP;     N = NP; c = bid - CH0; }
    else                      { obase = off + 2 * NP + 2; curb = cur + 2 * NP; N = NL; c = bid - CH0 - CH1; }
    int i = c * 1024 + threadIdx.x;
    if (i < N) {
        int v = obase[i] + chunkbase[bid];
        obase[i] = v;
        curb[i] = v;
    }
}

__global__ void scatter_all(const int* __restrict__ ei_pp, const float* __restrict__ ea_pp,
                            const int* __restrict__ ei_lp, const float* __restrict__ ea_lp,
                            const int* __restrict__ ei_pl, const float* __restrict__ ea_pl,
                            int* __restrict__ cur, int* __restrict__ ssrc,
                            float* __restrict__ su)
{
    const float usc = (float)NBIN / 8.0f;
    int idx = blockIdx.x * blockDim.x + threadIdx.x;
    if (idx >= ETOT) return;
    if (idx < EPP) {
        int e = idx;
        int d = ei_pp[EPP + e];
        int p = atomicAdd(&cur[d], 1);
        ssrc[p] = ei_pp[e];
        su[p] = ea_pp[e] * usc;
    } else if (idx < EPP + ELP) {
        int e = idx - EPP;
        int d = ei_lp[ELP + e];
        int p = EPP + atomicAdd(&cur[NP + d], 1);
        ssrc[p] = ei_lp[e];
        su[p] = ea_lp[e] * usc;
    } else {
        int e = idx - EPP - ELP;
        int d = ei_pl[EPL + e];
        int p = EPP + ELP + atomicAdd(&cur[2 * NP + d], 1);
        ssrc[p] = ei_pl[e];
        su[p] = ea_pl[e] * usc;
    }
}

// ---------------- LUT build ----------------
__global__ __launch_bounds__(256) void lut_build(
    const float* __restrict__ Wf, const float* __restrict__ Ws, float* __restrict__ T)
{
    int b = blockIdx.x;
    int lt = blockIdx.y;
    int j = threadIdx.x;
    float d = (float)b * (8.0f / (float)NBIN);
    const float step = 8.0f / 15.0f;
    const float coeff = -0.5f / (step * step);
    float r[16];
    #pragma unroll
    for (int k = 0; k < 16; ++k) {
        float dlt = d - (float)k * step;
        r[k] = __expf(coeff * dlt * dlt);
    }
    const float* W = (j < 128 ? Wf : Ws) + ((size_t)lt * 272 + 256) * H + (j & 127);
    float acc = 0.f;
    #pragma unroll
    for (int k = 0; k < 16; ++k) acc += r[k] * W[(size_t)k * H];
    T[((size_t)lt * (NBIN + 1) + b) * 256 + j] = acc;
}

// ---------------- merged initial embedding ----------------
__global__ __launch_bounds__(128) void embed_kernel(
    const float* __restrict__ xp, const float* __restrict__ Wp, const float* __restrict__ bp,
    const float* __restrict__ xl, const float* __restrict__ Wl, const float* __restrict__ bl,
    float* __restrict__ outp, float* __restrict__ outl)
{
    int i = blockIdx.x;
    int j = threadIdx.x;
    const float *x, *W, *b; float* o; int r;
    if (i < NP) { x = xp; W = Wp; b = bp; o = outp; r = i; }
    else        { x = xl; W = Wl; b = bl; o = outl; r = i - NP; }
    const float* xr = x + (size_t)r * 6;
    float acc = b[j];
    #pragma unroll
    for (int k = 0; k < 6; ++k) acc += xr[k] * W[k * H + j];
    o[(size_t)r * H + j] = acc;
}

// ---------------- pipelined tf32 mma.sync projection GEMM (cp.async, BK=32) ------
struct PtrArr12 { const float* p[12]; };

#define APA 36
#define APB 136
#define AST (128 * APA)       /* 4608 floats */
#define BST (32 * APB)        /* 4352 floats */
#define STG (AST + BST)       /* 8960 floats */
#define SMEM_MMA_BYTES (2 * STG * 4)   /* 71680 B */

__global__ __launch_bounds__(256, 2) void proj_mma(
    const float* __restrict__ Xp, const float* __restrict__ Xl, PtrArr12 wp,
    float* __restrict__ outP, float* __restrict__ outL)
{
    int slice = blockIdx.y;
    const float* X; float* out; int N, outStride, col;
    if (slice < 8) { X = Xp; out = outP; N = NP; outStride = 8 * H; col = slice; }
    else           { X = Xl; out = outL; N = NL; outStride = 4 * H; col = slice - 8; }
    int m0 = blockIdx.x * 128;
    if (m0 >= N) return;

    extern __shared__ float sm[];
    uint32_t smb = smem_u32(sm);
    const float* W = wp.p[slice];
    int tid = threadIdx.x;
    int lane = tid & 31, warp = tid >> 5;
    int g = lane >> 2, t = lane & 3;

    // cp.async stage loader: A chunk [128 x 32] + B chunk [32 x 128]
    auto load_stage = [&](int chunk, int s) {
        int kb = chunk * 32;
        uint32_t abase = smb + (uint32_t)(s * STG) * 4u;
        uint32_t bbase = abase + (uint32_t)AST * 4u;
        #pragma unroll
        for (int i = 0; i < 4; ++i) {
            int idx = tid + i * 256;
            int r = idx >> 3, c4 = (idx & 7) * 4;
            uint32_t dst = abase + (uint32_t)(r * APA + c4) * 4u;
            const float* src = X + (size_t)(m0 + r) * H + kb + c4;
            int sz = (m0 + r < N) ? 16 : 0;
            asm volatile("cp.async.cg.shared.global [%0], [%1], 16, %2;"
                         :: "r"(dst), "l"(src), "r"(sz));
        }
        #pragma unroll
        for (int i = 0; i < 4; ++i) {
            int idx = tid + i * 256;
            int k = idx >> 5, n4 = (idx & 31) * 4;
            uint32_t dst = bbase + (uint32_t)(k * APB + n4) * 4u;
            const float* src = W + (size_t)(kb + k) * H + n4;
            asm volatile("cp.async.cg.shared.global [%0], [%1], 16;"
                         :: "r"(dst), "l"(src));
        }
        asm volatile("cp.async.commit_group;" ::: "memory");
    };

    load_stage(0, 0);
    load_stage(1, 1);

    int wm = warp >> 2;
    int wn = warp & 3;
    int mbase = wm * 64;
    int nbase = wn * 32;

    float d[4][4][4];
    #pragma unroll
    for (int i = 0; i < 4; ++i)
        #pragma unroll
        for (int j = 0; j < 4; ++j)
            #pragma unroll
            for (int q = 0; q < 4; ++q) d[i][j][q] = 0.f;

    #pragma unroll
    for (int c = 0; c < 4; ++c) {
        if (c < 3) asm volatile("cp.async.wait_group 1;" ::: "memory");
        else       asm volatile("cp.async.wait_group 0;" ::: "memory");
        __syncthreads();

        const float* Asp = sm + (c & 1) * STG;
        const float* Bsp = Asp + AST;

        #pragma unroll
        for (int ks = 0; ks < 4; ++ks) {
            int kbl = ks * 8;
            uint32_t a[4][4];
            #pragma unroll
            for (int i = 0; i < 4; ++i) {
                int r0 = mbase + i * 16 + g;
                a[i][0] = *(const uint32_t*)&Asp[r0 * APA + kbl + t];
                a[i][1] = *(const uint32_t*)&Asp[(r0 + 8) * APA + kbl + t];
                a[i][2] = *(const uint32_t*)&Asp[r0 * APA + kbl + 4 + t];
                a[i][3] = *(const uint32_t*)&Asp[(r0 + 8) * APA + kbl + 4 + t];
            }
            uint32_t b[4][2];
            #pragma unroll
            for (int j = 0; j < 4; ++j) {
                int c0 = nbase + j * 8 + g;
                b[j][0] = *(const uint32_t*)&Bsp[(kbl + t) * APB + c0];
                b[j][1] = *(const uint32_t*)&Bsp[(kbl + 4 + t) * APB + c0];
            }
            #pragma unroll
            for (int i = 0; i < 4; ++i)
                #pragma unroll
                for (int j = 0; j < 4; ++j) {
                    asm volatile(
                        "mma.sync.aligned.m16n8k8.row.col.f32.tf32.tf32.f32 "
                        "{%0,%1,%2,%3}, {%4,%5,%6,%7}, {%8,%9}, {%0,%1,%2,%3};"
                        : "+f"(d[i][j][0]), "+f"(d[i][j][1]), "+f"(d[i][j][2]), "+f"(d[i][j][3])
                        : "r"(a[i][0]), "r"(a[i][1]), "r"(a[i][2]), "r"(a[i][3]),
                          "r"(b[j][0]), "r"(b[j][1]));
                }
        }
        __syncthreads();
        if (c + 2 < 4) load_stage(c + 2, c & 1);
    }

    size_t colbase = (size_t)col * H;
    #pragma unroll
    for (int i = 0; i < 4; ++i) {
        int gr0 = m0 + mbase + i * 16 + g;
        int gr1 = gr0 + 8;
        #pragma unroll
        for (int j = 0; j < 4; ++j) {
            int gc = nbase + j * 8 + t * 2;
            if (gr0 < N)
                *(float2*)(out + (size_t)gr0 * outStride + colbase + gc) =
                    make_float2(d[i][j][0], d[i][j][1]);
            if (gr1 < N)
                *(float2*)(out + (size_t)gr1 * outStride + colbase + gc) =
                    make_float2(d[i][j][2], d[i][j][3]);
        }
    }
}

// ---------------- merged CSR edge kernel: 4-edge batched gathers ----------------
struct EdgeArgs {
    const int*   off[3];
    const int*   ssrc[3];
    const float* su[3];
    const float* T[3];
    const float* Pd[3]; int dstr[3];
    const float* Ps[3]; int sstr[3];
    const float* bfp[3];
    const float* bsp[3];
    float*       agg[3];
};

__device__ __forceinline__ void edge_math(
    float4 fsv, float4 ssv, float u, const float* __restrict__ T, int j0,
    float fd0, float fd1, float fd2, float fd3,
    float sd0, float sd1, float sd2, float sd3,
    float& a0, float& a1, float& a2, float& a3, bool valid)
{
    int b = min((int)u, NBIN - 1);
    float w = u - (float)b;
    const float* Tb = T + (size_t)b * 256 + j0;
    float4 flo = *(const float4*)(Tb);
    float4 fhi = *(const float4*)(Tb + 256);
    float4 slo = *(const float4*)(Tb + 128);
    float4 shi = *(const float4*)(Tb + 384);

    float f0 = fd0 + fsv.x + flo.x + w * (fhi.x - flo.x);
    float f1 = fd1 + fsv.y + flo.y + w * (fhi.y - flo.y);
    float f2 = fd2 + fsv.z + flo.z + w * (fhi.z - flo.z);
    float f3 = fd3 + fsv.w + flo.w + w * (fhi.w - flo.w);
    float s0 = sd0 + ssv.x + slo.x + w * (shi.x - slo.x);
    float s1 = sd1 + ssv.y + slo.y + w * (shi.y - slo.y);
    float s2 = sd2 + ssv.z + slo.z + w * (shi.z - slo.z);
    float s3 = sd3 + ssv.w + slo.w + w * (shi.w - slo.w);

    if (valid) {
        a0 += sig_tanh(f0) * softplus_f(s0);
        a1 += sig_tanh(f1) * softplus_f(s1);
        a2 += sig_tanh(f2) * softplus_f(s2);
        a3 += sig_tanh(f3) * softplus_f(s3);
    }
}

__global__ __launch_bounds__(256) void edge_all(EdgeArgs ea)
{
    int w = blockIdx.x * 8 + (threadIdx.x >> 5);
    int lane = threadIdx.x & 31;
    int j0 = lane * 4;

    int t, n;
    if (w < NP)               { t = 0; n = w; }
    else if (w < 2 * NP)      { t = 1; n = w - NP; }
    else if (w < 2 * NP + NL) { t = 2; n = w - 2 * NP; }
    else return;

    const int* off = ea.off[t];
    int p0 = off[n], p1 = off[n + 1];

    float4 bf4 = *(const float4*)(ea.bfp[t] + j0);
    float4 bs4 = *(const float4*)(ea.bsp[t] + j0);
    const float* pd = ea.Pd[t] + (size_t)n * ea.dstr[t] + j0;
    float4 fdv = *(const float4*)(pd);
    float4 sdv = *(const float4*)(pd + H);
    float fd0 = fdv.x + bf4.x, fd1 = fdv.y + bf4.y, fd2 = fdv.z + bf4.z, fd3 = fdv.w + bf4.w;
    float sd0 = sdv.x + bs4.x, sd1 = sdv.y + bs4.y, sd2 = sdv.z + bs4.z, sd3 = sdv.w + bs4.w;

    const float* Ps = ea.Ps[t];
    int sstr = ea.sstr[t];
    const int* ssrc = ea.ssrc[t];
    const float* su = ea.su[t];
    const float* T = ea.T[t];

    float a0 = 0.f, a1 = 0.f, a2 = 0.f, a3 = 0.f;

    for (int p = p0; p < p1; p += 4) {
        int pe = p1 - 1;
        int i1 = min(p + 1, pe), i2 = min(p + 2, pe), i3 = min(p + 3, pe);
        int sA = ssrc[p], sB = ssrc[i1], sC = ssrc[i2], sD = ssrc[i3];
        float uA = su[p], uB = su[i1], uC = su[i2], uD = su[i3];

        const float* qA = Ps + (size_t)sA * sstr + j0;
        const float* qB = Ps + (size_t)sB * sstr + j0;
        const float* qC = Ps + (size_t)sC * sstr + j0;
        const float* qD = Ps + (size_t)sD * sstr + j0;
        float4 fA = *(const float4*)(qA);
        float4 fB = *(const float4*)(qB);
        float4 fC = *(const float4*)(qC);
        float4 fD = *(const float4*)(qD);
        float4 sA4 = *(const float4*)(qA + H);
        float4 sB4 = *(const float4*)(qB + H);
        float4 sC4 = *(const float4*)(qC + H);
        float4 sD4 = *(const float4*)(qD + H);

        edge_math(fA, sA4, uA, T, j0, fd0, fd1, fd2, fd3, sd0, sd1, sd2, sd3,
                  a0, a1, a2, a3, true);
        edge_math(fB, sB4, uB, T, j0, fd0, fd1, fd2, fd3, sd0, sd1, sd2, sd3,
                  a0, a1, a2, a3, p + 1 < p1);
        edge_math(fC, sC4, uC, T, j0, fd0, fd1, fd2, fd3, sd0, sd1, sd2, sd3,
                  a0, a1, a2, a3, p + 2 < p1);
        edge_math(fD, sD4, uD, T, j0, fd0, fd1, fd2, fd3, sd0, sd1, sd2, sd3,
                  a0, a1, a2, a3, p + 3 < p1);
    }
    *(float4*)(ea.agg[t] + (size_t)n * H + j0) = make_float4(a0, a1, a2, a3);
}

// ---------------- merged node epilogue ----------------
__global__ __launch_bounds__(256) void node_update(
    const float* __restrict__ xp_in, const float* __restrict__ agg_pp,
    const float* __restrict__ agg_lp,
    const float* __restrict__ xl_in, const float* __restrict__ agg_pl,
    const float* __restrict__ bn_w, const float* __restrict__ bn_b,
    const float* __restrict__ ln_w, const float* __restrict__ ln_b, int l,
    float* __restrict__ xp_out, float* __restrict__ xl_out)
{
    int w = blockIdx.x * 8 + (threadIdx.x >> 5);
    int lane = threadIdx.x & 31;
    int j0 = lane * 4;
    const float bnf = rsqrtf(1.0f + 1e-5f);

    if (w < NP) {
        size_t off = (size_t)w * H + j0;
        float4 x = *(const float4*)(xp_in + off);

        size_t pb0 = (size_t)(l * 3 + 0) * H + j0;
        float4 bw = *(const float4*)(bn_w + pb0);
        float4 bb = *(const float4*)(bn_b + pb0);
        float4 lw = *(const float4*)(ln_w + pb0);
        float4 lb = *(const float4*)(ln_b + pb0);
        float4 g = *(const float4*)(agg_pp + off);
        float4 a;
        a.x = g.x * (bw.x * bnf) + bb.x + x.x;
        a.y = g.y * (bw.y * bnf) + bb.y + x.y;
        a.z = g.z * (bw.z * bnf) + bb.z + x.z;
        a.w = g.w * (bw.w * bnf) + bb.w + x.w;
        float4 y1 = cg_ln_relu(a, lw, lb);

        size_t pb1 = (size_t)(l * 3 + 1) * H + j0;
        bw = *(const float4*)(bn_w + pb1);
        bb = *(const float4*)(bn_b + pb1);
        lw = *(const float4*)(ln_w + pb1);
        lb = *(const float4*)(ln_b + pb1);
        g = *(const float4*)(agg_lp + off);
        a.x = g.x * (bw.x * bnf) + bb.x + x.x;
        a.y = g.y * (bw.y * bnf) + bb.y + x.y;
        a.z = g.z * (bw.z * bnf) + bb.z + x.z;
        a.w = g.w * (bw.w * bnf) + bb.w + x.w;
        float4 y2 = cg_ln_relu(a, lw, lb);

        float4 r;
        r.x = y1.x + y2.x + 2.f * x.x;
        r.y = y1.y + y2.y + 2.f * x.y;
        r.z = y1.z + y2.z + 2.f * x.z;
        r.w = y1.w + y2.w + 2.f * x.w;
        *(float4*)(xp_out + off) = r;
    } else if (w < NP + NL) {
        int i = w - NP;
        size_t off = (size_t)i * H + j0;
        float4 x = *(const float4*)(xl_in + off);
        size_t pb2 = (size_t)(l * 3 + 2) * H + j0;
        float4 bw = *(const float4*)(bn_w + pb2);
        float4 bb = *(const float4*)(bn_b + pb2);
        float4 lw = *(const float4*)(ln_w + pb2);
        float4 lb = *(const float4*)(ln_b + pb2);
        float4 g = *(const float4*)(agg_pl + off);
        float4 a;
        a.x = g.x * (bw.x * bnf) + bb.x + x.x;
        a.y = g.y * (bw.y * bnf) + bb.y + x.y;
        a.z = g.z * (bw.z * bnf) + bb.z + x.z;
        a.w = g.w * (bw.w * bnf) + bb.w + x.w;
        float4 y = cg_ln_relu(a, lw, lb);
        float4 r;
        r.x = y.x + x.x; r.y = y.y + x.y; r.z = y.z + x.z; r.w = y.w + x.w;
        *(float4*)(xl_out + off) = r;
    }
}

// ---------------- final: LN(xp) @ fc_w + fc_b ----------------
__global__ __launch_bounds__(128) void final_kernel(
    const float* __restrict__ xp,
    const float* __restrict__ lnw, const float* __restrict__ lnb,
    const float* __restrict__ fcw, const float* __restrict__ fcb,
    float* __restrict__ out)
{
    __shared__ float sh[8];
    __shared__ float yb[H];
    __shared__ float part[4][21];
    int i = blockIdx.x, j = threadIdx.x;
    float x = xp[(size_t)i * H + j];
    float s = x, q = x * x;
    block_reduce_2(s, q, sh);
    float mean = s * (1.0f / H);
    float var = q * (1.0f / H) - mean * mean;
    yb[j] = (x - mean) * rsqrtf(var + 1e-5f) * lnw[j] + lnb[j];
    __syncthreads();
    if (j < 84) {
        int c = j % 21, qq = j / 21;
        float acc = 0.f;
        #pragma unroll
        for (int t = 0; t < 32; ++t) acc += yb[qq * 32 + t] * fcw[(qq * 32 + t) * 21 + c];
        part[qq][c] = acc;
    }
    __syncthreads();
    if (j < 21)
        out[(size_t)i * 21 + j] = part[0][j] + part[1][j] + part[2][j] + part[3][j] + fcb[j];
}

// ---------------- host ----------------
extern "C" void kernel_launch(void* const* d_in, const int* in_sizes, int n_in,
                              void* d_out, int out_size)
{
    const float* x_protein = (const float*)d_in[0];
    const float* x_ligand  = (const float*)d_in[1];
    const int*   ei_pp     = (const int*)d_in[2];
    const float* ea_pp     = (const float*)d_in[3];
    const int*   ei_lp     = (const int*)d_in[4];
    const float* ea_lp     = (const float*)d_in[5];
    const int*   ei_pl     = (const int*)d_in[6];
    const float* ea_pl     = (const float*)d_in[7];
    const float* Wp        = (const float*)d_in[8];
    const float* bp        = (const float*)d_in[9];
    const float* Wl        = (const float*)d_in[10];
    const float* bl        = (const float*)d_in[11];
    const float* Wf        = (const float*)d_in[12];
    const float* bf        = (const float*)d_in[13];
    const float* Ws        = (const float*)d_in[14];
    const float* bs        = (const float*)d_in[15];
    const float* bn_w      = (const float*)d_in[16];
    const float* bn_b      = (const float*)d_in[17];
    const float* ln_w      = (const float*)d_in[18];
    const float* ln_b      = (const float*)d_in[19];
    const float* lno_w     = (const float*)d_in[20];
    const float* lno_b     = (const float*)d_in[21];
    const float* fc_w      = (const float*)d_in[22];
    const float* fc_b      = (const float*)d_in[23];
    float* out = (float*)d_out;

    float *xpA, *xpB, *xlA, *xlB, *Pp, *Pl, *agg_pp, *agg_lp, *agg_pl, *su, *Tb;
    int *cnt, *offs, *cur, *ssrc, *chs, *chb;
    cudaGetSymbolAddress((void**)&xpA, g_xpA);
    cudaGetSymbolAddress((void**)&xpB, g_xpB);
    cudaGetSymbolAddress((void**)&xlA, g_xlA);
    cudaGetSymbolAddress((void**)&xlB, g_xlB);
    cudaGetSymbolAddress((void**)&Pp, g_Pp);
    cudaGetSymbolAddress((void**)&Pl, g_Pl);
    cudaGetSymbolAddress((void**)&agg_pp, g_agg_pp);
    cudaGetSymbolAddress((void**)&agg_lp, g_agg_lp);
    cudaGetSymbolAddress((void**)&agg_pl, g_agg_pl);
    cudaGetSymbolAddress((void**)&Tb, g_T);
    cudaGetSymbolAddress((void**)&cnt, g_cnt);
    cudaGetSymbolAddress((void**)&offs, g_off);
    cudaGetSymbolAddress((void**)&cur, g_cur);
    cudaGetSymbolAddress((void**)&ssrc, g_ssrc);
    cudaGetSymbolAddress((void**)&su, g_su);
    cudaGetSymbolAddress((void**)&chs, g_chunksum);
    cudaGetSymbolAddress((void**)&chb, g_chunkbase);

    cudaFuncSetAttribute(proj_mma, cudaFuncAttributeMaxDynamicSharedMemorySize, SMEM_MMA_BYTES);

    auto wfp = [&](int l, int b, int r) { return Wf + ((size_t)(l * 3 + b) * 272 + r) * H; };
    auto wsp = [&](int l, int b, int r) { return Ws + ((size_t)(l * 3 + b) * 272 + r) * H; };
    auto mkw = [&](int l) {
        PtrArr12 w;
        w.p[0] = wfp(l, 0, 0);    w.p[1] = wsp(l, 0, 0);
        w.p[2] = wfp(l, 0, 128);  w.p[3] = wsp(l, 0, 128);
        w.p[4] = wfp(l, 1, 0);    w.p[5] = wsp(l, 1, 0);
        w.p[6] = wfp(l, 2, 128);  w.p[7] = wsp(l, 2, 128);
        w.p[8] = wfp(l, 1, 128);  w.p[9] = wsp(l, 1, 128);
        w.p[10] = wfp(l, 2, 0);   w.p[11] = wsp(l, 2, 0);
        return w;
    };

    embed_kernel<<<NP + NL, 128>>>(x_protein, Wp, bp, x_ligand, Wl, bl, xpA, xlA);
    lut_build<<<dim3(NBIN + 1, 12), 256>>>(Wf, Ws, Tb);
    cudaMemsetAsync(cnt, 0, NCNT * sizeof(int), 0);
    hist_all<<<(ETOT + 255) / 256, 256>>>(ei_pp, ei_lp, ei_pl, cnt);
    proj_mma<<<dim3((NP + 127) / 128, 12), 256, SMEM_MMA_BYTES>>>(xpA, xlA, mkw(0), Pp, Pl);
    scanA<<<CHT, 1024>>>(cnt, offs, chs);
    scanB<<<1, 32>>>(chs, chb, offs);
    scanC<<<CHT, 1024>>>(offs, chb, cur);
    scatter_all<<<(ETOT + 255) / 256, 256>>>(ei_pp, ea_pp, ei_lp, ea_lp, ei_pl, ea_pl,
                                             cur, ssrc, su);

    float* xp_cur = xpA; float* xp_nxt = xpB;
    float* xl_cur = xlA; float* xl_nxt = xlB;

    for (int l = 0; l < NLAYER; ++l) {
        if (l > 0)
            proj_mma<<<dim3((NP + 127) / 128, 12), 256, SMEM_MMA_BYTES>>>(xp_cur, xl_cur, mkw(l), Pp, Pl);

        EdgeArgs ea;
        ea.off[0] = offs;              ea.ssrc[0] = ssrc;             ea.su[0] = su;
        ea.T[0] = Tb + (size_t)(l * 3 + 0) * (NBIN + 1) * 256;
        ea.Pd[0] = Pp + 0 * H; ea.dstr[0] = 8 * H;
        ea.Ps[0] = Pp + 2 * H; ea.sstr[0] = 8 * H;
        ea.bfp[0] = bf + (size_t)(l * 3 + 0) * H; ea.bsp[0] = bs + (size_t)(l * 3 + 0) * H;
        ea.agg[0] = agg_pp;
        ea.off[1] = offs + NP + 1;     ea.ssrc[1] = ssrc + EPP;       ea.su[1] = su + EPP;
        ea.T[1] = Tb + (size_t)(l * 3 + 1) * (NBIN + 1) * 256;
        ea.Pd[1] = Pp + 4 * H; ea.dstr[1] = 8 * H;
        ea.Ps[1] = Pl + 0 * H; ea.sstr[1] = 4 * H;
        ea.bfp[1] = bf + (size_t)(l * 3 + 1) * H; ea.bsp[1] = bs + (size_t)(l * 3 + 1) * H;
        ea.agg[1] = agg_lp;
        ea.off[2] = offs + 2 * NP + 2; ea.ssrc[2] = ssrc + EPP + ELP; ea.su[2] = su + EPP + ELP;
        ea.T[2] = Tb + (size_t)(l * 3 + 2) * (NBIN + 1) * 256;
        ea.Pd[2] = Pl + 2 * H; ea.dstr[2] = 4 * H;
        ea.Ps[2] = Pp + 6 * H; ea.sstr[2] = 8 * H;
        ea.bfp[2] = bf + (size_t)(l * 3 + 2) * H; ea.bsp[2] = bs + (size_t)(l * 3 + 2) * H;
        ea.agg[2] = agg_pl;

        edge_all<<<(2 * NP + NL + 7) / 8, 256>>>(ea);

        node_update<<<(NP + NL + 7) / 8, 256>>>(xp_cur, agg_pp, agg_lp,
                                                xl_cur, agg_pl,
                                                bn_w, bn_b, ln_w, ln_b, l,
                                                xp_nxt, xl_nxt);

        float* t;
        t = xp_cur; xp_cur = xp_nxt; xp_nxt = t;
        t = xl_cur; xl_cur = xl_nxt; xl_nxt = t;
    }

    final_kernel<<<NP, 128>>>(xp_cur, lno_w, lno_b, fc_w, fc_b, out);
}

// round 9
// speedup vs baseline: 3.9381x; 1.0905x over previous
#include <cuda_runtime.h>
#include <cuda_fp16.h>
#include <cstdint>
#include <cstddef>

#define NP 50000
#define NL 10000
#define H  128
#define D  16
#define NLAYER 4
#define EPP 500000
#define ELP 100000
#define EPL 100000
#define ETOT (EPP + ELP + EPL)
#define NCNT (2 * NP + NL)
#define NBIN 512
#define CH0 49
#define CH1 49
#define CH2 10
#define CHT (CH0 + CH1 + CH2)

// ---------------- scratch (device globals; no runtime allocation) ----------------
__device__ float  g_xpA[NP * H];
__device__ float  g_xpB[NP * H];
__device__ float  g_xlA[NL * H];
__device__ float  g_xlB[NL * H];
__device__ __half g_Pp[(size_t)NP * 8 * H];   // fp16 projection slices (f|s pairs adjacent)
__device__ __half g_Pl[(size_t)NL * 4 * H];
__device__ float  g_agg_pp[NP * H];
__device__ float  g_agg_lp[NP * H];
__device__ float  g_agg_pl[NL * H];
__device__ float  g_T[(size_t)12 * (NBIN + 1) * 256];
__device__ int    g_cnt[NCNT];
__device__ int    g_off[NCNT + 3];
__device__ int    g_cur[NCNT];
__device__ int    g_ssrc[ETOT];
__device__ float  g_su[ETOT];
__device__ int    g_chunksum[CHT];
__device__ int    g_chunkbase[CHT];

// ---------------- small helpers ----------------
__device__ __forceinline__ uint32_t smem_u32(const void* p) {
    uint32_t a;
    asm("{ .reg .u64 t; cvta.to.shared.u64 t, %1; cvt.u32.u64 %0, t; }" : "=r"(a) : "l"(p));
    return a;
}
__device__ __forceinline__ void block_reduce_2(float& s, float& q, float* shbuf)
{
    unsigned m = 0xffffffffu;
    #pragma unroll
    for (int o = 16; o > 0; o >>= 1) {
        s += __shfl_down_sync(m, s, o);
        q += __shfl_down_sync(m, q, o);
    }
    int lane = threadIdx.x & 31, wid = threadIdx.x >> 5;
    if (lane == 0) { shbuf[wid] = s; shbuf[4 + wid] = q; }
    __syncthreads();
    s = shbuf[0] + shbuf[1] + shbuf[2] + shbuf[3];
    q = shbuf[4] + shbuf[5] + shbuf[6] + shbuf[7];
    __syncthreads();
}
__device__ __forceinline__ float sig_tanh(float x) {
    float t;
    asm("tanh.approx.f32 %0, %1;" : "=f"(t) : "f"(x * 0.5f));
    return 0.5f * t + 0.5f;
}
__device__ __forceinline__ float softplus_f(float x) {
    return fmaxf(x, 0.f) + __logf(1.0f + __expf(-fabsf(x)));
}
__device__ __forceinline__ float4 h4f(uint2 v) {
    __half2 a = *(__half2*)&v.x;
    __half2 b = *(__half2*)&v.y;
    float2 fa = __half22float2(a);
    float2 fb = __half22float2(b);
    return make_float4(fa.x, fa.y, fb.x, fb.y);
}
__device__ __forceinline__ float4 cg_ln_relu(float4 a, float4 lw, float4 lb)
{
    float s = a.x + a.y + a.z + a.w;
    float q = a.x * a.x + a.y * a.y + a.z * a.z + a.w * a.w;
    #pragma unroll
    for (int o = 16; o > 0; o >>= 1) {
        s += __shfl_xor_sync(0xffffffffu, s, o);
        q += __shfl_xor_sync(0xffffffffu, q, o);
    }
    float mean = s * (1.0f / H);
    float var = q * (1.0f / H) - mean * mean;
    float r = rsqrtf(var + 1e-5f);
    float4 y;
    y.x = fmaxf((a.x - mean) * r * lw.x + lb.x, 0.f);
    y.y = fmaxf((a.y - mean) * r * lw.y + lb.y, 0.f);
    y.z = fmaxf((a.z - mean) * r * lw.z + lb.z, 0.f);
    y.w = fmaxf((a.w - mean) * r * lw.w + lb.w, 0.f);
    return y;
}

// ---------------- CSR build ----------------
__global__ void hist_all(const int* __restrict__ ei_pp, const int* __restrict__ ei_lp,
                         const int* __restrict__ ei_pl, int* __restrict__ cnt)
{
    int idx = blockIdx.x * blockDim.x + threadIdx.x;
    if (idx >= ETOT) return;
    if (idx < EPP) {
        atomicAdd(&cnt[ei_pp[EPP + idx]], 1);
    } else if (idx < EPP + ELP) {
        int e = idx - EPP;
        atomicAdd(&cnt[NP + ei_lp[ELP + e]], 1);
    } else {
        int e = idx - EPP - ELP;
        atomicAdd(&cnt[2 * NP + ei_pl[EPL + e]], 1);
    }
}

__global__ __launch_bounds__(1024) void scanA(const int* __restrict__ cnt,
                                              int* __restrict__ off,
                                              int* __restrict__ chunksum)
{
    __shared__ int s[1024];
    int bid = blockIdx.x;
    const int* cbase; int* obase; int N; int c;
    if (bid < CH0)            { cbase = cnt;          obase = off;              N = NP; c = bid; }
    else if (bid < CH0 + CH1) { cbase = cnt + NP;     obase = off + NP + 1;     N = NP; c = bid - CH0; }
    else                      { cbase = cnt + 2 * NP; obase = off + 2 * NP + 2; N = NL; c = bid - CH0 - CH1; }
    int tid = threadIdx.x;
    int i = c * 1024 + tid;
    int v = (i < N) ? cbase[i] : 0;
    s[tid] = v;
    __syncthreads();
    #pragma unroll
    for (int o = 1; o < 1024; o <<= 1) {
        int t = (tid >= o) ? s[tid - o] : 0;
        __syncthreads();
        s[tid] += t;
        __syncthreads();
    }
    if (i < N) obase[i] = s[tid] - v;
    if (tid == 1023) chunksum[bid] = s[1023];
}

__global__ void scanB(const int* __restrict__ chunksum, int* __restrict__ chunkbase,
                      int* __restrict__ off)
{
    int t = threadIdx.x;
    if (t == 0) {
        int b = 0;
        for (int c = 0; c < CH0; ++c) { chunkbase[c] = b; b += chunksum[c]; }
        off[NP] = b;
    } else if (t == 1) {
        int b = 0;
        for (int c = 0; c < CH1; ++c) { chunkbase[CH0 + c] = b; b += chunksum[CH0 + c]; }
        off[NP + 1 + NP] = b;
    } else if (t == 2) {
        int b = 0;
        for (int c = 0; c < CH2; ++c) { chunkbase[CH0 + CH1 + c] = b; b += chunksum[CH0 + CH1 + c]; }
        off[2 * NP + 2 + NL] = b;
    }
}

__global__ __launch_bounds__(1024) void scanC(int* __restrict__ off,
                                              const int* __restrict__ chunkbase,
                                              int* __restrict__ cur)
{
    int bid = blockIdx.x;
    int* obase; int* curb; int N; int c;
    if (bid < CH0)            { obase = off;              curb = cur;          N = NP; c = bid; }
    else if (bid < CH0 + CH1) { obase = off + NP + 1;     curb = cur + NP;     N = NP; c = bid - CH0; }
    else                      { obase = off + 2 * NP + 2; curb = cur + 2 * NP; N = NL; c = bid - CH0 - CH1; }
    int i = c * 1024 + threadIdx.x;
    if (i < N) {
        int v = obase[i] + chunkbase[bid];
        obase[i] = v;
        curb[i] = v;
    }
}

__global__ void scatter_all(const int* __restrict__ ei_pp, const float* __restrict__ ea_pp,
                            const int* __restrict__ ei_lp, const float* __restrict__ ea_lp,
                            const int* __restrict__ ei_pl, const float* __restrict__ ea_pl,
                            int* __restrict__ cur, int* __restrict__ ssrc,
                            float* __restrict__ su)
{
    const float usc = (float)NBIN / 8.0f;
    int idx = blockIdx.x * blockDim.x + threadIdx.x;
    if (idx >= ETOT) return;
    if (idx < EPP) {
        int e = idx;
        int d = ei_pp[EPP + e];
        int p = atomicAdd(&cur[d], 1);
        ssrc[p] = ei_pp[e];
        su[p] = ea_pp[e] * usc;
    } else if (idx < EPP + ELP) {
        int e = idx - EPP;
        int d = ei_lp[ELP + e];
        int p = EPP + atomicAdd(&cur[NP + d], 1);
        ssrc[p] = ei_lp[e];
        su[p] = ea_lp[e] * usc;
    } else {
        int e = idx - EPP - ELP;
        int d = ei_pl[EPL + e];
        int p = EPP + ELP + atomicAdd(&cur[2 * NP + d], 1);
        ssrc[p] = ei_pl[e];
        su[p] = ea_pl[e] * usc;
    }
}

// ---------------- LUT build ----------------
__global__ __launch_bounds__(256) void lut_build(
    const float* __restrict__ Wf, const float* __restrict__ Ws, float* __restrict__ T)
{
    int b = blockIdx.x;
    int lt = blockIdx.y;
    int j = threadIdx.x;
    float d = (float)b * (8.0f / (float)NBIN);
    const float step = 8.0f / 15.0f;
    const float coeff = -0.5f / (step * step);
    float r[16];
    #pragma unroll
    for (int k = 0; k < 16; ++k) {
        float dlt = d - (float)k * step;
        r[k] = __expf(coeff * dlt * dlt);
    }
    const float* W = (j < 128 ? Wf : Ws) + ((size_t)lt * 272 + 256) * H + (j & 127);
    float acc = 0.f;
    #pragma unroll
    for (int k = 0; k < 16; ++k) acc += r[k] * W[(size_t)k * H];
    T[((size_t)lt * (NBIN + 1) + b) * 256 + j] = acc;
}

// ---------------- merged initial embedding ----------------
__global__ __launch_bounds__(128) void embed_kernel(
    const float* __restrict__ xp, const float* __restrict__ Wp, const float* __restrict__ bp,
    const float* __restrict__ xl, const float* __restrict__ Wl, const float* __restrict__ bl,
    float* __restrict__ outp, float* __restrict__ outl)
{
    int i = blockIdx.x;
    int j = threadIdx.x;
    const float *x, *W, *b; float* o; int r;
    if (i < NP) { x = xp; W = Wp; b = bp; o = outp; r = i; }
    else        { x = xl; W = Wl; b = bl; o = outl; r = i - NP; }
    const float* xr = x + (size_t)r * 6;
    float acc = b[j];
    #pragma unroll
    for (int k = 0; k < 6; ++k) acc += xr[k] * W[k * H + j];
    o[(size_t)r * H + j] = acc;
}

// ---------------- pipelined tf32 mma.sync projection GEMM (cp.async, BK=32) ------
struct PtrArr12 { const float* p[12]; };

#define APA 36
#define APB 136
#define AST (128 * APA)
#define BST (32 * APB)
#define STG (AST + BST)
#define SMEM_MMA_BYTES (2 * STG * 4)

__global__ __launch_bounds__(256, 2) void proj_mma(
    const float* __restrict__ Xp, const float* __restrict__ Xl, PtrArr12 wp,
    __half* __restrict__ outP, __half* __restrict__ outL)
{
    int slice = blockIdx.y;
    const float* X; __half* out; int N, outStride, col;
    if (slice < 8) { X = Xp; out = outP; N = NP; outStride = 8 * H; col = slice; }
    else           { X = Xl; out = outL; N = NL; outStride = 4 * H; col = slice - 8; }
    int m0 = blockIdx.x * 128;
    if (m0 >= N) return;

    extern __shared__ float sm[];
    uint32_t smb = smem_u32(sm);
    const float* W = wp.p[slice];
    int tid = threadIdx.x;
    int lane = tid & 31, warp = tid >> 5;
    int g = lane >> 2, t = lane & 3;

    auto load_stage = [&](int chunk, int s) {
        int kb = chunk * 32;
        uint32_t abase = smb + (uint32_t)(s * STG) * 4u;
        uint32_t bbase = abase + (uint32_t)AST * 4u;
        #pragma unroll
        for (int i = 0; i < 4; ++i) {
            int idx = tid + i * 256;
            int r = idx >> 3, c4 = (idx & 7) * 4;
            uint32_t dst = abase + (uint32_t)(r * APA + c4) * 4u;
            const float* src = X + (size_t)(m0 + r) * H + kb + c4;
            int sz = (m0 + r < N) ? 16 : 0;
            asm volatile("cp.async.cg.shared.global [%0], [%1], 16, %2;"
                         :: "r"(dst), "l"(src), "r"(sz));
        }
        #pragma unroll
        for (int i = 0; i < 4; ++i) {
            int idx = tid + i * 256;
            int k = idx >> 5, n4 = (idx & 31) * 4;
            uint32_t dst = bbase + (uint32_t)(k * APB + n4) * 4u;
            const float* src = W + (size_t)(kb + k) * H + n4;
            asm volatile("cp.async.cg.shared.global [%0], [%1], 16;"
                         :: "r"(dst), "l"(src));
        }
        asm volatile("cp.async.commit_group;" ::: "memory");
    };

    load_stage(0, 0);
    load_stage(1, 1);

    int wm = warp >> 2;
    int wn = warp & 3;
    int mbase = wm * 64;
    int nbase = wn * 32;

    float d[4][4][4];
    #pragma unroll
    for (int i = 0; i < 4; ++i)
        #pragma unroll
        for (int j = 0; j < 4; ++j)
            #pragma unroll
            for (int q = 0; q < 4; ++q) d[i][j][q] = 0.f;

    #pragma unroll
    for (int c = 0; c < 4; ++c) {
        if (c < 3) asm volatile("cp.async.wait_group 1;" ::: "memory");
        else       asm volatile("cp.async.wait_group 0;" ::: "memory");
        __syncthreads();

        const float* Asp = sm + (c & 1) * STG;
        const float* Bsp = Asp + AST;

        #pragma unroll
        for (int ks = 0; ks < 4; ++ks) {
            int kbl = ks * 8;
            uint32_t a[4][4];
            #pragma unroll
            for (int i = 0; i < 4; ++i) {
                int r0 = mbase + i * 16 + g;
                a[i][0] = *(const uint32_t*)&Asp[r0 * APA + kbl + t];
                a[i][1] = *(const uint32_t*)&Asp[(r0 + 8) * APA + kbl + t];
                a[i][2] = *(const uint32_t*)&Asp[r0 * APA + kbl + 4 + t];
                a[i][3] = *(const uint32_t*)&Asp[(r0 + 8) * APA + kbl + 4 + t];
            }
            uint32_t b[4][2];
            #pragma unroll
            for (int j = 0; j < 4; ++j) {
                int c0 = nbase + j * 8 + g;
                b[j][0] = *(const uint32_t*)&Bsp[(kbl + t) * APB + c0];
                b[j][1] = *(const uint32_t*)&Bsp[(kbl + 4 + t) * APB + c0];
            }
            #pragma unroll
            for (int i = 0; i < 4; ++i)
                #pragma unroll
                for (int j = 0; j < 4; ++j) {
                    asm volatile(
                        "mma.sync.aligned.m16n8k8.row.col.f32.tf32.tf32.f32 "
                        "{%0,%1,%2,%3}, {%4,%5,%6,%7}, {%8,%9}, {%0,%1,%2,%3};"
                        : "+f"(d[i][j][0]), "+f"(d[i][j][1]), "+f"(d[i][j][2]), "+f"(d[i][j][3])
                        : "r"(a[i][0]), "r"(a[i][1]), "r"(a[i][2]), "r"(a[i][3]),
                          "r"(b[j][0]), "r"(b[j][1]));
                }
        }
        __syncthreads();
        if (c + 2 < 4) load_stage(c + 2, c & 1);
    }

    size_t colbase = (size_t)col * H;
    #pragma unroll
    for (int i = 0; i < 4; ++i) {
        int gr0 = m0 + mbase + i * 16 + g;
        int gr1 = gr0 + 8;
        #pragma unroll
        for (int j = 0; j < 4; ++j) {
            int gc = nbase + j * 8 + t * 2;
            if (gr0 < N)
                *(__half2*)(out + (size_t)gr0 * outStride + colbase + gc) =
                    __floats2half2_rn(d[i][j][0], d[i][j][1]);
            if (gr1 < N)
                *(__half2*)(out + (size_t)gr1 * outStride + colbase + gc) =
                    __floats2half2_rn(d[i][j][2], d[i][j][3]);
        }
    }
}

// ---------------- merged CSR edge kernel: fp16 P, 4-edge batched gathers ----------
struct EdgeArgs {
    const int*    off[3];
    const int*    ssrc[3];
    const float*  su[3];
    const float*  T[3];
    const __half* Pd[3]; int dstr[3];
    const __half* Ps[3]; int sstr[3];
    const float*  bfp[3];
    const float*  bsp[3];
    float*        agg[3];
};

__device__ __forceinline__ void edge_math(
    float4 fsv, float4 ssv, float u, const float* __restrict__ T, int j0,
    float fd0, float fd1, float fd2, float fd3,
    float sd0, float sd1, float sd2, float sd3,
    float& a0, float& a1, float& a2, float& a3, bool valid)
{
    int b = min((int)u, NBIN - 1);
    float w = u - (float)b;
    const float* Tb = T + (size_t)b * 256 + j0;
    float4 flo = *(const float4*)(Tb);
    float4 fhi = *(const float4*)(Tb + 256);
    float4 slo = *(const float4*)(Tb + 128);
    float4 shi = *(const float4*)(Tb + 384);

    float f0 = fd0 + fsv.x + flo.x + w * (fhi.x - flo.x);
    float f1 = fd1 + fsv.y + flo.y + w * (fhi.y - flo.y);
    float f2 = fd2 + fsv.z + flo.z + w * (fhi.z - flo.z);
    float f3 = fd3 + fsv.w + flo.w + w * (fhi.w - flo.w);
    float s0 = sd0 + ssv.x + slo.x + w * (shi.x - slo.x);
    float s1 = sd1 + ssv.y + slo.y + w * (shi.y - slo.y);
    float s2 = sd2 + ssv.z + slo.z + w * (shi.z - slo.z);
    float s3 = sd3 + ssv.w + slo.w + w * (shi.w - slo.w);

    if (valid) {
        a0 += sig_tanh(f0) * softplus_f(s0);
        a1 += sig_tanh(f1) * softplus_f(s1);
        a2 += sig_tanh(f2) * softplus_f(s2);
        a3 += sig_tanh(f3) * softplus_f(s3);
    }
}

__global__ __launch_bounds__(256) void edge_all(EdgeArgs ea)
{
    int w = blockIdx.x * 8 + (threadIdx.x >> 5);
    int lane = threadIdx.x & 31;
    int j0 = lane * 4;

    int t, n;
    if (w < NP)               { t = 0; n = w; }
    else if (w < 2 * NP)      { t = 1; n = w - NP; }
    else if (w < 2 * NP + NL) { t = 2; n = w - 2 * NP; }
    else return;

    const int* off = ea.off[t];
    int p0 = off[n], p1 = off[n + 1];

    float4 bf4 = *(const float4*)(ea.bfp[t] + j0);
    float4 bs4 = *(const float4*)(ea.bsp[t] + j0);
    const __half* pd = ea.Pd[t] + (size_t)n * ea.dstr[t] + j0;
    float4 fdv = h4f(*(const uint2*)(pd));
    float4 sdv = h4f(*(const uint2*)(pd + H));
    float fd0 = fdv.x + bf4.x, fd1 = fdv.y + bf4.y, fd2 = fdv.z + bf4.z, fd3 = fdv.w + bf4.w;
    float sd0 = sdv.x + bs4.x, sd1 = sdv.y + bs4.y, sd2 = sdv.z + bs4.z, sd3 = sdv.w + bs4.w;

    const __half* Ps = ea.Ps[t];
    int sstr = ea.sstr[t];
    const int* ssrc = ea.ssrc[t];
    const float* su = ea.su[t];
    const float* T = ea.T[t];

    float a0 = 0.f, a1 = 0.f, a2 = 0.f, a3 = 0.f;

    for (int p = p0; p < p1; p += 4) {
        int pe = p1 - 1;
        int i1 = min(p + 1, pe), i2 = min(p + 2, pe), i3 = min(p + 3, pe);
        int sA = ssrc[p], sB = ssrc[i1], sC = ssrc[i2], sD = ssrc[i3];
        float uA = su[p], uB = su[i1], uC = su[i2], uD = su[i3];

        const __half* qA = Ps + (size_t)sA * sstr + j0;
        const __half* qB = Ps + (size_t)sB * sstr + j0;
        const __half* qC = Ps + (size_t)sC * sstr + j0;
        const __half* qD = Ps + (size_t)sD * sstr + j0;
        uint2 rfA = *(const uint2*)(qA);
        uint2 rfB = *(const uint2*)(qB);
        uint2 rfC = *(const uint2*)(qC);
        uint2 rfD = *(const uint2*)(qD);
        uint2 rsA = *(const uint2*)(qA + H);
        uint2 rsB = *(const uint2*)(qB + H);
        uint2 rsC = *(const uint2*)(qC + H);
        uint2 rsD = *(const uint2*)(qD + H);

        edge_math(h4f(rfA), h4f(rsA), uA, T, j0, fd0, fd1, fd2, fd3, sd0, sd1, sd2, sd3,
                  a0, a1, a2, a3, true);
        edge_math(h4f(rfB), h4f(rsB), uB, T, j0, fd0, fd1, fd2, fd3, sd0, sd1, sd2, sd3,
                  a0, a1, a2, a3, p + 1 < p1);
        edge_math(h4f(rfC), h4f(rsC), uC, T, j0, fd0, fd1, fd2, fd3, sd0, sd1, sd2, sd3,
                  a0, a1, a2, a3, p + 2 < p1);
        edge_math(h4f(rfD), h4f(rsD), uD, T, j0, fd0, fd1, fd2, fd3, sd0, sd1, sd2, sd3,
                  a0, a1, a2, a3, p + 3 < p1);
    }
    *(float4*)(ea.agg[t] + (size_t)n * H + j0) = make_float4(a0, a1, a2, a3);
}

// ---------------- merged node epilogue ----------------
__global__ __launch_bounds__(256) void node_update(
    const float* __restrict__ xp_in, const float* __restrict__ agg_pp,
    const float* __restrict__ agg_lp,
    const float* __restrict__ xl_in, const float* __restrict__ agg_pl,
    const float* __restrict__ bn_w, const float* __restrict__ bn_b,
    const float* __restrict__ ln_w, const float* __restrict__ ln_b, int l,
    float* __restrict__ xp_out, float* __restrict__ xl_out)
{
    int w = blockIdx.x * 8 + (threadIdx.x >> 5);
    int lane = threadIdx.x & 31;
    int j0 = lane * 4;
    const float bnf = rsqrtf(1.0f + 1e-5f);

    if (w < NP) {
        size_t off = (size_t)w * H + j0;
        float4 x = *(const float4*)(xp_in + off);

        size_t pb0 = (size_t)(l * 3 + 0) * H + j0;
        float4 bw = *(const float4*)(bn_w + pb0);
        float4 bb = *(const float4*)(bn_b + pb0);
        float4 lw = *(const float4*)(ln_w + pb0);
        float4 lb = *(const float4*)(ln_b + pb0);
        float4 g = *(const float4*)(agg_pp + off);
        float4 a;
        a.x = g.x * (bw.x * bnf) + bb.x + x.x;
        a.y = g.y * (bw.y * bnf) + bb.y + x.y;
        a.z = g.z * (bw.z * bnf) + bb.z + x.z;
        a.w = g.w * (bw.w * bnf) + bb.w + x.w;
        float4 y1 = cg_ln_relu(a, lw, lb);

        size_t pb1 = (size_t)(l * 3 + 1) * H + j0;
        bw = *(const float4*)(bn_w + pb1);
        bb = *(const float4*)(bn_b + pb1);
        lw = *(const float4*)(ln_w + pb1);
        lb = *(const float4*)(ln_b + pb1);
        g = *(const float4*)(agg_lp + off);
        a.x = g.x * (bw.x * bnf) + bb.x + x.x;
        a.y = g.y * (bw.y * bnf) + bb.y + x.y;
        a.z = g.z * (bw.z * bnf) + bb.z + x.z;
        a.w = g.w * (bw.w * bnf) + bb.w + x.w;
        float4 y2 = cg_ln_relu(a, lw, lb);

        float4 r;
        r.x = y1.x + y2.x + 2.f * x.x;
        r.y = y1.y + y2.y + 2.f * x.y;
        r.z = y1.z + y2.z + 2.f * x.z;
        r.w = y1.w + y2.w + 2.f * x.w;
        *(float4*)(xp_out + off) = r;
    } else if (w < NP + NL) {
        int i = w - NP;
        size_t off = (size_t)i * H + j0;
        float4 x = *(const float4*)(xl_in + off);
        size_t pb2 = (size_t)(l * 3 + 2) * H + j0;
        float4 bw = *(const float4*)(bn_w + pb2);
        float4 bb = *(const float4*)(bn_b + pb2);
        float4 lw = *(const float4*)(ln_w + pb2);
        float4 lb = *(const float4*)(ln_b + pb2);
        float4 g = *(const float4*)(agg_pl + off);
        float4 a;
        a.x = g.x * (bw.x * bnf) + bb.x + x.x;
        a.y = g.y * (bw.y * bnf) + bb.y + x.y;
        a.z = g.z * (bw.z * bnf) + bb.z + x.z;
        a.w = g.w * (bw.w * bnf) + bb.w + x.w;
        float4 y = cg_ln_relu(a, lw, lb);
        float4 r;
        r.x = y.x + x.x; r.y = y.y + x.y; r.z = y.z + x.z; r.w = y.w + x.w;
        *(float4*)(xl_out + off) = r;
    }
}

// ---------------- final: LN(xp) @ fc_w + fc_b ----------------
__global__ __launch_bounds__(128) void final_kernel(
    const float* __restrict__ xp,
    const float* __restrict__ lnw, const float* __restrict__ lnb,
    const float* __restrict__ fcw, const float* __restrict__ fcb,
    float* __restrict__ out)
{
    __shared__ float sh[8];
    __shared__ float yb[H];
    __shared__ float part[4][21];
    int i = blockIdx.x, j = threadIdx.x;
    float x = xp[(size_t)i * H + j];
    float s = x, q = x * x;
    block_reduce_2(s, q, sh);
    float mean = s * (1.0f / H);
    float var = q * (1.0f / H) - mean * mean;
    yb[j] = (x - mean) * rsqrtf(var + 1e-5f) * lnw[j] + lnb[j];
    __syncthreads();
    if (j < 84) {
        int c = j % 21, qq = j / 21;
        float acc = 0.f;
        #pragma unroll
        for (int t = 0; t < 32; ++t) acc += yb[qq * 32 + t] * fcw[(qq * 32 + t) * 21 + c];
        part[qq][c] = acc;
    }
    __syncthreads();
    if (j < 21)
        out[(size_t)i * 21 + j] = part[0][j] + part[1][j] + part[2][j] + part[3][j] + fcb[j];
}

// ---------------- host ----------------
extern "C" void kernel_launch(void* const* d_in, const int* in_sizes, int n_in,
                              void* d_out, int out_size)
{
    const float* x_protein = (const float*)d_in[0];
    const float* x_ligand  = (const float*)d_in[1];
    const int*   ei_pp     = (const int*)d_in[2];
    const float* ea_pp     = (const float*)d_in[3];
    const int*   ei_lp     = (const int*)d_in[4];
    const float* ea_lp     = (const float*)d_in[5];
    const int*   ei_pl     = (const int*)d_in[6];
    const float* ea_pl     = (const float*)d_in[7];
    const float* Wp        = (const float*)d_in[8];
    const float* bp        = (const float*)d_in[9];
    const float* Wl        = (const float*)d_in[10];
    const float* bl        = (const float*)d_in[11];
    const float* Wf        = (const float*)d_in[12];
    const float* bf        = (const float*)d_in[13];
    const float* Ws        = (const float*)d_in[14];
    const float* bs        = (const float*)d_in[15];
    const float* bn_w      = (const float*)d_in[16];
    const float* bn_b      = (const float*)d_in[17];
    const float* ln_w      = (const float*)d_in[18];
    const float* ln_b      = (const float*)d_in[19];
    const float* lno_w     = (const float*)d_in[20];
    const float* lno_b     = (const float*)d_in[21];
    const float* fc_w      = (const float*)d_in[22];
    const float* fc_b      = (const float*)d_in[23];
    float* out = (float*)d_out;

    float *xpA, *xpB, *xlA, *xlB, *agg_pp, *agg_lp, *agg_pl, *su, *Tb;
    __half *Pp, *Pl;
    int *cnt, *offs, *cur, *ssrc, *chs, *chb;
    cudaGetSymbolAddress((void**)&xpA, g_xpA);
    cudaGetSymbolAddress((void**)&xpB, g_xpB);
    cudaGetSymbolAddress((void**)&xlA, g_xlA);
    cudaGetSymbolAddress((void**)&xlB, g_xlB);
    cudaGetSymbolAddress((void**)&Pp, g_Pp);
    cudaGetSymbolAddress((void**)&Pl, g_Pl);
    cudaGetSymbolAddress((void**)&agg_pp, g_agg_pp);
    cudaGetSymbolAddress((void**)&agg_lp, g_agg_lp);
    cudaGetSymbolAddress((void**)&agg_pl, g_agg_pl);
    cudaGetSymbolAddress((void**)&Tb, g_T);
    cudaGetSymbolAddress((void**)&cnt, g_cnt);
    cudaGetSymbolAddress((void**)&offs, g_off);
    cudaGetSymbolAddress((void**)&cur, g_cur);
    cudaGetSymbolAddress((void**)&ssrc, g_ssrc);
    cudaGetSymbolAddress((void**)&su, g_su);
    cudaGetSymbolAddress((void**)&chs, g_chunksum);
    cudaGetSymbolAddress((void**)&chb, g_chunkbase);

    cudaFuncSetAttribute(proj_mma, cudaFuncAttributeMaxDynamicSharedMemorySize, SMEM_MMA_BYTES);

    auto wfp = [&](int l, int b, int r) { return Wf + ((size_t)(l * 3 + b) * 272 + r) * H; };
    auto wsp = [&](int l, int b, int r) { return Ws + ((size_t)(l * 3 + b) * 272 + r) * H; };
    auto mkw = [&](int l) {
        PtrArr12 w;
        w.p[0] = wfp(l, 0, 0);    w.p[1] = wsp(l, 0, 0);
        w.p[2] = wfp(l, 0, 128);  w.p[3] = wsp(l, 0, 128);
        w.p[4] = wfp(l, 1, 0);    w.p[5] = wsp(l, 1, 0);
        w.p[6] = wfp(l, 2, 128);  w.p[7] = wsp(l, 2, 128);
        w.p[8] = wfp(l, 1, 128);  w.p[9] = wsp(l, 1, 128);
        w.p[10] = wfp(l, 2, 0);   w.p[11] = wsp(l, 2, 0);
        return w;
    };

    embed_kernel<<<NP + NL, 128>>>(x_protein, Wp, bp, x_ligand, Wl, bl, xpA, xlA);
    lut_build<<<dim3(NBIN + 1, 12), 256>>>(Wf, Ws, Tb);
    cudaMemsetAsync(cnt, 0, NCNT * sizeof(int), 0);
    hist_all<<<(ETOT + 255) / 256, 256>>>(ei_pp, ei_lp, ei_pl, cnt);
    proj_mma<<<dim3((NP + 127) / 128, 12), 256, SMEM_MMA_BYTES>>>(xpA, xlA, mkw(0), Pp, Pl);
    scanA<<<CHT, 1024>>>(cnt, offs, chs);
    scanB<<<1, 32>>>(chs, chb, offs);
    scanC<<<CHT, 1024>>>(offs, chb, cur);
    scatter_all<<<(ETOT + 255) / 256, 256>>>(ei_pp, ea_pp, ei_lp, ea_lp, ei_pl, ea_pl,
                                             cur, ssrc, su);

    float* xp_cur = xpA; float* xp_nxt = xpB;
    float* xl_cur = xlA; float* xl_nxt = xlB;

    for (int l = 0; l < NLAYER; ++l) {
        if (l > 0)
            proj_mma<<<dim3((NP + 127) / 128, 12), 256, SMEM_MMA_BYTES>>>(xp_cur, xl_cur, mkw(l), Pp, Pl);

        EdgeArgs ea;
        ea.off[0] = offs;              ea.ssrc[0] = ssrc;             ea.su[0] = su;
        ea.T[0] = Tb + (size_t)(l * 3 + 0) * (NBIN + 1) * 256;
        ea.Pd[0] = Pp + 0 * H; ea.dstr[0] = 8 * H;
        ea.Ps[0] = Pp + 2 * H; ea.sstr[0] = 8 * H;
        ea.bfp[0] = bf + (size_t)(l * 3 + 0) * H; ea.bsp[0] = bs + (size_t)(l * 3 + 0) * H;
        ea.agg[0] = agg_pp;
        ea.off[1] = offs + NP + 1;     ea.ssrc[1] = ssrc + EPP;       ea.su[1] = su + EPP;
        ea.T[1] = Tb + (size_t)(l * 3 + 1) * (NBIN + 1) * 256;
        ea.Pd[1] = Pp + 4 * H; ea.dstr[1] = 8 * H;
        ea.Ps[1] = Pl + 0 * H; ea.sstr[1] = 4 * H;
        ea.bfp[1] = bf + (size_t)(l * 3 + 1) * H; ea.bsp[1] = bs + (size_t)(l * 3 + 1) * H;
        ea.agg[1] = agg_lp;
        ea.off[2] = offs + 2 * NP + 2; ea.ssrc[2] = ssrc + EPP + ELP; ea.su[2] = su + EPP + ELP;
        ea.T[2] = Tb + (size_t)(l * 3 + 2) * (NBIN + 1) * 256;
        ea.Pd[2] = Pl + 2 * H; ea.dstr[2] = 4 * H;
        ea.Ps[2] = Pp + 6 * H; ea.sstr[2] = 8 * H;
        ea.bfp[2] = bf + (size_t)(l * 3 + 2) * H; ea.bsp[2] = bs + (size_t)(l * 3 + 2) * H;
        ea.agg[2] = agg_pl;

        edge_all<<<(2 * NP + NL + 7) / 8, 256>>>(ea);

        node_update<<<(NP + NL + 7) / 8, 256>>>(xp_cur, agg_pp, agg_lp,
                                                xl_cur, agg_pl,
                                                bn_w, bn_b, ln_w, ln_b, l,
                                                xp_nxt, xl_nxt);

        float* t;
        t = xp_cur; xp_cur = xp_nxt; xp_nxt = t;
        t = xl_cur; xl_cur = xl_nxt; xl_nxt = t;
    }

    final_kernel<<<NP, 128>>>(xp_cur, lno_w, lno_b, fc_w, fc_b, out);
}

// round 10
// speedup vs baseline: 4.5211x; 1.1480x over previous
#include <cuda_runtime.h>
#include <cuda_fp16.h>
#include <cstdint>
#include <cstddef>

#define NP 50000
#define NL 10000
#define H  128
#define D  16
#define NLAYER 4
#define EPP 500000
#define ELP 100000
#define EPL 100000
#define ETOT (EPP + ELP + EPL)
#define NCNT (2 * NP + NL)
#define NBIN 512
#define CH0 49
#define CH1 49
#define CH2 10
#define CHT (CH0 + CH1 + CH2)

// ---------------- scratch (device globals; no runtime allocation) ----------------
__device__ float  g_xpA[NP * H];
__device__ float  g_xpB[NP * H];
__device__ float  g_xlA[NL * H];
__device__ float  g_xlB[NL * H];
__device__ __align__(16) __half g_xph[NP * H];       // fp16 mirror of current xp
__device__ __align__(16) __half g_xlh[NL * H];       // fp16 mirror of current xl
__device__ __align__(16) __half g_Wh[(size_t)48 * 128 * 128];  // fp16 W slices [layer*12+s][n][k]
__device__ __align__(16) __half g_Pp[(size_t)NP * 8 * H];
__device__ __align__(16) __half g_Pl[(size_t)NL * 4 * H];
__device__ float  g_agg_pp[NP * H];
__device__ float  g_agg_lp[NP * H];
__device__ float  g_agg_pl[NL * H];
__device__ float  g_T[(size_t)12 * (NBIN + 1) * 256];
__device__ int    g_cnt[NCNT];
__device__ int    g_off[NCNT + 3];
__device__ int    g_cur[NCNT];
__device__ int    g_ssrc[ETOT];
__device__ float  g_su[ETOT];
__device__ int    g_chunksum[CHT];
__device__ int    g_chunkbase[CHT];

// ---------------- small helpers ----------------
__device__ __forceinline__ uint32_t smem_u32(const void* p) {
    uint32_t a;
    asm("{ .reg .u64 t; cvta.to.shared.u64 t, %1; cvt.u32.u64 %0, t; }" : "=r"(a) : "l"(p));
    return a;
}
__device__ __forceinline__ void block_reduce_2(float& s, float& q, float* shbuf)
{
    unsigned m = 0xffffffffu;
    #pragma unroll
    for (int o = 16; o > 0; o >>= 1) {
        s += __shfl_down_sync(m, s, o);
        q += __shfl_down_sync(m, q, o);
    }
    int lane = threadIdx.x & 31, wid = threadIdx.x >> 5;
    if (lane == 0) { shbuf[wid] = s; shbuf[4 + wid] = q; }
    __syncthreads();
    s = shbuf[0] + shbuf[1] + shbuf[2] + shbuf[3];
    q = shbuf[4] + shbuf[5] + shbuf[6] + shbuf[7];
    __syncthreads();
}
__device__ __forceinline__ float sig_tanh(float x) {
    float t;
    asm("tanh.approx.f32 %0, %1;" : "=f"(t) : "f"(x * 0.5f));
    return 0.5f * t + 0.5f;
}
__device__ __forceinline__ float softplus_f(float x) {
    return fmaxf(x, 0.f) + __logf(1.0f + __expf(-fabsf(x)));
}
__device__ __forceinline__ float4 h4f(uint2 v) {
    __half2 a = *(__half2*)&v.x;
    __half2 b = *(__half2*)&v.y;
    float2 fa = __half22float2(a);
    float2 fb = __half22float2(b);
    return make_float4(fa.x, fa.y, fb.x, fb.y);
}
__device__ __forceinline__ float4 cg_ln_relu(float4 a, float4 lw, float4 lb)
{
    float s = a.x + a.y + a.z + a.w;
    float q = a.x * a.x + a.y * a.y + a.z * a.z + a.w * a.w;
    #pragma unroll
    for (int o = 16; o > 0; o >>= 1) {
        s += __shfl_xor_sync(0xffffffffu, s, o);
        q += __shfl_xor_sync(0xffffffffu, q, o);
    }
    float mean = s * (1.0f / H);
    float var = q * (1.0f / H) - mean * mean;
    float r = rsqrtf(var + 1e-5f);
    float4 y;
    y.x = fmaxf((a.x - mean) * r * lw.x + lb.x, 0.f);
    y.y = fmaxf((a.y - mean) * r * lw.y + lb.y, 0.f);
    y.z = fmaxf((a.z - mean) * r * lw.z + lb.z, 0.f);
    y.w = fmaxf((a.w - mean) * r * lw.w + lb.w, 0.f);
    return y;
}

// ---------------- CSR build ----------------
__global__ void hist_all(const int* __restrict__ ei_pp, const int* __restrict__ ei_lp,
                         const int* __restrict__ ei_pl, int* __restrict__ cnt)
{
    int idx = blockIdx.x * blockDim.x + threadIdx.x;
    if (idx >= ETOT) return;
    if (idx < EPP) {
        atomicAdd(&cnt[ei_pp[EPP + idx]], 1);
    } else if (idx < EPP + ELP) {
        int e = idx - EPP;
        atomicAdd(&cnt[NP + ei_lp[ELP + e]], 1);
    } else {
        int e = idx - EPP - ELP;
        atomicAdd(&cnt[2 * NP + ei_pl[EPL + e]], 1);
    }
}

__global__ __launch_bounds__(1024) void scanA(const int* __restrict__ cnt,
                                              int* __restrict__ off,
                                              int* __restrict__ chunksum)
{
    __shared__ int s[1024];
    int bid = blockIdx.x;
    const int* cbase; int* obase; int N; int c;
    if (bid < CH0)            { cbase = cnt;          obase = off;              N = NP; c = bid; }
    else if (bid < CH0 + CH1) { cbase = cnt + NP;     obase = off + NP + 1;     N = NP; c = bid - CH0; }
    else                      { cbase = cnt + 2 * NP; obase = off + 2 * NP + 2; N = NL; c = bid - CH0 - CH1; }
    int tid = threadIdx.x;
    int i = c * 1024 + tid;
    int v = (i < N) ? cbase[i] : 0;
    s[tid] = v;
    __syncthreads();
    #pragma unroll
    for (int o = 1; o < 1024; o <<= 1) {
        int t = (tid >= o) ? s[tid - o] : 0;
        __syncthreads();
        s[tid] += t;
        __syncthreads();
    }
    if (i < N) obase[i] = s[tid] - v;
    if (tid == 1023) chunksum[bid] = s[1023];
}

__global__ void scanB(const int* __restrict__ chunksum, int* __restrict__ chunkbase,
                      int* __restrict__ off)
{
    int t = threadIdx.x;
    if (t == 0) {
        int b = 0;
        for (int c = 0; c < CH0; ++c) { chunkbase[c] = b; b += chunksum[c]; }
        off[NP] = b;
    } else if (t == 1) {
        int b = 0;
        for (int c = 0; c < CH1; ++c) { chunkbase[CH0 + c] = b; b += chunksum[CH0 + c]; }
        off[NP + 1 + NP] = b;
    } else if (t == 2) {
        int b = 0;
        for (int c = 0; c < CH2; ++c) { chunkbase[CH0 + CH1 + c] = b; b += chunksum[CH0 + CH1 + c]; }
        off[2 * NP + 2 + NL] = b;
    }
}

__global__ __launch_bounds__(1024) void scanC(int* __restrict__ off,
                                              const int* __restrict__ chunkbase,
                                              int* __restrict__ cur)
{
    int bid = blockIdx.x;
    int* obase; int* curb; int N; int c;
    if (bid < CH0)            { obase = off;              curb = cur;          N = NP; c = bid; }
    else if (bid < CH0 + CH1) { obase = off + NP + 1;     curb = cur + NP;     N = NP; c = bid - CH0; }
    else                      { obase = off + 2 * NP + 2; curb = cur + 2 * NP; N = NL; c = bid - CH0 - CH1; }
    int i = c * 1024 + threadIdx.x;
    if (i < N) {
        int v = obase[i] + chunkbase[bid];
        obase[i] = v;
        curb[i] = v;
    }
}

__global__ void scatter_all(const int* __restrict__ ei_pp, const float* __restrict__ ea_pp,
                            const int* __restrict__ ei_lp, const float* __restrict__ ea_lp,
                            const int* __restrict__ ei_pl, const float* __restrict__ ea_pl,
                            int* __restrict__ cur, int* __restrict__ ssrc,
                            float* __restrict__ su)
{
    const float usc = (float)NBIN / 8.0f;
    int idx = blockIdx.x * blockDim.x + threadIdx.x;
    if (idx >= ETOT) return;
    if (idx < EPP) {
        int e = idx;
        int d = ei_pp[EPP + e];
        int p = atomicAdd(&cur[d], 1);
        ssrc[p] = ei_pp[e];
        su[p] = ea_pp[e] * usc;
    } else if (idx < EPP + ELP) {
        int e = idx - EPP;
        int d = ei_lp[ELP + e];
        int p = EPP + atomicAdd(&cur[NP + d], 1);
        ssrc[p] = ei_lp[e];
        su[p] = ea_lp[e] * usc;
    } else {
        int e = idx - EPP - ELP;
        int d = ei_pl[EPL + e];
        int p = EPP + ELP + atomicAdd(&cur[2 * NP + d], 1);
        ssrc[p] = ei_pl[e];
        su[p] = ea_pl[e] * usc;
    }
}

// ---------------- LUT build ----------------
__global__ __launch_bounds__(256) void lut_build(
    const float* __restrict__ Wf, const float* __restrict__ Ws, float* __restrict__ T)
{
    int b = blockIdx.x;
    int lt = blockIdx.y;
    int j = threadIdx.x;
    float d = (float)b * (8.0f / (float)NBIN);
    const float step = 8.0f / 15.0f;
    const float coeff = -0.5f / (step * step);
    float r[16];
    #pragma unroll
    for (int k = 0; k < 16; ++k) {
        float dlt = d - (float)k * step;
        r[k] = __expf(coeff * dlt * dlt);
    }
    const float* W = (j < 128 ? Wf : Ws) + ((size_t)lt * 272 + 256) * H + (j & 127);
    float acc = 0.f;
    #pragma unroll
    for (int k = 0; k < 16; ++k) acc += r[k] * W[(size_t)k * H];
    T[((size_t)lt * (NBIN + 1) + b) * 256 + j] = acc;
}

// ---------------- fp16 weight pre-convert: Wh[ls][n][k] = W[ls](k, n) ----------------
__global__ __launch_bounds__(128) void wconv(
    const float* __restrict__ Wf, const float* __restrict__ Ws, __half* __restrict__ Wh)
{
    const int bmap[12] = {0, 0, 0, 0, 1, 1, 2, 2, 1, 1, 2, 2};
    const int rmap[12] = {0, 0, 128, 128, 0, 0, 128, 128, 128, 128, 0, 0};
    const int fmap[12] = {1, 0, 1, 0, 1, 0, 1, 0, 1, 0, 1, 0};
    int ls = blockIdx.x;          // layer*12 + s
    int layer = ls / 12, s = ls % 12;
    int k = blockIdx.y;
    int n = threadIdx.x;
    const float* base = fmap[s] ? Wf : Ws;
    float v = base[((size_t)(layer * 3 + bmap[s]) * 272 + rmap[s] + k) * H + n];
    Wh[((size_t)ls * 128 + n) * 128 + k] = __float2half(v);
}

// ---------------- merged initial embedding (fp32 + fp16 mirror) ----------------
__global__ __launch_bounds__(128) void embed_kernel(
    const float* __restrict__ xp, const float* __restrict__ Wp, const float* __restrict__ bp,
    const float* __restrict__ xl, const float* __restrict__ Wl, const float* __restrict__ bl,
    float* __restrict__ outp, float* __restrict__ outl,
    __half* __restrict__ outph, __half* __restrict__ outlh)
{
    int i = blockIdx.x;
    int j = threadIdx.x;
    const float *x, *W, *b; float* o; __half* oh; int r;
    if (i < NP) { x = xp; W = Wp; b = bp; o = outp; oh = outph; r = i; }
    else        { x = xl; W = Wl; b = bl; o = outl; oh = outlh; r = i - NP; }
    const float* xr = x + (size_t)r * 6;
    float acc = b[j];
    #pragma unroll
    for (int k = 0; k < 6; ++k) acc += xr[k] * W[k * H + j];
    o[(size_t)r * H + j] = acc;
    oh[(size_t)r * H + j] = __float2half(acc);
}

// ---------------- pipelined fp16 mma.sync projection GEMM (cp.async, BK=64) ------
#define APH 72                     /* halves per smem row (8-half pad) */
#define ASTH (128 * APH)           /* 9216 halves */
#define BSTH (128 * APH)           /* 9216 halves */
#define STGH (ASTH + BSTH)         /* 18432 halves */
#define SMEM_MMA_BYTES (2 * STGH * 2)   /* 73728 B */

__global__ __launch_bounds__(256, 2) void proj_mma(
    const __half* __restrict__ Xph, const __half* __restrict__ Xlh,
    const __half* __restrict__ Wh,   // this layer's 12 slices, [s][n][k]
    __half* __restrict__ outP, __half* __restrict__ outL)
{
    int slice = blockIdx.y;
    const __half* Xh; __half* out; int N, outStride, col;
    if (slice < 8) { Xh = Xph; out = outP; N = NP; outStride = 8 * H; col = slice; }
    else           { Xh = Xlh; out = outL; N = NL; outStride = 4 * H; col = slice - 8; }
    int m0 = blockIdx.x * 128;
    if (m0 >= N) return;

    extern __shared__ __half smh[];
    uint32_t smb = smem_u32(smh);
    const __half* Whs = Wh + (size_t)slice * 128 * 128;
    int tid = threadIdx.x;
    int lane = tid & 31, warp = tid >> 5;
    int g = lane >> 2, t = lane & 3;

    auto load_stage = [&](int chunk, int s) {
        int kb = chunk * 64;
        uint32_t abase = smb + (uint32_t)(s * STGH) * 2u;
        uint32_t bbase = abase + (uint32_t)ASTH * 2u;
        #pragma unroll
        for (int i = 0; i < 4; ++i) {
            int idx = tid + i * 256;
            int r = idx >> 3, c8 = (idx & 7) * 8;
            uint32_t dst = abase + (uint32_t)(r * APH + c8) * 2u;
            const __half* src = Xh + (size_t)(m0 + r) * H + kb + c8;
            int sz = (m0 + r < N) ? 16 : 0;
            asm volatile("cp.async.cg.shared.global [%0], [%1], 16, %2;"
                         :: "r"(dst), "l"(src), "r"(sz));
        }
        #pragma unroll
        for (int i = 0; i < 4; ++i) {
            int idx = tid + i * 256;
            int n = idx >> 3, k8 = (idx & 7) * 8;
            uint32_t dst = bbase + (uint32_t)(n * APH + k8) * 2u;
            const __half* src = Whs + (size_t)n * 128 + kb + k8;
            asm volatile("cp.async.cg.shared.global [%0], [%1], 16;"
                         :: "r"(dst), "l"(src));
        }
        asm volatile("cp.async.commit_group;" ::: "memory");
    };

    load_stage(0, 0);
    load_stage(1, 1);

    int wm = warp >> 2;
    int wn = warp & 3;
    int mbase = wm * 64;
    int nbase = wn * 32;

    float d[4][4][4];
    #pragma unroll
    for (int i = 0; i < 4; ++i)
        #pragma unroll
        for (int j = 0; j < 4; ++j)
            #pragma unroll
            for (int q = 0; q < 4; ++q) d[i][j][q] = 0.f;

    #pragma unroll
    for (int c = 0; c < 2; ++c) {
        if (c == 0) asm volatile("cp.async.wait_group 1;" ::: "memory");
        else        asm volatile("cp.async.wait_group 0;" ::: "memory");
        __syncthreads();

        const __half* Asp = smh + c * STGH;
        const __half* Bsp = Asp + ASTH;

        #pragma unroll
        for (int ks = 0; ks < 4; ++ks) {
            int kbl = ks * 16;
            uint32_t a[4][4];
            #pragma unroll
            for (int i = 0; i < 4; ++i) {
                int r0 = mbase + i * 16 + g;
                a[i][0] = *(const uint32_t*)&Asp[r0 * APH + kbl + 2 * t];
                a[i][1] = *(const uint32_t*)&Asp[(r0 + 8) * APH + kbl + 2 * t];
                a[i][2] = *(const uint32_t*)&Asp[r0 * APH + kbl + 8 + 2 * t];
                a[i][3] = *(const uint32_t*)&Asp[(r0 + 8) * APH + kbl + 8 + 2 * t];
            }
            uint32_t b[4][2];
            #pragma unroll
            for (int j = 0; j < 4; ++j) {
                int c0 = nbase + j * 8 + g;
                b[j][0] = *(const uint32_t*)&Bsp[c0 * APH + kbl + 2 * t];
                b[j][1] = *(const uint32_t*)&Bsp[c0 * APH + kbl + 8 + 2 * t];
            }
            #pragma unroll
            for (int i = 0; i < 4; ++i)
                #pragma unroll
                for (int j = 0; j < 4; ++j) {
                    asm volatile(
                        "mma.sync.aligned.m16n8k16.row.col.f32.f16.f16.f32 "
                        "{%0,%1,%2,%3}, {%4,%5,%6,%7}, {%8,%9}, {%0,%1,%2,%3};"
                        : "+f"(d[i][j][0]), "+f"(d[i][j][1]), "+f"(d[i][j][2]), "+f"(d[i][j][3])
                        : "r"(a[i][0]), "r"(a[i][1]), "r"(a[i][2]), "r"(a[i][3]),
                          "r"(b[j][0]), "r"(b[j][1]));
                }
        }
    }

    size_t colbase = (size_t)col * H;
    #pragma unroll
    for (int i = 0; i < 4; ++i) {
        int gr0 = m0 + mbase + i * 16 + g;
        int gr1 = gr0 + 8;
        #pragma unroll
        for (int j = 0; j < 4; ++j) {
            int gc = nbase + j * 8 + t * 2;
            if (gr0 < N)
                *(__half2*)(out + (size_t)gr0 * outStride + colbase + gc) =
                    __floats2half2_rn(d[i][j][0], d[i][j][1]);
            if (gr1 < N)
                *(__half2*)(out + (size_t)gr1 * outStride + colbase + gc) =
                    __floats2half2_rn(d[i][j][2], d[i][j][3]);
        }
    }
}

// ---------------- merged CSR edge kernel: fp16 P, 4-edge batched gathers ----------
struct EdgeArgs {
    const int*    off[3];
    const int*    ssrc[3];
    const float*  su[3];
    const float*  T[3];
    const __half* Pd[3]; int dstr[3];
    const __half* Ps[3]; int sstr[3];
    const float*  bfp[3];
    const float*  bsp[3];
    float*        agg[3];
};

__device__ __forceinline__ void edge_math(
    float4 fsv, float4 ssv, float u, const float* __restrict__ T, int j0,
    float fd0, float fd1, float fd2, float fd3,
    float sd0, float sd1, float sd2, float sd3,
    float& a0, float& a1, float& a2, float& a3, bool valid)
{
    int b = min((int)u, NBIN - 1);
    float w = u - (float)b;
    const float* Tb = T + (size_t)b * 256 + j0;
    float4 flo = *(const float4*)(Tb);
    float4 fhi = *(const float4*)(Tb + 256);
    float4 slo = *(const float4*)(Tb + 128);
    float4 shi = *(const float4*)(Tb + 384);

    float f0 = fd0 + fsv.x + flo.x + w * (fhi.x - flo.x);
    float f1 = fd1 + fsv.y + flo.y + w * (fhi.y - flo.y);
    float f2 = fd2 + fsv.z + flo.z + w * (fhi.z - flo.z);
    float f3 = fd3 + fsv.w + flo.w + w * (fhi.w - flo.w);
    float s0 = sd0 + ssv.x + slo.x + w * (shi.x - slo.x);
    float s1 = sd1 + ssv.y + slo.y + w * (shi.y - slo.y);
    float s2 = sd2 + ssv.z + slo.z + w * (shi.z - slo.z);
    float s3 = sd3 + ssv.w + slo.w + w * (shi.w - slo.w);

    if (valid) {
        a0 += sig_tanh(f0) * softplus_f(s0);
        a1 += sig_tanh(f1) * softplus_f(s1);
        a2 += sig_tanh(f2) * softplus_f(s2);
        a3 += sig_tanh(f3) * softplus_f(s3);
    }
}

__global__ __launch_bounds__(256) void edge_all(EdgeArgs ea)
{
    int w = blockIdx.x * 8 + (threadIdx.x >> 5);
    int lane = threadIdx.x & 31;
    int j0 = lane * 4;

    int t, n;
    if (w < NP)               { t = 0; n = w; }
    else if (w < 2 * NP)      { t = 1; n = w - NP; }
    else if (w < 2 * NP + NL) { t = 2; n = w - 2 * NP; }
    else return;

    const int* off = ea.off[t];
    int p0 = off[n], p1 = off[n + 1];

    float4 bf4 = *(const float4*)(ea.bfp[t] + j0);
    float4 bs4 = *(const float4*)(ea.bsp[t] + j0);
    const __half* pd = ea.Pd[t] + (size_t)n * ea.dstr[t] + j0;
    float4 fdv = h4f(*(const uint2*)(pd));
    float4 sdv = h4f(*(const uint2*)(pd + H));
    float fd0 = fdv.x + bf4.x, fd1 = fdv.y + bf4.y, fd2 = fdv.z + bf4.z, fd3 = fdv.w + bf4.w;
    float sd0 = sdv.x + bs4.x, sd1 = sdv.y + bs4.y, sd2 = sdv.z + bs4.z, sd3 = sdv.w + bs4.w;

    const __half* Ps = ea.Ps[t];
    int sstr = ea.sstr[t];
    const int* ssrc = ea.ssrc[t];
    const float* su = ea.su[t];
    const float* T = ea.T[t];

    float a0 = 0.f, a1 = 0.f, a2 = 0.f, a3 = 0.f;

    for (int p = p0; p < p1; p += 4) {
        int pe = p1 - 1;
        int i1 = min(p + 1, pe), i2 = min(p + 2, pe), i3 = min(p + 3, pe);
        int sA = ssrc[p], sB = ssrc[i1], sC = ssrc[i2], sD = ssrc[i3];
        float uA = su[p], uB = su[i1], uC = su[i2], uD = su[i3];

        const __half* qA = Ps + (size_t)sA * sstr + j0;
        const __half* qB = Ps + (size_t)sB * sstr + j0;
        const __half* qC = Ps + (size_t)sC * sstr + j0;
        const __half* qD = Ps + (size_t)sD * sstr + j0;
        uint2 rfA = *(const uint2*)(qA);
        uint2 rfB = *(const uint2*)(qB);
        uint2 rfC = *(const uint2*)(qC);
        uint2 rfD = *(const uint2*)(qD);
        uint2 rsA = *(const uint2*)(qA + H);
        uint2 rsB = *(const uint2*)(qB + H);
        uint2 rsC = *(const uint2*)(qC + H);
        uint2 rsD = *(const uint2*)(qD + H);

        edge_math(h4f(rfA), h4f(rsA), uA, T, j0, fd0, fd1, fd2, fd3, sd0, sd1, sd2, sd3,
                  a0, a1, a2, a3, true);
        edge_math(h4f(rfB), h4f(rsB), uB, T, j0, fd0, fd1, fd2, fd3, sd0, sd1, sd2, sd3,
                  a0, a1, a2, a3, p + 1 < p1);
        edge_math(h4f(rfC), h4f(rsC), uC, T, j0, fd0, fd1, fd2, fd3, sd0, sd1, sd2, sd3,
                  a0, a1, a2, a3, p + 2 < p1);
        edge_math(h4f(rfD), h4f(rsD), uD, T, j0, fd0, fd1, fd2, fd3, sd0, sd1, sd2, sd3,
                  a0, a1, a2, a3, p + 3 < p1);
    }
    *(float4*)(ea.agg[t] + (size_t)n * H + j0) = make_float4(a0, a1, a2, a3);
}

// ---------------- merged node epilogue (fp32 + fp16 mirror) ----------------
__global__ __launch_bounds__(256) void node_update(
    const float* __restrict__ xp_in, const float* __restrict__ agg_pp,
    const float* __restrict__ agg_lp,
    const float* __restrict__ xl_in, const float* __restrict__ agg_pl,
    const float* __restrict__ bn_w, const float* __restrict__ bn_b,
    const float* __restrict__ ln_w, const float* __restrict__ ln_b, int l,
    float* __restrict__ xp_out, float* __restrict__ xl_out,
    __half* __restrict__ xph_out, __half* __restrict__ xlh_out)
{
    int w = blockIdx.x * 8 + (threadIdx.x >> 5);
    int lane = threadIdx.x & 31;
    int j0 = lane * 4;
    const float bnf = rsqrtf(1.0f + 1e-5f);

    if (w < NP) {
        size_t off = (size_t)w * H + j0;
        float4 x = *(const float4*)(xp_in + off);

        size_t pb0 = (size_t)(l * 3 + 0) * H + j0;
        float4 bw = *(const float4*)(bn_w + pb0);
        float4 bb = *(const float4*)(bn_b + pb0);
        float4 lw = *(const float4*)(ln_w + pb0);
        float4 lb = *(const float4*)(ln_b + pb0);
        float4 g = *(const float4*)(agg_pp + off);
        float4 a;
        a.x = g.x * (bw.x * bnf) + bb.x + x.x;
        a.y = g.y * (bw.y * bnf) + bb.y + x.y;
        a.z = g.z * (bw.z * bnf) + bb.z + x.z;
        a.w = g.w * (bw.w * bnf) + bb.w + x.w;
        float4 y1 = cg_ln_relu(a, lw, lb);

        size_t pb1 = (size_t)(l * 3 + 1) * H + j0;
        bw = *(const float4*)(bn_w + pb1);
        bb = *(const float4*)(bn_b + pb1);
        lw = *(const float4*)(ln_w + pb1);
        lb = *(const float4*)(ln_b + pb1);
        g = *(const float4*)(agg_lp + off);
        a.x = g.x * (bw.x * bnf) + bb.x + x.x;
        a.y = g.y * (bw.y * bnf) + bb.y + x.y;
        a.z = g.z * (bw.z * bnf) + bb.z + x.z;
        a.w = g.w * (bw.w * bnf) + bb.w + x.w;
        float4 y2 = cg_ln_relu(a, lw, lb);

        float4 r;
        r.x = y1.x + y2.x + 2.f * x.x;
        r.y = y1.y + y2.y + 2.f * x.y;
        r.z = y1.z + y2.z + 2.f * x.z;
        r.w = y1.w + y2.w + 2.f * x.w;
        *(float4*)(xp_out + off) = r;
        *(__half2*)(xph_out + off) = __floats2half2_rn(r.x, r.y);
        *(__half2*)(xph_out + off + 2) = __floats2half2_rn(r.z, r.w);
    } else if (w < NP + NL) {
        int i = w - NP;
        size_t off = (size_t)i * H + j0;
        float4 x = *(const float4*)(xl_in + off);
        size_t pb2 = (size_t)(l * 3 + 2) * H + j0;
        float4 bw = *(const float4*)(bn_w + pb2);
        float4 bb = *(const float4*)(bn_b + pb2);
        float4 lw = *(const float4*)(ln_w + pb2);
        float4 lb = *(const float4*)(ln_b + pb2);
        float4 g = *(const float4*)(agg_pl + off);
        float4 a;
        a.x = g.x * (bw.x * bnf) + bb.x + x.x;
        a.y = g.y * (bw.y * bnf) + bb.y + x.y;
        a.z = g.z * (bw.z * bnf) + bb.z + x.z;
        a.w = g.w * (bw.w * bnf) + bb.w + x.w;
        float4 y = cg_ln_relu(a, lw, lb);
        float4 r;
        r.x = y.x + x.x; r.y = y.y + x.y; r.z = y.z + x.z; r.w = y.w + x.w;
        *(float4*)(xl_out + off) = r;
        *(__half2*)(xlh_out + off) = __floats2half2_rn(r.x, r.y);
        *(__half2*)(xlh_out + off + 2) = __floats2half2_rn(r.z, r.w);
    }
}

// ---------------- final: LN(xp) @ fc_w + fc_b ----------------
__global__ __launch_bounds__(128) void final_kernel(
    const float* __restrict__ xp,
    const float* __restrict__ lnw, const float* __restrict__ lnb,
    const float* __restrict__ fcw, const float* __restrict__ fcb,
    float* __restrict__ out)
{
    __shared__ float sh[8];
    __shared__ float yb[H];
    __shared__ float part[4][21];
    int i = blockIdx.x, j = threadIdx.x;
    float x = xp[(size_t)i * H + j];
    float s = x, q = x * x;
    block_reduce_2(s, q, sh);
    float mean = s * (1.0f / H);
    float var = q * (1.0f / H) - mean * mean;
    yb[j] = (x - mean) * rsqrtf(var + 1e-5f) * lnw[j] + lnb[j];
    __syncthreads();
    if (j < 84) {
        int c = j % 21, qq = j / 21;
        float acc = 0.f;
        #pragma unroll
        for (int t = 0; t < 32; ++t) acc += yb[qq * 32 + t] * fcw[(qq * 32 + t) * 21 + c];
        part[qq][c] = acc;
    }
    __syncthreads();
    if (j < 21)
        out[(size_t)i * 21 + j] = part[0][j] + part[1][j] + part[2][j] + part[3][j] + fcb[j];
}

// ---------------- host ----------------
extern "C" void kernel_launch(void* const* d_in, const int* in_sizes, int n_in,
                              void* d_out, int out_size)
{
    const float* x_protein = (const float*)d_in[0];
    const float* x_ligand  = (const float*)d_in[1];
    const int*   ei_pp     = (const int*)d_in[2];
    const float* ea_pp     = (const float*)d_in[3];
    const int*   ei_lp     = (const int*)d_in[4];
    const float* ea_lp     = (const float*)d_in[5];
    const int*   ei_pl     = (const int*)d_in[6];
    const float* ea_pl     = (const float*)d_in[7];
    const float* Wp        = (const float*)d_in[8];
    const float* bp        = (const float*)d_in[9];
    const float* Wl        = (const float*)d_in[10];
    const float* bl        = (const float*)d_in[11];
    const float* Wf        = (const float*)d_in[12];
    const float* bf        = (const float*)d_in[13];
    const float* Ws        = (const float*)d_in[14];
    const float* bs        = (const float*)d_in[15];
    const float* bn_w      = (const float*)d_in[16];
    const float* bn_b      = (const float*)d_in[17];
    const float* ln_w      = (const float*)d_in[18];
    const float* ln_b      = (const float*)d_in[19];
    const float* lno_w     = (const float*)d_in[20];
    const float* lno_b     = (const float*)d_in[21];
    const float* fc_w      = (const float*)d_in[22];
    const float* fc_b      = (const float*)d_in[23];
    float* out = (float*)d_out;

    float *xpA, *xpB, *xlA, *xlB, *agg_pp, *agg_lp, *agg_pl, *su, *Tb;
    __half *Pp, *Pl, *xph, *xlh, *Wh;
    int *cnt, *offs, *cur, *ssrc, *chs, *chb;
    cudaGetSymbolAddress((void**)&xpA, g_xpA);
    cudaGetSymbolAddress((void**)&xpB, g_xpB);
    cudaGetSymbolAddress((void**)&xlA, g_xlA);
    cudaGetSymbolAddress((void**)&xlB, g_xlB);
    cudaGetSymbolAddress((void**)&xph, g_xph);
    cudaGetSymbolAddress((void**)&xlh, g_xlh);
    cudaGetSymbolAddress((void**)&Wh, g_Wh);
    cudaGetSymbolAddress((void**)&Pp, g_Pp);
    cudaGetSymbolAddress((void**)&Pl, g_Pl);
    cudaGetSymbolAddress((void**)&agg_pp, g_agg_pp);
    cudaGetSymbolAddress((void**)&agg_lp, g_agg_lp);
    cudaGetSymbolAddress((void**)&agg_pl, g_agg_pl);
    cudaGetSymbolAddress((void**)&Tb, g_T);
    cudaGetSymbolAddress((void**)&cnt, g_cnt);
    cudaGetSymbolAddress((void**)&offs, g_off);
    cudaGetSymbolAddress((void**)&cur, g_cur);
    cudaGetSymbolAddress((void**)&ssrc, g_ssrc);
    cudaGetSymbolAddress((void**)&su, g_su);
    cudaGetSymbolAddress((void**)&chs, g_chunksum);
    cudaGetSymbolAddress((void**)&chb, g_chunkbase);

    cudaFuncSetAttribute(proj_mma, cudaFuncAttributeMaxDynamicSharedMemorySize, SMEM_MMA_BYTES);

    // setup
    embed_kernel<<<NP + NL, 128>>>(x_protein, Wp, bp, x_ligand, Wl, bl, xpA, xlA, xph, xlh);
    wconv<<<dim3(48, 128), 128>>>(Wf, Ws, Wh);
    lut_build<<<dim3(NBIN + 1, 12), 256>>>(Wf, Ws, Tb);
    cudaMemsetAsync(cnt, 0, NCNT * sizeof(int), 0);
    hist_all<<<(ETOT + 255) / 256, 256>>>(ei_pp, ei_lp, ei_pl, cnt);
    proj_mma<<<dim3((NP + 127) / 128, 12), 256, SMEM_MMA_BYTES>>>(xph, xlh, Wh, Pp, Pl);
    scanA<<<CHT, 1024>>>(cnt, offs, chs);
    scanB<<<1, 32>>>(chs, chb, offs);
    scanC<<<CHT, 1024>>>(offs, chb, cur);
    scatter_all<<<(ETOT + 255) / 256, 256>>>(ei_pp, ea_pp, ei_lp, ea_lp, ei_pl, ea_pl,
                                             cur, ssrc, su);

    float* xp_cur = xpA; float* xp_nxt = xpB;
    float* xl_cur = xlA; float* xl_nxt = xlB;

    for (int l = 0; l < NLAYER; ++l) {
        if (l > 0)
            proj_mma<<<dim3((NP + 127) / 128, 12), 256, SMEM_MMA_BYTES>>>(
                xph, xlh, Wh + (size_t)l * 12 * 128 * 128, Pp, Pl);

        EdgeArgs ea;
        ea.off[0] = offs;              ea.ssrc[0] = ssrc;             ea.su[0] = su;
        ea.T[0] = Tb + (size_t)(l * 3 + 0) * (NBIN + 1) * 256;
        ea.Pd[0] = Pp + 0 * H; ea.dstr[0] = 8 * H;
        ea.Ps[0] = Pp + 2 * H; ea.sstr[0] = 8 * H;
        ea.bfp[0] = bf + (size_t)(l * 3 + 0) * H; ea.bsp[0] = bs + (size_t)(l * 3 + 0) * H;
        ea.agg[0] = agg_pp;
        ea.off[1] = offs + NP + 1;     ea.ssrc[1] = ssrc + EPP;       ea.su[1] = su + EPP;
        ea.T[1] = Tb + (size_t)(l * 3 + 1) * (NBIN + 1) * 256;
        ea.Pd[1] = Pp + 4 * H; ea.dstr[1] = 8 * H;
        ea.Ps[1] = Pl + 0 * H; ea.sstr[1] = 4 * H;
        ea.bfp[1] = bf + (size_t)(l * 3 + 1) * H; ea.bsp[1] = bs + (size_t)(l * 3 + 1) * H;
        ea.agg[1] = agg_lp;
        ea.off[2] = offs + 2 * NP + 2; ea.ssrc[2] = ssrc + EPP + ELP; ea.su[2] = su + EPP + ELP;
        ea.T[2] = Tb + (size_t)(l * 3 + 2) * (NBIN + 1) * 256;
        ea.Pd[2] = Pl + 2 * H; ea.dstr[2] = 4 * H;
        ea.Ps[2] = Pp + 6 * H; ea.sstr[2] = 8 * H;
        ea.bfp[2] = bf + (size_t)(l * 3 + 2) * H; ea.bsp[2] = bs + (size_t)(l * 3 + 2) * H;
        ea.agg[2] = agg_pl;

        edge_all<<<(2 * NP + NL + 7) / 8, 256>>>(ea);

        node_update<<<(NP + NL + 7) / 8, 256>>>(xp_cur, agg_pp, agg_lp,
                                                xl_cur, agg_pl,
                                                bn_w, bn_b, ln_w, ln_b, l,
                                                xp_nxt, xl_nxt, xph, xlh);

        float* t;
        t = xp_cur; xp_cur = xp_nxt; xp_nxt = t;
        t = xl_cur; xl_cur = xl_nxt; xl_nxt = t;
    }

    final_kernel<<<NP, 128>>>(xp_cur, lno_w, lno_b, fc_w, fc_b, out);
}

// round 11
// speedup vs baseline: 4.7809x; 1.0575x over previous
#include <cuda_runtime.h>
#include <cuda_fp16.h>
#include <cstdint>
#include <cstddef>

#define NP 50000
#define NL 10000
#define H  128
#define D  16
#define NLAYER 4
#define EPP 500000
#define ELP 100000
#define EPL 100000
#define ETOT (EPP + ELP + EPL)
#define NCNT (2 * NP + NL)
#define NBIN 512
#define CH0 49
#define CH1 49
#define CH2 10
#define CHT (CH0 + CH1 + CH2)

// ---------------- scratch (device globals; no runtime allocation) ----------------
__device__ float  g_xpA[NP * H];
__device__ float  g_xpB[NP * H];
__device__ float  g_xlA[NL * H];
__device__ float  g_xlB[NL * H];
__device__ __align__(16) __half g_xph[NP * H];
__device__ __align__(16) __half g_xlh[NL * H];
__device__ __align__(16) __half g_Wh[(size_t)48 * 128 * 128];
__device__ __align__(16) __half g_Pp[(size_t)NP * 8 * H];
__device__ __align__(16) __half g_Pl[(size_t)NL * 4 * H];
__device__ float  g_agg_pp[NP * H];
__device__ float  g_agg_lp[NP * H];
__device__ float  g_agg_pl[NL * H];
// fp16 interleaved LUT: Th[lt][bin][col] = (T(bin), T(bin+1))
__device__ __align__(16) __half2 g_Th[(size_t)12 * NBIN * 256];
__device__ int    g_cnt[NCNT];
__device__ int    g_off[NCNT + 3];
__device__ int    g_cur[NCNT];
__device__ int    g_ssrc[ETOT];
__device__ float  g_su[ETOT];
__device__ int    g_chunksum[CHT];
__device__ int    g_chunkbase[CHT];

// ---------------- small helpers ----------------
__device__ __forceinline__ uint32_t smem_u32(const void* p) {
    uint32_t a;
    asm("{ .reg .u64 t; cvta.to.shared.u64 t, %1; cvt.u32.u64 %0, t; }" : "=r"(a) : "l"(p));
    return a;
}
__device__ __forceinline__ void ldsm_x4(uint32_t& r0, uint32_t& r1, uint32_t& r2, uint32_t& r3,
                                        uint32_t addr) {
    asm volatile("ldmatrix.sync.aligned.m8n8.x4.shared.b16 {%0,%1,%2,%3}, [%4];"
                 : "=r"(r0), "=r"(r1), "=r"(r2), "=r"(r3) : "r"(addr));
}
__device__ __forceinline__ void block_reduce_2(float& s, float& q, float* shbuf)
{
    unsigned m = 0xffffffffu;
    #pragma unroll
    for (int o = 16; o > 0; o >>= 1) {
        s += __shfl_down_sync(m, s, o);
        q += __shfl_down_sync(m, q, o);
    }
    int lane = threadIdx.x & 31, wid = threadIdx.x >> 5;
    if (lane == 0) { shbuf[wid] = s; shbuf[4 + wid] = q; }
    __syncthreads();
    s = shbuf[0] + shbuf[1] + shbuf[2] + shbuf[3];
    q = shbuf[4] + shbuf[5] + shbuf[6] + shbuf[7];
    __syncthreads();
}
__device__ __forceinline__ float sig_tanh(float x) {
    float t;
    asm("tanh.approx.f32 %0, %1;" : "=f"(t) : "f"(x * 0.5f));
    return 0.5f * t + 0.5f;
}
__device__ __forceinline__ float softplus_f(float x) {
    return fmaxf(x, 0.f) + __logf(1.0f + __expf(-fabsf(x)));
}
__device__ __forceinline__ float4 h4f(uint2 v) {
    __half2 a = *(__half2*)&v.x;
    __half2 b = *(__half2*)&v.y;
    float2 fa = __half22float2(a);
    float2 fb = __half22float2(b);
    return make_float4(fa.x, fa.y, fb.x, fb.y);
}
__device__ __forceinline__ float4 cg_ln_relu(float4 a, float4 lw, float4 lb)
{
    float s = a.x + a.y + a.z + a.w;
    float q = a.x * a.x + a.y * a.y + a.z * a.z + a.w * a.w;
    #pragma unroll
    for (int o = 16; o > 0; o >>= 1) {
        s += __shfl_xor_sync(0xffffffffu, s, o);
        q += __shfl_xor_sync(0xffffffffu, q, o);
    }
    float mean = s * (1.0f / H);
    float var = q * (1.0f / H) - mean * mean;
    float r = rsqrtf(var + 1e-5f);
    float4 y;
    y.x = fmaxf((a.x - mean) * r * lw.x + lb.x, 0.f);
    y.y = fmaxf((a.y - mean) * r * lw.y + lb.y, 0.f);
    y.z = fmaxf((a.z - mean) * r * lw.z + lb.z, 0.f);
    y.w = fmaxf((a.w - mean) * r * lw.w + lb.w, 0.f);
    return y;
}

// ---------------- CSR build ----------------
__global__ void hist_all(const int* __restrict__ ei_pp, const int* __restrict__ ei_lp,
                         const int* __restrict__ ei_pl, int* __restrict__ cnt)
{
    int idx = blockIdx.x * blockDim.x + threadIdx.x;
    if (idx >= ETOT) return;
    if (idx < EPP) {
        atomicAdd(&cnt[ei_pp[EPP + idx]], 1);
    } else if (idx < EPP + ELP) {
        int e = idx - EPP;
        atomicAdd(&cnt[NP + ei_lp[ELP + e]], 1);
    } else {
        int e = idx - EPP - ELP;
        atomicAdd(&cnt[2 * NP + ei_pl[EPL + e]], 1);
    }
}

__global__ __launch_bounds__(1024) void scanA(const int* __restrict__ cnt,
                                              int* __restrict__ off,
                                              int* __restrict__ chunksum)
{
    __shared__ int s[1024];
    int bid = blockIdx.x;
    const int* cbase; int* obase; int N; int c;
    if (bid < CH0)            { cbase = cnt;          obase = off;              N = NP; c = bid; }
    else if (bid < CH0 + CH1) { cbase = cnt + NP;     obase = off + NP + 1;     N = NP; c = bid - CH0; }
    else                      { cbase = cnt + 2 * NP; obase = off + 2 * NP + 2; N = NL; c = bid - CH0 - CH1; }
    int tid = threadIdx.x;
    int i = c * 1024 + tid;
    int v = (i < N) ? cbase[i] : 0;
    s[tid] = v;
    __syncthreads();
    #pragma unroll
    for (int o = 1; o < 1024; o <<= 1) {
        int t = (tid >= o) ? s[tid - o] : 0;
        __syncthreads();
        s[tid] += t;
        __syncthreads();
    }
    if (i < N) obase[i] = s[tid] - v;
    if (tid == 1023) chunksum[bid] = s[1023];
}

__global__ void scanB(const int* __restrict__ chunksum, int* __restrict__ chunkbase,
                      int* __restrict__ off)
{
    int t = threadIdx.x;
    if (t == 0) {
        int b = 0;
        for (int c = 0; c < CH0; ++c) { chunkbase[c] = b; b += chunksum[c]; }
        off[NP] = b;
    } else if (t == 1) {
        int b = 0;
        for (int c = 0; c < CH1; ++c) { chunkbase[CH0 + c] = b; b += chunksum[CH0 + c]; }
        off[NP + 1 + NP] = b;
    } else if (t == 2) {
        int b = 0;
        for (int c = 0; c < CH2; ++c) { chunkbase[CH0 + CH1 + c] = b; b += chunksum[CH0 + CH1 + c]; }
        off[2 * NP + 2 + NL] = b;
    }
}

__global__ __launch_bounds__(1024) void scanC(int* __restrict__ off,
                                              const int* __restrict__ chunkbase,
                                              int* __restrict__ cur)
{
    int bid = blockIdx.x;
    int* obase; int* curb; int N; int c;
    if (bid < CH0)            { obase = off;              curb = cur;          N = NP; c = bid; }
    else if (bid < CH0 + CH1) { obase = off + NP + 1;     curb = cur + NP;     N = NP; c = bid - CH0; }
    else                      { obase = off + 2 * NP + 2; curb = cur + 2 * NP; N = NL; c = bid - CH0 - CH1; }
    int i = c * 1024 + threadIdx.x;
    if (i < N) {
        int v = obase[i] + chunkbase[bid];
        obase[i] = v;
        curb[i] = v;
    }
}

__global__ void scatter_all(const int* __restrict__ ei_pp, const float* __restrict__ ea_pp,
                            const int* __restrict__ ei_lp, const float* __restrict__ ea_lp,
                            const int* __restrict__ ei_pl, const float* __restrict__ ea_pl,
                            int* __restrict__ cur, int* __restrict__ ssrc,
                            float* __restrict__ su)
{
    const float usc = (float)NBIN / 8.0f;
    int idx = blockIdx.x * blockDim.x + threadIdx.x;
    if (idx >= ETOT) return;
    if (idx < EPP) {
        int e = idx;
        int d = ei_pp[EPP + e];
        int p = atomicAdd(&cur[d], 1);
        ssrc[p] = ei_pp[e];
        su[p] = ea_pp[e] * usc;
    } else if (idx < EPP + ELP) {
        int e = idx - EPP;
        int d = ei_lp[ELP + e];
        int p = EPP + atomicAdd(&cur[NP + d], 1);
        ssrc[p] = ei_lp[e];
        su[p] = ea_lp[e] * usc;
    } else {
        int e = idx - EPP - ELP;
        int d = ei_pl[EPL + e];
        int p = EPP + ELP + atomicAdd(&cur[2 * NP + d], 1);
        ssrc[p] = ei_pl[e];
        su[p] = ea_pl[e] * usc;
    }
}

// ---------------- LUT build: fp16 interleaved (lo, hi) ----------------
__global__ __launch_bounds__(256) void lut_build(
    const float* __restrict__ Wf, const float* __restrict__ Ws, __half2* __restrict__ Th)
{
    int b = blockIdx.x;        // 0..NBIN-1
    int lt = blockIdx.y;
    int j = threadIdx.x;
    const float step = 8.0f / 15.0f;
    const float coeff = -0.5f / (step * step);
    const float* W = (j < 128 ? Wf : Ws) + ((size_t)lt * 272 + 256) * H + (j & 127);
    float accL = 0.f, accH = 0.f;
    float dL = (float)b * (8.0f / (float)NBIN);
    float dH = (float)(b + 1) * (8.0f / (float)NBIN);
    #pragma unroll
    for (int k = 0; k < 16; ++k) {
        float w = W[(size_t)k * H];
        float dltL = dL - (float)k * step;
        float dltH = dH - (float)k * step;
        accL += __expf(coeff * dltL * dltL) * w;
        accH += __expf(coeff * dltH * dltH) * w;
    }
    Th[((size_t)lt * NBIN + b) * 256 + j] = __floats2half2_rn(accL, accH);
}

// ---------------- fp16 weight pre-convert ----------------
__global__ __launch_bounds__(128) void wconv(
    const float* __restrict__ Wf, const float* __restrict__ Ws, __half* __restrict__ Wh)
{
    const int bmap[12] = {0, 0, 0, 0, 1, 1, 2, 2, 1, 1, 2, 2};
    const int rmap[12] = {0, 0, 128, 128, 0, 0, 128, 128, 128, 128, 0, 0};
    const int fmap[12] = {1, 0, 1, 0, 1, 0, 1, 0, 1, 0, 1, 0};
    int ls = blockIdx.x;
    int layer = ls / 12, s = ls % 12;
    int k = blockIdx.y;
    int n = threadIdx.x;
    const float* base = fmap[s] ? Wf : Ws;
    float v = base[((size_t)(layer * 3 + bmap[s]) * 272 + rmap[s] + k) * H + n];
    Wh[((size_t)ls * 128 + n) * 128 + k] = __float2half(v);
}

// ---------------- merged initial embedding ----------------
__global__ __launch_bounds__(128) void embed_kernel(
    const float* __restrict__ xp, const float* __restrict__ Wp, const float* __restrict__ bp,
    const float* __restrict__ xl, const float* __restrict__ Wl, const float* __restrict__ bl,
    float* __restrict__ outp, float* __restrict__ outl,
    __half* __restrict__ outph, __half* __restrict__ outlh)
{
    int i = blockIdx.x;
    int j = threadIdx.x;
    const float *x, *W, *b; float* o; __half* oh; int r;
    if (i < NP) { x = xp; W = Wp; b = bp; o = outp; oh = outph; r = i; }
    else        { x = xl; W = Wl; b = bl; o = outl; oh = outlh; r = i - NP; }
    const float* xr = x + (size_t)r * 6;
    float acc = b[j];
    #pragma unroll
    for (int k = 0; k < 6; ++k) acc += xr[k] * W[k * H + j];
    o[(size_t)r * H + j] = acc;
    oh[(size_t)r * H + j] = __float2half(acc);
}

// ---------------- pipelined fp16 mma GEMM with ldmatrix ----------------
#define APH 72
#define ASTH (128 * APH)
#define BSTH (128 * APH)
#define STGH (ASTH + BSTH)
#define SMEM_MMA_BYTES (2 * STGH * 2)

__global__ __launch_bounds__(256, 2) void proj_mma(
    const __half* __restrict__ Xph, const __half* __restrict__ Xlh,
    const __half* __restrict__ Wh,
    __half* __restrict__ outP, __half* __restrict__ outL)
{
    int slice = blockIdx.y;
    const __half* Xh; __half* out; int N, outStride, col;
    if (slice < 8) { Xh = Xph; out = outP; N = NP; outStride = 8 * H; col = slice; }
    else           { Xh = Xlh; out = outL; N = NL; outStride = 4 * H; col = slice - 8; }
    int m0 = blockIdx.x * 128;
    if (m0 >= N) return;

    extern __shared__ __half smh[];
    uint32_t smb = smem_u32(smh);
    const __half* Whs = Wh + (size_t)slice * 128 * 128;
    int tid = threadIdx.x;
    int lane = tid & 31, warp = tid >> 5;
    int g = lane >> 2, t = lane & 3;

    auto load_stage = [&](int chunk, int s) {
        int kb = chunk * 64;
        uint32_t abase = smb + (uint32_t)(s * STGH) * 2u;
        uint32_t bbase = abase + (uint32_t)ASTH * 2u;
        #pragma unroll
        for (int i = 0; i < 4; ++i) {
            int idx = tid + i * 256;
            int r = idx >> 3, c8 = (idx & 7) * 8;
            uint32_t dst = abase + (uint32_t)(r * APH + c8) * 2u;
            const __half* src = Xh + (size_t)(m0 + r) * H + kb + c8;
            int sz = (m0 + r < N) ? 16 : 0;
            asm volatile("cp.async.cg.shared.global [%0], [%1], 16, %2;"
                         :: "r"(dst), "l"(src), "r"(sz));
        }
        #pragma unroll
        for (int i = 0; i < 4; ++i) {
            int idx = tid + i * 256;
            int n = idx >> 3, k8 = (idx & 7) * 8;
            uint32_t dst = bbase + (uint32_t)(n * APH + k8) * 2u;
            const __half* src = Whs + (size_t)n * 128 + kb + k8;
            asm volatile("cp.async.cg.shared.global [%0], [%1], 16;"
                         :: "r"(dst), "l"(src));
        }
        asm volatile("cp.async.commit_group;" ::: "memory");
    };

    load_stage(0, 0);
    load_stage(1, 1);

    int wm = warp >> 2;
    int wn = warp & 3;
    int mbase = wm * 64;
    int nbase = wn * 32;

    // ldmatrix lane-address components
    int a_row = lane & 15;           // row within 16-row block
    int a_kh = (lane >> 4) * 8;      // k-half select (0 or 8)
    int b_nrow = (lane >> 4) * 8 + (lane & 7);  // n within 16-col j-pair
    int b_kh = ((lane >> 3) & 1) * 8;           // k-half select

    float d[4][4][4];
    #pragma unroll
    for (int i = 0; i < 4; ++i)
        #pragma unroll
        for (int j = 0; j < 4; ++j)
            #pragma unroll
            for (int q = 0; q < 4; ++q) d[i][j][q] = 0.f;

    #pragma unroll
    for (int c = 0; c < 2; ++c) {
        if (c == 0) asm volatile("cp.async.wait_group 1;" ::: "memory");
        else        asm volatile("cp.async.wait_group 0;" ::: "memory");
        __syncthreads();

        uint32_t abase = smb + (uint32_t)(c * STGH) * 2u;
        uint32_t bbase = abase + (uint32_t)ASTH * 2u;

        #pragma unroll
        for (int ks = 0; ks < 4; ++ks) {
            int kbl = ks * 16;
            uint32_t a[4][4];
            #pragma unroll
            for (int i = 0; i < 4; ++i) {
                uint32_t addr = abase +
                    (uint32_t)((mbase + i * 16 + a_row) * APH + kbl + a_kh) * 2u;
                ldsm_x4(a[i][0], a[i][1], a[i][2], a[i][3], addr);
            }
            uint32_t b[4][2];
            #pragma unroll
            for (int jp = 0; jp < 2; ++jp) {
                uint32_t addr = bbase +
                    (uint32_t)((nbase + jp * 16 + b_nrow) * APH + kbl + b_kh) * 2u;
                ldsm_x4(b[2 * jp][0], b[2 * jp][1], b[2 * jp + 1][0], b[2 * jp + 1][1], addr);
            }
            #pragma unroll
            for (int i = 0; i < 4; ++i)
                #pragma unroll
                for (int j = 0; j < 4; ++j) {
                    asm volatile(
                        "mma.sync.aligned.m16n8k16.row.col.f32.f16.f16.f32 "
                        "{%0,%1,%2,%3}, {%4,%5,%6,%7}, {%8,%9}, {%0,%1,%2,%3};"
                        : "+f"(d[i][j][0]), "+f"(d[i][j][1]), "+f"(d[i][j][2]), "+f"(d[i][j][3])
                        : "r"(a[i][0]), "r"(a[i][1]), "r"(a[i][2]), "r"(a[i][3]),
                          "r"(b[j][0]), "r"(b[j][1]));
                }
        }
    }

    size_t colbase = (size_t)col * H;
    #pragma unroll
    for (int i = 0; i < 4; ++i) {
        int gr0 = m0 + mbase + i * 16 + g;
        int gr1 = gr0 + 8;
        #pragma unroll
        for (int j = 0; j < 4; ++j) {
            int gc = nbase + j * 8 + t * 2;
            if (gr0 < N)
                *(__half2*)(out + (size_t)gr0 * outStride + colbase + gc) =
                    __floats2half2_rn(d[i][j][0], d[i][j][1]);
            if (gr1 < N)
                *(__half2*)(out + (size_t)gr1 * outStride + colbase + gc) =
                    __floats2half2_rn(d[i][j][2], d[i][j][3]);
        }
    }
}

// ---------------- merged CSR edge kernel: fp16 P + fp16 interleaved LUT ----------
struct EdgeArgs {
    const int*    off[3];
    const int*    ssrc[3];
    const float*  su[3];
    const __half2* T[3];
    const __half* Pd[3]; int dstr[3];
    const __half* Ps[3]; int sstr[3];
    const float*  bfp[3];
    const float*  bsp[3];
    float*        agg[3];
};

__device__ __forceinline__ void edge_math(
    float4 fsv, float4 ssv, float u, const __half2* __restrict__ T, int j0,
    float fd0, float fd1, float fd2, float fd3,
    float sd0, float sd1, float sd2, float sd3,
    float& a0, float& a1, float& a2, float& a3, bool valid)
{
    int b = min((int)u, NBIN - 1);
    float w = u - (float)b;
    const __half2* Tb = T + (size_t)b * 256 + j0;
    uint4 fv = *(const uint4*)(Tb);         // 4 half2: (lo,hi) f cols j0..j0+3
    uint4 sv = *(const uint4*)(Tb + 128);   // s cols
    float2 f0p = __half22float2(*(__half2*)&fv.x);
    float2 f1p = __half22float2(*(__half2*)&fv.y);
    float2 f2p = __half22float2(*(__half2*)&fv.z);
    float2 f3p = __half22float2(*(__half2*)&fv.w);
    float2 s0p = __half22float2(*(__half2*)&sv.x);
    float2 s1p = __half22float2(*(__half2*)&sv.y);
    float2 s2p = __half22float2(*(__half2*)&sv.z);
    float2 s3p = __half22float2(*(__half2*)&sv.w);

    float f0 = fd0 + fsv.x + f0p.x + w * (f0p.y - f0p.x);
    float f1 = fd1 + fsv.y + f1p.x + w * (f1p.y - f1p.x);
    float f2 = fd2 + fsv.z + f2p.x + w * (f2p.y - f2p.x);
    float f3 = fd3 + fsv.w + f3p.x + w * (f3p.y - f3p.x);
    float s0 = sd0 + ssv.x + s0p.x + w * (s0p.y - s0p.x);
    float s1 = sd1 + ssv.y + s1p.x + w * (s1p.y - s1p.x);
    float s2 = sd2 + ssv.z + s2p.x + w * (s2p.y - s2p.x);
    float s3 = sd3 + ssv.w + s3p.x + w * (s3p.y - s3p.x);

    if (valid) {
        a0 += sig_tanh(f0) * softplus_f(s0);
        a1 += sig_tanh(f1) * softplus_f(s1);
        a2 += sig_tanh(f2) * softplus_f(s2);
        a3 += sig_tanh(f3) * softplus_f(s3);
    }
}

__global__ __launch_bounds__(256) void edge_all(EdgeArgs ea)
{
    int w = blockIdx.x * 8 + (threadIdx.x >> 5);
    int lane = threadIdx.x & 31;
    int j0 = lane * 4;

    int t, n;
    if (w < NP)               { t = 0; n = w; }
    else if (w < 2 * NP)      { t = 1; n = w - NP; }
    else if (w < 2 * NP + NL) { t = 2; n = w - 2 * NP; }
    else return;

    const int* off = ea.off[t];
    int p0 = off[n], p1 = off[n + 1];

    float4 bf4 = *(const float4*)(ea.bfp[t] + j0);
    float4 bs4 = *(const float4*)(ea.bsp[t] + j0);
    const __half* pd = ea.Pd[t] + (size_t)n * ea.dstr[t] + j0;
    float4 fdv = h4f(*(const uint2*)(pd));
    float4 sdv = h4f(*(const uint2*)(pd + H));
    float fd0 = fdv.x + bf4.x, fd1 = fdv.y + bf4.y, fd2 = fdv.z + bf4.z, fd3 = fdv.w + bf4.w;
    float sd0 = sdv.x + bs4.x, sd1 = sdv.y + bs4.y, sd2 = sdv.z + bs4.z, sd3 = sdv.w + bs4.w;

    const __half* Ps = ea.Ps[t];
    int sstr = ea.sstr[t];
    const int* ssrc = ea.ssrc[t];
    const float* su = ea.su[t];
    const __half2* T = ea.T[t];

    float a0 = 0.f, a1 = 0.f, a2 = 0.f, a3 = 0.f;

    for (int p = p0; p < p1; p += 4) {
        int pe = p1 - 1;
        int i1 = min(p + 1, pe), i2 = min(p + 2, pe), i3 = min(p + 3, pe);
        int sA = ssrc[p], sB = ssrc[i1], sC = ssrc[i2], sD = ssrc[i3];
        float uA = su[p], uB = su[i1], uC = su[i2], uD = su[i3];

        const __half* qA = Ps + (size_t)sA * sstr + j0;
        const __half* qB = Ps + (size_t)sB * sstr + j0;
        const __half* qC = Ps + (size_t)sC * sstr + j0;
        const __half* qD = Ps + (size_t)sD * sstr + j0;
        uint2 rfA = *(const uint2*)(qA);
        uint2 rfB = *(const uint2*)(qB);
        uint2 rfC = *(const uint2*)(qC);
        uint2 rfD = *(const uint2*)(qD);
        uint2 rsA = *(const uint2*)(qA + H);
        uint2 rsB = *(const uint2*)(qB + H);
        uint2 rsC = *(const uint2*)(qC + H);
        uint2 rsD = *(const uint2*)(qD + H);

        edge_math(h4f(rfA), h4f(rsA), uA, T, j0, fd0, fd1, fd2, fd3, sd0, sd1, sd2, sd3,
                  a0, a1, a2, a3, true);
        edge_math(h4f(rfB), h4f(rsB), uB, T, j0, fd0, fd1, fd2, fd3, sd0, sd1, sd2, sd3,
                  a0, a1, a2, a3, p + 1 < p1);
        edge_math(h4f(rfC), h4f(rsC), uC, T, j0, fd0, fd1, fd2, fd3, sd0, sd1, sd2, sd3,
                  a0, a1, a2, a3, p + 2 < p1);
        edge_math(h4f(rfD), h4f(rsD), uD, T, j0, fd0, fd1, fd2, fd3, sd0, sd1, sd2, sd3,
                  a0, a1, a2, a3, p + 3 < p1);
    }
    *(float4*)(ea.agg[t] + (size_t)n * H + j0) = make_float4(a0, a1, a2, a3);
}

// ---------------- merged node epilogue ----------------
__global__ __launch_bounds__(256) void node_update(
    const float* __restrict__ xp_in, const float* __restrict__ agg_pp,
    const float* __restrict__ agg_lp,
    const float* __restrict__ xl_in, const float* __restrict__ agg_pl,
    const float* __restrict__ bn_w, const float* __restrict__ bn_b,
    const float* __restrict__ ln_w, const float* __restrict__ ln_b, int l,
    float* __restrict__ xp_out, float* __restrict__ xl_out,
    __half* __restrict__ xph_out, __half* __restrict__ xlh_out)
{
    int w = blockIdx.x * 8 + (threadIdx.x >> 5);
    int lane = threadIdx.x & 31;
    int j0 = lane * 4;
    const float bnf = rsqrtf(1.0f + 1e-5f);

    if (w < NP) {
        size_t off = (size_t)w * H + j0;
        float4 x = *(const float4*)(xp_in + off);

        size_t pb0 = (size_t)(l * 3 + 0) * H + j0;
        float4 bw = *(const float4*)(bn_w + pb0);
        float4 bb = *(const float4*)(bn_b + pb0);
        float4 lw = *(const float4*)(ln_w + pb0);
        float4 lb = *(const float4*)(ln_b + pb0);
        float4 g = *(const float4*)(agg_pp + off);
        float4 a;
        a.x = g.x * (bw.x * bnf) + bb.x + x.x;
        a.y = g.y * (bw.y * bnf) + bb.y + x.y;
        a.z = g.z * (bw.z * bnf) + bb.z + x.z;
        a.w = g.w * (bw.w * bnf) + bb.w + x.w;
        float4 y1 = cg_ln_relu(a, lw, lb);

        size_t pb1 = (size_t)(l * 3 + 1) * H + j0;
        bw = *(const float4*)(bn_w + pb1);
        bb = *(const float4*)(bn_b + pb1);
        lw = *(const float4*)(ln_w + pb1);
        lb = *(const float4*)(ln_b + pb1);
        g = *(const float4*)(agg_lp + off);
        a.x = g.x * (bw.x * bnf) + bb.x + x.x;
        a.y = g.y * (bw.y * bnf) + bb.y + x.y;
        a.z = g.z * (bw.z * bnf) + bb.z + x.z;
        a.w = g.w * (bw.w * bnf) + bb.w + x.w;
        float4 y2 = cg_ln_relu(a, lw, lb);

        float4 r;
        r.x = y1.x + y2.x + 2.f * x.x;
        r.y = y1.y + y2.y + 2.f * x.y;
        r.z = y1.z + y2.z + 2.f * x.z;
        r.w = y1.w + y2.w + 2.f * x.w;
        *(float4*)(xp_out + off) = r;
        *(__half2*)(xph_out + off) = __floats2half2_rn(r.x, r.y);
        *(__half2*)(xph_out + off + 2) = __floats2half2_rn(r.z, r.w);
    } else if (w < NP + NL) {
        int i = w - NP;
        size_t off = (size_t)i * H + j0;
        float4 x = *(const float4*)(xl_in + off);
        size_t pb2 = (size_t)(l * 3 + 2) * H + j0;
        float4 bw = *(const float4*)(bn_w + pb2);
        float4 bb = *(const float4*)(bn_b + pb2);
        float4 lw = *(const float4*)(ln_w + pb2);
        float4 lb = *(const float4*)(ln_b + pb2);
        float4 g = *(const float4*)(agg_pl + off);
        float4 a;
        a.x = g.x * (bw.x * bnf) + bb.x + x.x;
        a.y = g.y * (bw.y * bnf) + bb.y + x.y;
        a.z = g.z * (bw.z * bnf) + bb.z + x.z;
        a.w = g.w * (bw.w * bnf) + bb.w + x.w;
        float4 y = cg_ln_relu(a, lw, lb);
        float4 r;
        r.x = y.x + x.x; r.y = y.y + x.y; r.z = y.z + x.z; r.w = y.w + x.w;
        *(float4*)(xl_out + off) = r;
        *(__half2*)(xlh_out + off) = __floats2half2_rn(r.x, r.y);
        *(__half2*)(xlh_out + off + 2) = __floats2half2_rn(r.z, r.w);
    }
}

// ---------------- final: LN(xp) @ fc_w + fc_b ----------------
__global__ __launch_bounds__(128) void final_kernel(
    const float* __restrict__ xp,
    const float* __restrict__ lnw, const float* __restrict__ lnb,
    const float* __restrict__ fcw, const float* __restrict__ fcb,
    float* __restrict__ out)
{
    __shared__ float sh[8];
    __shared__ float yb[H];
    __shared__ float part[4][21];
    int i = blockIdx.x, j = threadIdx.x;
    float x = xp[(size_t)i * H + j];
    float s = x, q = x * x;
    block_reduce_2(s, q, sh);
    float mean = s * (1.0f / H);
    float var = q * (1.0f / H) - mean * mean;
    yb[j] = (x - mean) * rsqrtf(var + 1e-5f) * lnw[j] + lnb[j];
    __syncthreads();
    if (j < 84) {
        int c = j % 21, qq = j / 21;
        float acc = 0.f;
        #pragma unroll
        for (int t = 0; t < 32; ++t) acc += yb[qq * 32 + t] * fcw[(qq * 32 + t) * 21 + c];
        part[qq][c] = acc;
    }
    __syncthreads();
    if (j < 21)
        out[(size_t)i * 21 + j] = part[0][j] + part[1][j] + part[2][j] + part[3][j] + fcb[j];
}

// ---------------- host ----------------
extern "C" void kernel_launch(void* const* d_in, const int* in_sizes, int n_in,
                              void* d_out, int out_size)
{
    const float* x_protein = (const float*)d_in[0];
    const float* x_ligand  = (const float*)d_in[1];
    const int*   ei_pp     = (const int*)d_in[2];
    const float* ea_pp     = (const float*)d_in[3];
    const int*   ei_lp     = (const int*)d_in[4];
    const float* ea_lp     = (const float*)d_in[5];
    const int*   ei_pl     = (const int*)d_in[6];
    const float* ea_pl     = (const float*)d_in[7];
    const float* Wp        = (const float*)d_in[8];
    const float* bp        = (const float*)d_in[9];
    const float* Wl        = (const float*)d_in[10];
    const float* bl        = (const float*)d_in[11];
    const float* Wf        = (const float*)d_in[12];
    const float* bf        = (const float*)d_in[13];
    const float* Ws        = (const float*)d_in[14];
    const float* bs        = (const float*)d_in[15];
    const float* bn_w      = (const float*)d_in[16];
    const float* bn_b      = (const float*)d_in[17];
    const float* ln_w      = (const float*)d_in[18];
    const float* ln_b      = (const float*)d_in[19];
    const float* lno_w     = (const float*)d_in[20];
    const float* lno_b     = (const float*)d_in[21];
    const float* fc_w      = (const float*)d_in[22];
    const float* fc_b      = (const float*)d_in[23];
    float* out = (float*)d_out;

    float *xpA, *xpB, *xlA, *xlB, *agg_pp, *agg_lp, *agg_pl, *su;
    __half2 *Th;
    __half *Pp, *Pl, *xph, *xlh, *Wh;
    int *cnt, *offs, *cur, *ssrc, *chs, *chb;
    cudaGetSymbolAddress((void**)&xpA, g_xpA);
    cudaGetSymbolAddress((void**)&xpB, g_xpB);
    cudaGetSymbolAddress((void**)&xlA, g_xlA);
    cudaGetSymbolAddress((void**)&xlB, g_xlB);
    cudaGetSymbolAddress((void**)&xph, g_xph);
    cudaGetSymbolAddress((void**)&xlh, g_xlh);
    cudaGetSymbolAddress((void**)&Wh, g_Wh);
    cudaGetSymbolAddress((void**)&Pp, g_Pp);
    cudaGetSymbolAddress((void**)&Pl, g_Pl);
    cudaGetSymbolAddress((void**)&agg_pp, g_agg_pp);
    cudaGetSymbolAddress((void**)&agg_lp, g_agg_lp);
    cudaGetSymbolAddress((void**)&agg_pl, g_agg_pl);
    cudaGetSymbolAddress((void**)&Th, g_Th);
    cudaGetSymbolAddress((void**)&cnt, g_cnt);
    cudaGetSymbolAddress((void**)&offs, g_off);
    cudaGetSymbolAddress((void**)&cur, g_cur);
    cudaGetSymbolAddress((void**)&ssrc, g_ssrc);
    cudaGetSymbolAddress((void**)&su, g_su);
    cudaGetSymbolAddress((void**)&chs, g_chunksum);
    cudaGetSymbolAddress((void**)&chb, g_chunkbase);

    cudaFuncSetAttribute(proj_mma, cudaFuncAttributeMaxDynamicSharedMemorySize, SMEM_MMA_BYTES);

    embed_kernel<<<NP + NL, 128>>>(x_protein, Wp, bp, x_ligand, Wl, bl, xpA, xlA, xph, xlh);
    wconv<<<dim3(48, 128), 128>>>(Wf, Ws, Wh);
    lut_build<<<dim3(NBIN, 12), 256>>>(Wf, Ws, Th);
    cudaMemsetAsync(cnt, 0, NCNT * sizeof(int), 0);
    hist_all<<<(ETOT + 255) / 256, 256>>>(ei_pp, ei_lp, ei_pl, cnt);
    proj_mma<<<dim3((NP + 127) / 128, 12), 256, SMEM_MMA_BYTES>>>(xph, xlh, Wh, Pp, Pl);
    scanA<<<CHT, 1024>>>(cnt, offs, chs);
    scanB<<<1, 32>>>(chs, chb, offs);
    scanC<<<CHT, 1024>>>(offs, chb, cur);
    scatter_all<<<(ETOT + 255) / 256, 256>>>(ei_pp, ea_pp, ei_lp, ea_lp, ei_pl, ea_pl,
                                             cur, ssrc, su);

    float* xp_cur = xpA; float* xp_nxt = xpB;
    float* xl_cur = xlA; float* xl_nxt = xlB;

    for (int l = 0; l < NLAYER; ++l) {
        if (l > 0)
            proj_mma<<<dim3((NP + 127) / 128, 12), 256, SMEM_MMA_BYTES>>>(
                xph, xlh, Wh + (size_t)l * 12 * 128 * 128, Pp, Pl);

        EdgeArgs ea;
        ea.off[0] = offs;              ea.ssrc[0] = ssrc;             ea.su[0] = su;
        ea.T[0] = Th + (size_t)(l * 3 + 0) * NBIN * 256;
        ea.Pd[0] = Pp + 0 * H; ea.dstr[0] = 8 * H;
        ea.Ps[0] = Pp + 2 * H; ea.sstr[0] = 8 * H;
        ea.bfp[0] = bf + (size_t)(l * 3 + 0) * H; ea.bsp[0] = bs + (size_t)(l * 3 + 0) * H;
        ea.agg[0] = agg_pp;
        ea.off[1] = offs + NP + 1;     ea.ssrc[1] = ssrc + EPP;       ea.su[1] = su + EPP;
        ea.T[1] = Th + (size_t)(l * 3 + 1) * NBIN * 256;
        ea.Pd[1] = Pp + 4 * H; ea.dstr[1] = 8 * H;
        ea.Ps[1] = Pl + 0 * H; ea.sstr[1] = 4 * H;
        ea.bfp[1] = bf + (size_t)(l * 3 + 1) * H; ea.bsp[1] = bs + (size_t)(l * 3 + 1) * H;
        ea.agg[1] = agg_lp;
        ea.off[2] = offs + 2 * NP + 2; ea.ssrc[2] = ssrc + EPP + ELP; ea.su[2] = su + EPP + ELP;
        ea.T[2] = Th + (size_t)(l * 3 + 2) * NBIN * 256;
        ea.Pd[2] = Pl + 2 * H; ea.dstr[2] = 4 * H;
        ea.Ps[2] = Pp + 6 * H; ea.sstr[2] = 8 * H;
        ea.bfp[2] = bf + (size_t)(l * 3 + 2) * H; ea.bsp[2] = bs + (size_t)(l * 3 + 2) * H;
        ea.agg[2] = agg_pl;

        edge_all<<<(2 * NP + NL + 7) / 8, 256>>>(ea);

        node_update<<<(NP + NL + 7) / 8, 256>>>(xp_cur, agg_pp, agg_lp,
                                                xl_cur, agg_pl,
                                                bn_w, bn_b, ln_w, ln_b, l,
                                                xp_nxt, xl_nxt, xph, xlh);

        float* t;
        t = xp_cur; xp_cur = xp_nxt; xp_nxt = t;
        t = xl_cur; xl_cur = xl_nxt; xl_nxt = t;
    }

    final_kernel<<<NP, 128>>>(xp_cur, lno_w, lno_b, fc_w, fc_b, out);
}